// round 9
// baseline (speedup 1.0000x reference)
#include <cuda_runtime.h>
#include <cuda_bf16.h>
#include <math.h>
#include <stdint.h>

// ---------------------------------------------------------------------------
// Problem constants
// ---------------------------------------------------------------------------
#define LNUM 4
#define DDIM 1024
#define HNUM 16
#define HD   64
#define MDIM 4096
#define SLEN 1024
#define BNUM 2
#define NTOK (BNUM*SLEN)        // 2048
#define D3   (3*DDIM)           // 3072
#define EPS  1e-5f

// Weight split array layout (element offsets)
#define W_IN1_OFF   0u
#define W_OUT1_OFF  12582912u
#define W_IN2_OFF   16777216u
#define W_OUT2_OFF  29360128u
#define FW1_OFF     33554432u
#define FW2_OFF     50331648u
#define WTOTAL      67108864u

// ---------------------------------------------------------------------------
// Device scratch (no allocations allowed)
// ---------------------------------------------------------------------------
static __device__ float g_proj[NTOK*DDIM];
static __device__ float g_x   [NTOK*DDIM];
static __device__ float g_x2  [NTOK*DDIM];
static __device__ float g_att [NTOK*DDIM];

static __device__ __nv_bfloat16 g_wh[WTOTAL];        // weight hi
static __device__ __nv_bfloat16 g_wl[WTOTAL];        // weight lo
static __device__ __nv_bfloat16 g_qkvh[NTOK*D3];     // qkv hi
static __device__ __nv_bfloat16 g_qkvl[NTOK*D3];     // qkv lo
static __device__ __nv_bfloat16 g_p1h[NTOK*DDIM];
static __device__ __nv_bfloat16 g_p1l[NTOK*DDIM];
static __device__ __nv_bfloat16 g_p2h[NTOK*MDIM];
static __device__ __nv_bfloat16 g_p2l[NTOK*MDIM];

// ---------------------------------------------------------------------------
// Helpers
// ---------------------------------------------------------------------------
__device__ __forceinline__ void cp16(uint32_t d, const void* s) {
    asm volatile("cp.async.cg.shared.global [%0], [%1], 16;\n" :: "r"(d), "l"(s));
}
__device__ __forceinline__ void cp_commit() {
    asm volatile("cp.async.commit_group;\n" ::: "memory");
}
__device__ __forceinline__ void cp_wait2() {
    asm volatile("cp.async.wait_group 2;\n" ::: "memory");
}
__device__ __forceinline__ void cp_wait1() {
    asm volatile("cp.async.wait_group 1;\n" ::: "memory");
}
__device__ __forceinline__ void cp_wait0() {
    asm volatile("cp.async.wait_group 0;\n" ::: "memory");
}
__device__ __forceinline__ void ldsm4(uint32_t* r, uint32_t a) {
    asm volatile("ldmatrix.sync.aligned.m8n8.x4.shared.b16 {%0,%1,%2,%3}, [%4];"
        : "=r"(r[0]), "=r"(r[1]), "=r"(r[2]), "=r"(r[3]) : "r"(a));
}
__device__ __forceinline__ void ldsm4t(uint32_t* r, uint32_t a) {
    asm volatile("ldmatrix.sync.aligned.m8n8.x4.trans.shared.b16 {%0,%1,%2,%3}, [%4];"
        : "=r"(r[0]), "=r"(r[1]), "=r"(r[2]), "=r"(r[3]) : "r"(a));
}
__device__ __forceinline__ void mma16816(float* c, const uint32_t* a,
                                         uint32_t b0, uint32_t b1) {
    asm volatile(
        "mma.sync.aligned.m16n8k16.row.col.f32.bf16.bf16.f32 "
        "{%0,%1,%2,%3},{%4,%5,%6,%7},{%8,%9},{%0,%1,%2,%3};"
        : "+f"(c[0]), "+f"(c[1]), "+f"(c[2]), "+f"(c[3])
        : "r"(a[0]), "r"(a[1]), "r"(a[2]), "r"(a[3]), "r"(b0), "r"(b1));
}
__device__ __forceinline__ uint32_t pack2(__nv_bfloat16 a, __nv_bfloat16 b) {
    __nv_bfloat162 t = __halves2bfloat162(a, b);
    return *reinterpret_cast<uint32_t*>(&t);
}
__device__ __forceinline__ void split1(float v, __nv_bfloat16& h, __nv_bfloat16& l) {
    h = __float2bfloat16(v);
    l = __float2bfloat16(v - __bfloat162float(h));
}
__device__ __forceinline__ float bf2f(__nv_bfloat16 v) { return __bfloat162float(v); }

// ---------------------------------------------------------------------------
// Merged fp32 -> (hi,lo) bf16 split for all 6 weight tensors + x_in.
// ---------------------------------------------------------------------------
#define SPLIT_TOTAL_BLOCKS 16896

__global__ __launch_bounds__(256)
void split_all_kernel(const float* __restrict__ w_in1, const float* __restrict__ w_out1,
                      const float* __restrict__ w_in2, const float* __restrict__ w_out2,
                      const float* __restrict__ fw1,  const float* __restrict__ fw2,
                      const float* __restrict__ x,
                      __nv_bfloat16* __restrict__ WH, __nv_bfloat16* __restrict__ WL,
                      __nv_bfloat16* __restrict__ P1H, __nv_bfloat16* __restrict__ P1L)
{
    const int bid = blockIdx.x;
    const float* src;
    __nv_bfloat16 *dh, *dl;
    int rb;
    if (bid < 3072)       { src = w_in1;  dh = WH + W_IN1_OFF;  dl = WL + W_IN1_OFF;  rb = bid; }
    else if (bid < 4096)  { src = w_out1; dh = WH + W_OUT1_OFF; dl = WL + W_OUT1_OFF; rb = bid - 3072; }
    else if (bid < 7168)  { src = w_in2;  dh = WH + W_IN2_OFF;  dl = WL + W_IN2_OFF;  rb = bid - 4096; }
    else if (bid < 8192)  { src = w_out2; dh = WH + W_OUT2_OFF; dl = WL + W_OUT2_OFF; rb = bid - 7168; }
    else if (bid < 12288) { src = fw1;    dh = WH + FW1_OFF;    dl = WL + FW1_OFF;    rb = bid - 8192; }
    else if (bid < 16384) { src = fw2;    dh = WH + FW2_OFF;    dl = WL + FW2_OFF;    rb = bid - 12288; }
    else                  { src = x;      dh = P1H;             dl = P1L;             rb = bid - 16384; }

    const size_t base = (size_t)rb * 4096 + threadIdx.x * 4;
    #pragma unroll
    for (int j = 0; j < 4; j++) {
        const size_t i = base + j * 1024;
        float4 v = *(const float4*)(src + i);
        __nv_bfloat16 h0,h1,h2,h3,l0,l1,l2,l3;
        split1(v.x,h0,l0); split1(v.y,h1,l1); split1(v.z,h2,l2); split1(v.w,h3,l3);
        uint2 uh; uh.x = pack2(h0,h1); uh.y = pack2(h2,h3);
        uint2 ul; ul.x = pack2(l0,l1); ul.y = pack2(l2,l3);
        *(uint2*)(dh + i) = uh;
        *(uint2*)(dl + i) = ul;
    }
}

// ---------------------------------------------------------------------------
// bf16x3 tensor-core GEMM: C[M,N] = A[M,K] @ Bw[N,K]^T + bias (+ epilogue)
// CTA tile 128x128x32; 256 threads, 8 warps. Each 64x64 output quad is owned
// by a PAIR of warps split along K (wko in {0,1} takes k-chunks 2wko..2wko+1
// of each stage). Per-warp ldsm:MMA reuse identical to the 4-warp version,
// but 2x warps/SMSP for latency hiding. Partials from wko=1 are reduced
// through smem, then wko=0 warps run the epilogue.
// 3-stage cp.async pipeline (96KB smem -> 2 CTA/SM).
// EPI: 0=bias, 1=bias+GELU, 2=bias+residual.
// ---------------------------------------------------------------------------
#define STAGE_BYTES 32768
#define GSMEM_BYTES (3*STAGE_BYTES)

template<int EPI, bool OSPLIT, bool OF32>
__global__ __launch_bounds__(256, 2)
void gemm_bf3(const __nv_bfloat16* __restrict__ Ah, const __nv_bfloat16* __restrict__ Al,
              const __nv_bfloat16* __restrict__ Bh, const __nv_bfloat16* __restrict__ Bl,
              const float* __restrict__ bias, const float* __restrict__ Res,
              float* __restrict__ C, __nv_bfloat16* __restrict__ Chi,
              __nv_bfloat16* __restrict__ Clo, int M, int N, int K)
{
    extern __shared__ __nv_bfloat16 smbuf[];
    const uint32_t smem_u32 = (uint32_t)__cvta_generic_to_shared(smbuf);

    const int tid = threadIdx.x;
    const int m0 = blockIdx.y * 128;
    const int n0 = blockIdx.x * 128;

    // ---- global->smem loader: warps 0-3 load A(h,l), warps 4-7 load B(h,l) ----
    const int lrow = tid & 127;
    const bool isB = tid >= 128;
    const __nv_bfloat16* pH = (isB ? Bh + (size_t)(n0 + lrow) * K
                                   : Ah + (size_t)(m0 + lrow) * K);
    const __nv_bfloat16* pL = (isB ? Bl + (size_t)(n0 + lrow) * K
                                   : Al + (size_t)(m0 + lrow) * K);
    const uint32_t regH = isB ? 16384u : 0u;
    const uint32_t rowb = (uint32_t)lrow * 16;

    auto load_stage = [&](int kt, int s) {
        const uint32_t sb = smem_u32 + (uint32_t)s * STAGE_BYTES + regH;
        const size_t gk = (size_t)kt * 32;
        #pragma unroll
        for (int ko = 0; ko < 4; ko++) {
            const uint32_t o = (uint32_t)ko * 2048 + rowb;
            cp16(sb + o,        pH + gk + ko*8);
            cp16(sb + 8192 + o, pL + gk + ko*8);
        }
        cp_commit();
    };

    // ---- warp/frag mapping: quad = 64x64 tile, wko = K-half within stage ----
    const int wid  = tid >> 5;
    const int lane = tid & 31;
    const int wko  = wid & 1;             // 0: k-chunks 0,1; 1: k-chunks 2,3
    const int quad = wid >> 1;            // 0..3
    const int wm = (quad >> 1) * 64;
    const int wn = (quad & 1) * 64;
    const int a_row = lane & 15;
    const int a_ko  = lane >> 4;
    const int b_row = (lane & 7) + ((lane & 16) >> 1);
    const int b_ko  = (lane >> 3) & 1;

    const uint32_t aoff = (uint32_t)(((wko*2 + a_ko)*1024 + (wm + a_row)*8) * 2);
    const uint32_t boff = (uint32_t)(16384 + ((wko*2 + b_ko)*1024 + (wn + b_row)*8) * 2);

    float acc[4][8][4];
    #pragma unroll
    for (int i = 0; i < 4; i++)
        #pragma unroll
        for (int j = 0; j < 8; j++)
            #pragma unroll
            for (int e = 0; e < 4; e++) acc[i][j][e] = 0.f;

    const int T = K >> 5;

    load_stage(0, 0);
    if (T > 1) load_stage(1, 1);

    for (int kt = 0; kt < T; kt++) {
        if (kt + 2 < T) { load_stage(kt + 2, (kt + 2) % 3); cp_wait2(); }
        else if (kt + 1 < T) cp_wait1();
        else cp_wait0();
        __syncthreads();

        const uint32_t sb = smem_u32 + (uint32_t)(kt % 3) * STAGE_BYTES;
        uint32_t a_h[4][4], a_l[4][4], b_h[16], b_l[16];
        #pragma unroll
        for (int mf = 0; mf < 4; mf++) {
            const uint32_t ad = sb + aoff + (uint32_t)mf*256;
            ldsm4(a_h[mf], ad);
            ldsm4(a_l[mf], ad + 8192);
        }
        #pragma unroll
        for (int nf2 = 0; nf2 < 4; nf2++) {
            const uint32_t bd = sb + boff + (uint32_t)nf2*256;
            ldsm4(&b_h[nf2*4], bd);
            ldsm4(&b_l[nf2*4], bd + 8192);
        }
        #pragma unroll
        for (int mf = 0; mf < 4; mf++)
            #pragma unroll
            for (int nf = 0; nf < 8; nf++) {
                mma16816(acc[mf][nf], a_h[mf], b_h[nf*2], b_h[nf*2+1]);
                mma16816(acc[mf][nf], a_h[mf], b_l[nf*2], b_l[nf*2+1]);
                mma16816(acc[mf][nf], a_l[mf], b_h[nf*2], b_h[nf*2+1]);
            }
        __syncthreads();
    }

    // ---- cross-warp K reduction: wko=1 partials -> smem -> wko=0 adds ----
    float* smf = (float*)smbuf;           // 64KB overlay on stage buffers
    if (wko == 1) {
        #pragma unroll
        for (int mf = 0; mf < 4; mf++)
            #pragma unroll
            for (int nf = 0; nf < 8; nf++)
                #pragma unroll
                for (int e = 0; e < 4; e++) {
                    const int idx = (mf*8 + nf)*4 + e;
                    smf[quad*4096 + idx*32 + lane] = acc[mf][nf][e];
                }
    }
    __syncthreads();
    if (wko == 0) {
        #pragma unroll
        for (int mf = 0; mf < 4; mf++)
            #pragma unroll
            for (int nf = 0; nf < 8; nf++)
                #pragma unroll
                for (int e = 0; e < 4; e++) {
                    const int idx = (mf*8 + nf)*4 + e;
                    acc[mf][nf][e] += smf[quad*4096 + idx*32 + lane];
                }

        // ---- epilogue (wko=0 warps only) ----
        const int er = lane >> 2;
        const int ec = (lane & 3) * 2;
        #pragma unroll
        for (int mf = 0; mf < 4; mf++) {
            #pragma unroll
            for (int nf = 0; nf < 8; nf++) {
                const int m = m0 + wm + mf*16 + er;
                const int n = n0 + wn + nf*8 + ec;
                const float2 bv = *(const float2*)(bias + n);
                #pragma unroll
                for (int half = 0; half < 2; half++) {
                    const int mm = m + half*8;
                    float t0 = acc[mf][nf][half*2+0] + bv.x;
                    float t1 = acc[mf][nf][half*2+1] + bv.y;
                    if (EPI == 1) {
                        t0 = 0.5f * t0 * (1.f + erff(t0 * 0.70710678118654752f));
                        t1 = 0.5f * t1 * (1.f + erff(t1 * 0.70710678118654752f));
                    }
                    if (EPI == 2) {
                        const float2 rv = *(const float2*)(Res + (size_t)mm * N + n);
                        t0 += rv.x; t1 += rv.y;
                    }
                    if (OF32) {
                        *(float2*)(C + (size_t)mm * N + n) = make_float2(t0, t1);
                    }
                    if (OSPLIT) {
                        __nv_bfloat16 h0,h1,l0,l1;
                        split1(t0,h0,l0); split1(t1,h1,l1);
                        *(uint32_t*)(Chi + (size_t)mm * N + n) = pack2(h0,h1);
                        *(uint32_t*)(Clo + (size_t)mm * N + n) = pack2(l0,l1);
                    }
                }
            }
        }
    }
}

// ---------------------------------------------------------------------------
// Tensor-core full attention (bf16x3 flash) — unchanged from round 7.
// ---------------------------------------------------------------------------
#define ATTN_TC_SMEM 65536

__global__ __launch_bounds__(128, 3)
void attn_tc_kernel(const __nv_bfloat16* __restrict__ qkvh,
                    const __nv_bfloat16* __restrict__ qkvl,
                    __nv_bfloat16* __restrict__ oh,
                    __nv_bfloat16* __restrict__ ol)
{
    extern __shared__ char smc[];
    const uint32_t sb = (uint32_t)__cvta_generic_to_shared(smc);

    const int bh = blockIdx.x;
    const int b  = bh >> 4;
    const int h  = bh & 15;
    const int qt = blockIdx.y;
    const int tid  = threadIdx.x;
    const int wid  = tid >> 5;
    const int lane = tid & 31;

    const int r    = tid >> 1;
    const int koh  = (tid & 1) * 4;

    {
        const size_t qrow = (size_t)(b*SLEN + qt*64 + r) * D3 + h*HD;
        #pragma unroll
        for (int it = 0; it < 4; it++) {
            const int ko = koh + it;
            const uint32_t dst = sb + (uint32_t)(((ko*64 + r)*8) * 2);
            cp16(dst,        qkvh + qrow + ko*8);
            cp16(dst + 8192, qkvl + qrow + ko*8);
        }
        cp_commit();
    }

    const int a_row = lane & 15;
    const int a_ko  = lane >> 4;
    const int b_row = (lane & 7) + ((lane & 16) >> 1);
    const int b_ko  = (lane >> 3) & 1;
    const int v_key = lane & 15;
    const int v_ko  = lane >> 4;

    uint32_t qa_h[4][4], qa_l[4][4];

    cp_wait0();
    __syncthreads();
    #pragma unroll
    for (int ks = 0; ks < 4; ks++) {
        const uint32_t ad = sb +
            (uint32_t)((((ks*2 + a_ko)*64 + wid*16 + a_row)*8) * 2);
        ldsm4(qa_h[ks], ad);
        ldsm4(qa_l[ks], ad + 8192);
    }
    __syncthreads();

    auto load_kv = [&](int kt, int s) {
        const uint32_t stg = sb + (uint32_t)s * 32768;
        const size_t krow = (size_t)(b*SLEN + kt*64 + r) * D3 + DDIM + h*HD;
        const size_t vrow = krow + DDIM;
        #pragma unroll
        for (int it = 0; it < 4; it++) {
            const int ko = koh + it;
            const uint32_t off = (uint32_t)(((ko*64 + r)*8) * 2);
            cp16(stg + off,          qkvh + krow + ko*8);
            cp16(stg + 8192  + off,  qkvl + krow + ko*8);
            cp16(stg + 16384 + off,  qkvh + vrow + ko*8);
            cp16(stg + 24576 + off,  qkvl + vrow + ko*8);
        }
    };

    load_kv(0, 0);
    cp_commit();

    float m0 = -1e30f, m1 = -1e30f, l0 = 0.f, l1 = 0.f;
    float oacc[8][4];
    #pragma unroll
    for (int nf = 0; nf < 8; nf++)
        #pragma unroll
        for (int e = 0; e < 4; e++) oacc[nf][e] = 0.f;

    for (int kt = 0; kt < 16; kt++) {
        const int s = kt & 1;
        if (kt + 1 < 16) {
            load_kv(kt + 1, s ^ 1);
            cp_commit();
            cp_wait1();
        } else {
            cp_wait0();
        }
        __syncthreads();

        const uint32_t stg = sb + (uint32_t)s * 32768;

        float sc[8][4];
        #pragma unroll
        for (int nf = 0; nf < 8; nf++)
            #pragma unroll
            for (int e = 0; e < 4; e++) sc[nf][e] = 0.f;

        #pragma unroll
        for (int ks = 0; ks < 4; ks++) {
            #pragma unroll
            for (int np = 0; np < 4; np++) {
                uint32_t kb[4], kl[4];
                const uint32_t kd = stg +
                    (uint32_t)((((ks*2 + b_ko)*64 + np*16 + b_row)*8) * 2);
                ldsm4(kb, kd);
                ldsm4(kl, kd + 8192);
                mma16816(sc[2*np],   qa_h[ks], kb[0], kb[1]);
                mma16816(sc[2*np],   qa_h[ks], kl[0], kl[1]);
                mma16816(sc[2*np],   qa_l[ks], kb[0], kb[1]);
                mma16816(sc[2*np+1], qa_h[ks], kb[2], kb[3]);
                mma16816(sc[2*np+1], qa_h[ks], kl[2], kl[3]);
                mma16816(sc[2*np+1], qa_l[ks], kb[2], kb[3]);
            }
        }

        #pragma unroll
        for (int nf = 0; nf < 8; nf++)
            #pragma unroll
            for (int e = 0; e < 4; e++) sc[nf][e] *= 0.125f;

        float mx0 = m0, mx1 = m1;
        #pragma unroll
        for (int nf = 0; nf < 8; nf++) {
            mx0 = fmaxf(mx0, fmaxf(sc[nf][0], sc[nf][1]));
            mx1 = fmaxf(mx1, fmaxf(sc[nf][2], sc[nf][3]));
        }
        mx0 = fmaxf(mx0, __shfl_xor_sync(0xffffffffu, mx0, 1));
        mx0 = fmaxf(mx0, __shfl_xor_sync(0xffffffffu, mx0, 2));
        mx1 = fmaxf(mx1, __shfl_xor_sync(0xffffffffu, mx1, 1));
        mx1 = fmaxf(mx1, __shfl_xor_sync(0xffffffffu, mx1, 2));

        const float al0 = __expf(m0 - mx0);
        const float al1 = __expf(m1 - mx1);
        m0 = mx0; m1 = mx1;

        float s0 = 0.f, s1 = 0.f;
        uint32_t pah[4][4], pal[4][4];
        #pragma unroll
        for (int nf = 0; nf < 8; nf++) {
            const float p0 = __expf(sc[nf][0] - m0);
            const float p1 = __expf(sc[nf][1] - m0);
            const float p2 = __expf(sc[nf][2] - m1);
            const float p3 = __expf(sc[nf][3] - m1);
            s0 += p0 + p1;
            s1 += p2 + p3;
            __nv_bfloat16 h0,h1,h2,h3,lo0,lo1,lo2,lo3;
            split1(p0,h0,lo0); split1(p1,h1,lo1);
            split1(p2,h2,lo2); split1(p3,h3,lo3);
            const int ks = nf >> 1;
            const int hv = (nf & 1) * 2;
            pah[ks][hv+0] = pack2(h0, h1);
            pah[ks][hv+1] = pack2(h2, h3);
            pal[ks][hv+0] = pack2(lo0, lo1);
            pal[ks][hv+1] = pack2(lo2, lo3);
        }
        s0 += __shfl_xor_sync(0xffffffffu, s0, 1);
        s0 += __shfl_xor_sync(0xffffffffu, s0, 2);
        s1 += __shfl_xor_sync(0xffffffffu, s1, 1);
        s1 += __shfl_xor_sync(0xffffffffu, s1, 2);
        l0 = l0 * al0 + s0;
        l1 = l1 * al1 + s1;

        #pragma unroll
        for (int nf = 0; nf < 8; nf++) {
            oacc[nf][0] *= al0; oacc[nf][1] *= al0;
            oacc[nf][2] *= al1; oacc[nf][3] *= al1;
        }

        #pragma unroll
        for (int ks = 0; ks < 4; ks++) {
            #pragma unroll
            for (int np = 0; np < 4; np++) {
                uint32_t vb[4], vl[4];
                const uint32_t vd = stg + 16384 +
                    (uint32_t)((((np*2 + v_ko)*64 + ks*16 + v_key)*8) * 2);
                ldsm4t(vb, vd);
                ldsm4t(vl, vd + 8192);
                mma16816(oacc[2*np],   pah[ks], vb[0], vb[1]);
                mma16816(oacc[2*np],   pah[ks], vl[0], vl[1]);
                mma16816(oacc[2*np],   pal[ks], vb[0], vb[1]);
                mma16816(oacc[2*np+1], pah[ks], vb[2], vb[3]);
                mma16816(oacc[2*np+1], pah[ks], vl[2], vl[3]);
                mma16816(oacc[2*np+1], pal[ks], vb[2], vb[3]);
            }
        }
        __syncthreads();
    }

    const float inv0 = 1.f / l0;
    const float inv1 = 1.f / l1;
    const int er  = lane >> 2;
    const int ec  = (lane & 3) * 2;
    const int tok0 = b*SLEN + qt*64 + wid*16 + er;
    const int tok1 = tok0 + 8;
    #pragma unroll
    for (int nf = 0; nf < 8; nf++) {
        const int col = h*HD + nf*8 + ec;
        const float o0 = oacc[nf][0] * inv0;
        const float o1 = oacc[nf][1] * inv0;
        const float o2 = oacc[nf][2] * inv1;
        const float o3 = oacc[nf][3] * inv1;
        __nv_bfloat16 h0,h1,h2,h3,lo0,lo1,lo2,lo3;
        split1(o0,h0,lo0); split1(o1,h1,lo1);
        split1(o2,h2,lo2); split1(o3,h3,lo3);
        *(uint32_t*)(oh + (size_t)tok0 * DDIM + col) = pack2(h0, h1);
        *(uint32_t*)(ol + (size_t)tok0 * DDIM + col) = pack2(lo0, lo1);
        *(uint32_t*)(oh + (size_t)tok1 * DDIM + col) = pack2(h2, h3);
        *(uint32_t*)(ol + (size_t)tok1 * DDIM + col) = pack2(lo2, lo3);
    }
}

// ---------------------------------------------------------------------------
// Banded attention — unchanged.
// ---------------------------------------------------------------------------
__global__ __launch_bounds__(256)
void attn_band_kernel(const __nv_bfloat16* __restrict__ qkvh,
                      const __nv_bfloat16* __restrict__ qkvl,
                      __nv_bfloat16* __restrict__ oh,
                      __nv_bfloat16* __restrict__ ol)
{
    const int gw   = (blockIdx.x * blockDim.x + threadIdx.x) >> 5;
    const int lane = threadIdx.x & 31;
    const int i = gw & (SLEN-1);
    const int h = (gw >> 10) & (HNUM-1);
    const int b = gw >> 14;

    const size_t qbase = (size_t)(b*SLEN + i) * D3 + h*HD;
    const float q0 = bf2f(qkvh[qbase + lane])      + bf2f(qkvl[qbase + lane]);
    const float q1 = bf2f(qkvh[qbase + 32 + lane]) + bf2f(qkvl[qbase + 32 + lane]);

    float sc[5];
    int   jc[5];
    #pragma unroll
    for (int jj = 0; jj < 5; jj++) {
        int j = i - 2 + jj;
        bool valid = (j >= 0) && (j < SLEN);
        jc[jj] = valid ? j : i;
        const size_t kb = (size_t)(b*SLEN + jc[jj]) * D3 + DDIM + h*HD;
        const float k0 = bf2f(qkvh[kb + lane])      + bf2f(qkvl[kb + lane]);
        const float k1 = bf2f(qkvh[kb + 32 + lane]) + bf2f(qkvl[kb + 32 + lane]);
        float p = q0 * k0 + q1 * k1;
        #pragma unroll
        for (int off = 16; off; off >>= 1) p += __shfl_xor_sync(0xffffffffu, p, off);
        sc[jj] = valid ? p * 0.125f : -1e30f;
    }
    float mx = sc[0];
    #pragma unroll
    for (int jj = 1; jj < 5; jj++) mx = fmaxf(mx, sc[jj]);
    float w[5], sum = 0.f;
    #pragma unroll
    for (int jj = 0; jj < 5; jj++) { w[jj] = __expf(sc[jj] - mx); sum += w[jj]; }
    const float inv = 1.f / sum;

    float o0 = 0.f, o1 = 0.f;
    #pragma unroll
    for (int jj = 0; jj < 5; jj++) {
        const size_t vb = (size_t)(b*SLEN + jc[jj]) * D3 + 2*DDIM + h*HD;
        const float v0 = bf2f(qkvh[vb + lane])      + bf2f(qkvl[vb + lane]);
        const float v1 = bf2f(qkvh[vb + 32 + lane]) + bf2f(qkvl[vb + 32 + lane]);
        o0 = fmaf(w[jj], v0, o0);
        o1 = fmaf(w[jj], v1, o1);
    }
    o0 *= inv; o1 *= inv;

    const size_t ob = (size_t)(b*SLEN + i) * DDIM + h*HD;
    __nv_bfloat16 hh, ll;
    split1(o0, hh, ll);
    oh[ob + lane] = hh;  ol[ob + lane] = ll;
    split1(o1, hh, ll);
    oh[ob + 32 + lane] = hh;  ol[ob + 32 + lane] = ll;
}

// ---------------------------------------------------------------------------
// LayerNorm — unchanged.
// ---------------------------------------------------------------------------
__global__ __launch_bounds__(256)
void ln_kernel(const float* __restrict__ a, const float* __restrict__ r,
               const float* __restrict__ g, const float* __restrict__ bt,
               float* __restrict__ out,
               __nv_bfloat16* __restrict__ ohh, __nv_bfloat16* __restrict__ oll)
{
    __shared__ float red[2][8];
    __shared__ float s_mean, s_rstd;
    const int n = blockIdx.x;
    const int tid = threadIdx.x;
    const size_t base = (size_t)n * DDIM + tid * 4;

    float4 va = *(const float4*)(a + base);
    if (r) {
        float4 vr = *(const float4*)(r + base);
        va.x += vr.x; va.y += vr.y; va.z += vr.z; va.w += vr.w;
    }
    float s  = va.x + va.y + va.z + va.w;
    float sq = va.x*va.x + va.y*va.y + va.z*va.z + va.w*va.w;

    #pragma unroll
    for (int off = 16; off; off >>= 1) {
        s  += __shfl_xor_sync(0xffffffffu, s,  off);
        sq += __shfl_xor_sync(0xffffffffu, sq, off);
    }
    const int wid = tid >> 5;
    if ((tid & 31) == 0) { red[0][wid] = s; red[1][wid] = sq; }
    __syncthreads();
    if (tid < 32) {
        float ts  = (tid < 8) ? red[0][tid] : 0.f;
        float tsq = (tid < 8) ? red[1][tid] : 0.f;
        #pragma unroll
        for (int off = 4; off; off >>= 1) {
            ts  += __shfl_xor_sync(0xffffffffu, ts,  off);
            tsq += __shfl_xor_sync(0xffffffffu, tsq, off);
        }
        if (tid == 0) {
            float mean = ts * (1.f / DDIM);
            float var  = tsq * (1.f / DDIM) - mean * mean;
            s_mean = mean;
            s_rstd = rsqrtf(var + EPS);
        }
    }
    __syncthreads();
    const float mean = s_mean, rstd = s_rstd;
    float4 gg = *(const float4*)(g + tid*4);
    float4 bb = *(const float4*)(bt + tid*4);
    float4 o;
    o.x = (va.x - mean) * rstd * gg.x + bb.x;
    o.y = (va.y - mean) * rstd * gg.y + bb.y;
    o.z = (va.z - mean) * rstd * gg.z + bb.z;
    o.w = (va.w - mean) * rstd * gg.w + bb.w;
    *(float4*)(out + base) = o;
    if (ohh) {
        __nv_bfloat16 h0,h1,h2,h3,l0,l1,l2,l3;
        split1(o.x,h0,l0); split1(o.y,h1,l1); split1(o.z,h2,l2); split1(o.w,h3,l3);
        uint2 uh; uh.x = pack2(h0,h1); uh.y = pack2(h2,h3);
        uint2 ul; ul.x = pack2(l0,l1); ul.y = pack2(l2,l3);
        *(uint2*)(ohh + base) = uh;
        *(uint2*)(oll + base) = ul;
    }
}

// ---------------------------------------------------------------------------
// Orchestration
// ---------------------------------------------------------------------------
extern "C" void kernel_launch(void* const* d_in, const int* in_sizes, int n_in,
                              void* d_out, int out_size)
{
    const float* x_in   = (const float*)d_in[0];
    const float* w_in1  = (const float*)d_in[1];
    const float* b_in1  = (const float*)d_in[2];
    const float* w_out1 = (const float*)d_in[3];
    const float* b_out1 = (const float*)d_in[4];
    const float* ln1_g  = (const float*)d_in[5];
    const float* ln1_b  = (const float*)d_in[6];
    const float* w_in2  = (const float*)d_in[7];
    const float* b_in2  = (const float*)d_in[8];
    const float* w_out2 = (const float*)d_in[9];
    const float* b_out2 = (const float*)d_in[10];
    const float* ln2_g  = (const float*)d_in[11];
    const float* ln2_b  = (const float*)d_in[12];
    const float* ffn_w1 = (const float*)d_in[13];
    const float* ffn_b1 = (const float*)d_in[14];
    const float* ffn_w2 = (const float*)d_in[15];
    const float* ffn_b2 = (const float*)d_in[16];
    const float* lnf_g  = (const float*)d_in[17];
    const float* lnf_b  = (const float*)d_in[18];

    float *PROJ, *X, *X2, *ATT;
    __nv_bfloat16 *WH, *WL, *QKVH, *QKVL, *P1H, *P1L, *P2H, *P2L;
    cudaGetSymbolAddress((void**)&PROJ, g_proj);
    cudaGetSymbolAddress((void**)&X,    g_x);
    cudaGetSymbolAddress((void**)&X2,   g_x2);
    cudaGetSymbolAddress((void**)&ATT,  g_att);
    cudaGetSymbolAddress((void**)&WH,   g_wh);
    cudaGetSymbolAddress((void**)&WL,   g_wl);
    cudaGetSymbolAddress((void**)&QKVH, g_qkvh);
    cudaGetSymbolAddress((void**)&QKVL, g_qkvl);
    cudaGetSymbolAddress((void**)&P1H,  g_p1h);
    cudaGetSymbolAddress((void**)&P1L,  g_p1l);
    cudaGetSymbolAddress((void**)&P2H,  g_p2h);
    cudaGetSymbolAddress((void**)&P2L,  g_p2l);

    cudaFuncSetAttribute(attn_tc_kernel,
                         cudaFuncAttributeMaxDynamicSharedMemorySize, ATTN_TC_SMEM);
    cudaFuncSetAttribute(gemm_bf3<0,true,false>,
                         cudaFuncAttributeMaxDynamicSharedMemorySize, GSMEM_BYTES);
    cudaFuncSetAttribute(gemm_bf3<0,false,true>,
                         cudaFuncAttributeMaxDynamicSharedMemorySize, GSMEM_BYTES);
    cudaFuncSetAttribute(gemm_bf3<1,true,false>,
                         cudaFuncAttributeMaxDynamicSharedMemorySize, GSMEM_BYTES);
    cudaFuncSetAttribute(gemm_bf3<2,true,true>,
                         cudaFuncAttributeMaxDynamicSharedMemorySize, GSMEM_BYTES);

    const dim3 blk(256);
    const dim3 gblk(256);
    const dim3 g_qkvp(D3/128,  NTOK/128);    // (24,16)
    const dim3 g_outp(DDIM/128, NTOK/128);   // (8,16)
    const dim3 g_ffn1(MDIM/128, NTOK/128);   // (32,16)
    const dim3 g_attn(BNUM*HNUM, SLEN/64);   // (32,16)
    const int  g_band = (BNUM*HNUM*SLEN*32) / 256;
    const int  g_ln   = NTOK;

    // ---- single merged split launch: all 6 weights + layer-0 input ----
    split_all_kernel<<<SPLIT_TOTAL_BLOCKS, blk>>>(
        w_in1, w_out1, w_in2, w_out2, ffn_w1, ffn_w2, x_in,
        WH, WL, P1H, P1L);

    const float* xcur = x_in;
    for (int l = 0; l < LNUM; l++) {
        const size_t oW3 = (size_t)l * D3 * DDIM;
        const size_t oW1 = (size_t)l * DDIM * DDIM;
        const size_t oWm = (size_t)l * MDIM * DDIM;

        // ---- intra-frame full MHA ----
        gemm_bf3<0,true,false><<<g_qkvp, gblk, GSMEM_BYTES>>>(
            P1H, P1L, WH+W_IN1_OFF+oW3, WL+W_IN1_OFF+oW3,
            b_in1 + (size_t)l*D3, nullptr, nullptr, QKVH, QKVL, NTOK, D3, DDIM);
        attn_tc_kernel<<<g_attn, 128, ATTN_TC_SMEM>>>(QKVH, QKVL, P1H, P1L);
        gemm_bf3<0,false,true><<<g_outp, gblk, GSMEM_BYTES>>>(
            P1H, P1L, WH+W_OUT1_OFF+oW1, WL+W_OUT1_OFF+oW1,
            b_out1 + (size_t)l*DDIM, nullptr, PROJ, nullptr, nullptr, NTOK, DDIM, DDIM);
        ln_kernel<<<g_ln, blk>>>(PROJ, xcur, ln1_g + (size_t)l*DDIM,
                                 ln1_b + (size_t)l*DDIM, X2, P1H, P1L);

        // ---- inter-frame banded MHA ----
        gemm_bf3<0,true,false><<<g_qkvp, gblk, GSMEM_BYTES>>>(
            P1H, P1L, WH+W_IN2_OFF+oW3, WL+W_IN2_OFF+oW3,
            b_in2 + (size_t)l*D3, nullptr, nullptr, QKVH, QKVL, NTOK, D3, DDIM);
        attn_band_kernel<<<g_band, blk>>>(QKVH, QKVL, P1H, P1L);
        gemm_bf3<0,false,true><<<g_outp, gblk, GSMEM_BYTES>>>(
            P1H, P1L, WH+W_OUT2_OFF+oW1, WL+W_OUT2_OFF+oW1,
            b_out2 + (size_t)l*DDIM, nullptr, PROJ, nullptr, nullptr, NTOK, DDIM, DDIM);
        ln_kernel<<<g_ln, blk>>>(PROJ, X2, ln2_g + (size_t)l*DDIM,
                                 ln2_b + (size_t)l*DDIM, ATT, P1H, P1L);

        // ---- FFN ----
        gemm_bf3<1,true,false><<<g_ffn1, gblk, GSMEM_BYTES>>>(
            P1H, P1L, WH+FW1_OFF+oWm, WL+FW1_OFF+oWm,
            ffn_b1 + (size_t)l*MDIM, nullptr, nullptr, P2H, P2L, NTOK, MDIM, DDIM);
        gemm_bf3<2,true,true><<<g_outp, gblk, GSMEM_BYTES>>>(
            P2H, P2L, WH+FW2_OFF+oWm, WL+FW2_OFF+oWm,
            ffn_b2 + (size_t)l*DDIM, ATT, X, P1H, P1L, NTOK, DDIM, MDIM);
        xcur = X;
    }

    ln_kernel<<<g_ln, blk>>>(xcur, nullptr, lnf_g, lnf_b, (float*)d_out,
                             nullptr, nullptr);
}

// round 10
// speedup vs baseline: 1.7672x; 1.7672x over previous
#include <cuda_runtime.h>
#include <cuda_bf16.h>
#include <math.h>
#include <stdint.h>

// ---------------------------------------------------------------------------
// Problem constants
// ---------------------------------------------------------------------------
#define LNUM 4
#define DDIM 1024
#define HNUM 16
#define HD   64
#define MDIM 4096
#define SLEN 1024
#define BNUM 2
#define NTOK (BNUM*SLEN)        // 2048
#define D3   (3*DDIM)           // 3072
#define EPS  1e-5f

// Weight split array layout (element offsets)
#define W_IN1_OFF   0u
#define W_OUT1_OFF  12582912u
#define W_IN2_OFF   16777216u
#define W_OUT2_OFF  29360128u
#define FW1_OFF     33554432u
#define FW2_OFF     50331648u
#define WTOTAL      67108864u

// ---------------------------------------------------------------------------
// Device scratch (no allocations allowed)
// ---------------------------------------------------------------------------
static __device__ float g_proj[NTOK*DDIM];
static __device__ float g_x   [NTOK*DDIM];
static __device__ float g_x2  [NTOK*DDIM];
static __device__ float g_att [NTOK*DDIM];

static __device__ __nv_bfloat16 g_wh[WTOTAL];        // weight hi
static __device__ __nv_bfloat16 g_wl[WTOTAL];        // weight lo
static __device__ __nv_bfloat16 g_qkvh[NTOK*D3];     // qkv hi
static __device__ __nv_bfloat16 g_qkvl[NTOK*D3];     // qkv lo
static __device__ __nv_bfloat16 g_p1h[NTOK*DDIM];
static __device__ __nv_bfloat16 g_p1l[NTOK*DDIM];
static __device__ __nv_bfloat16 g_p2h[NTOK*MDIM];
static __device__ __nv_bfloat16 g_p2l[NTOK*MDIM];

// ---------------------------------------------------------------------------
// Helpers
// ---------------------------------------------------------------------------
__device__ __forceinline__ void cp16(uint32_t d, const void* s) {
    asm volatile("cp.async.cg.shared.global [%0], [%1], 16;\n" :: "r"(d), "l"(s));
}
__device__ __forceinline__ void cp_commit() {
    asm volatile("cp.async.commit_group;\n" ::: "memory");
}
__device__ __forceinline__ void cp_wait2() {
    asm volatile("cp.async.wait_group 2;\n" ::: "memory");
}
__device__ __forceinline__ void cp_wait1() {
    asm volatile("cp.async.wait_group 1;\n" ::: "memory");
}
__device__ __forceinline__ void cp_wait0() {
    asm volatile("cp.async.wait_group 0;\n" ::: "memory");
}
__device__ __forceinline__ void ldsm4(uint32_t* r, uint32_t a) {
    asm volatile("ldmatrix.sync.aligned.m8n8.x4.shared.b16 {%0,%1,%2,%3}, [%4];"
        : "=r"(r[0]), "=r"(r[1]), "=r"(r[2]), "=r"(r[3]) : "r"(a));
}
__device__ __forceinline__ void ldsm4t(uint32_t* r, uint32_t a) {
    asm volatile("ldmatrix.sync.aligned.m8n8.x4.trans.shared.b16 {%0,%1,%2,%3}, [%4];"
        : "=r"(r[0]), "=r"(r[1]), "=r"(r[2]), "=r"(r[3]) : "r"(a));
}
__device__ __forceinline__ void mma16816(float* c, const uint32_t* a,
                                         uint32_t b0, uint32_t b1) {
    asm volatile(
        "mma.sync.aligned.m16n8k16.row.col.f32.bf16.bf16.f32 "
        "{%0,%1,%2,%3},{%4,%5,%6,%7},{%8,%9},{%0,%1,%2,%3};"
        : "+f"(c[0]), "+f"(c[1]), "+f"(c[2]), "+f"(c[3])
        : "r"(a[0]), "r"(a[1]), "r"(a[2]), "r"(a[3]), "r"(b0), "r"(b1));
}
__device__ __forceinline__ uint32_t pack2(__nv_bfloat16 a, __nv_bfloat16 b) {
    __nv_bfloat162 t = __halves2bfloat162(a, b);
    return *reinterpret_cast<uint32_t*>(&t);
}
__device__ __forceinline__ void split1(float v, __nv_bfloat16& h, __nv_bfloat16& l) {
    h = __float2bfloat16(v);
    l = __float2bfloat16(v - __bfloat162float(h));
}
__device__ __forceinline__ float bf2f(__nv_bfloat16 v) { return __bfloat162float(v); }

// ---------------------------------------------------------------------------
// Merged fp32 -> (hi,lo) bf16 split for all 6 weight tensors + x_in.
// ---------------------------------------------------------------------------
#define SPLIT_TOTAL_BLOCKS 16896

__global__ __launch_bounds__(256)
void split_all_kernel(const float* __restrict__ w_in1, const float* __restrict__ w_out1,
                      const float* __restrict__ w_in2, const float* __restrict__ w_out2,
                      const float* __restrict__ fw1,  const float* __restrict__ fw2,
                      const float* __restrict__ x,
                      __nv_bfloat16* __restrict__ WH, __nv_bfloat16* __restrict__ WL,
                      __nv_bfloat16* __restrict__ P1H, __nv_bfloat16* __restrict__ P1L)
{
    const int bid = blockIdx.x;
    const float* src;
    __nv_bfloat16 *dh, *dl;
    int rb;
    if (bid < 3072)       { src = w_in1;  dh = WH + W_IN1_OFF;  dl = WL + W_IN1_OFF;  rb = bid; }
    else if (bid < 4096)  { src = w_out1; dh = WH + W_OUT1_OFF; dl = WL + W_OUT1_OFF; rb = bid - 3072; }
    else if (bid < 7168)  { src = w_in2;  dh = WH + W_IN2_OFF;  dl = WL + W_IN2_OFF;  rb = bid - 4096; }
    else if (bid < 8192)  { src = w_out2; dh = WH + W_OUT2_OFF; dl = WL + W_OUT2_OFF; rb = bid - 7168; }
    else if (bid < 12288) { src = fw1;    dh = WH + FW1_OFF;    dl = WL + FW1_OFF;    rb = bid - 8192; }
    else if (bid < 16384) { src = fw2;    dh = WH + FW2_OFF;    dl = WL + FW2_OFF;    rb = bid - 12288; }
    else                  { src = x;      dh = P1H;             dl = P1L;             rb = bid - 16384; }

    const size_t base = (size_t)rb * 4096 + threadIdx.x * 4;
    #pragma unroll
    for (int j = 0; j < 4; j++) {
        const size_t i = base + j * 1024;
        float4 v = *(const float4*)(src + i);
        __nv_bfloat16 h0,h1,h2,h3,l0,l1,l2,l3;
        split1(v.x,h0,l0); split1(v.y,h1,l1); split1(v.z,h2,l2); split1(v.w,h3,l3);
        uint2 uh; uh.x = pack2(h0,h1); uh.y = pack2(h2,h3);
        uint2 ul; ul.x = pack2(l0,l1); ul.y = pack2(l2,l3);
        *(uint2*)(dh + i) = uh;
        *(uint2*)(dl + i) = ul;
    }
}

// ---------------------------------------------------------------------------
// bf16x3 tensor-core GEMM: C[M,N] = A[M,K] @ Bw[N,K]^T + bias (+ epilogue)
// CTA tile 128x128x32; 256 threads, 8 warps, warp tile 32x64 (4x2 grid).
// acc = 64 floats/thread -> no register spills under the 128-reg/2-CTA cap.
// B fragments consumed per-nf2 to keep live registers ~100.
// 3-stage cp.async pipeline (96KB smem, 2 CTA/SM -> 4 warps/SMSP).
// EPI: 0=bias, 1=bias+GELU, 2=bias+residual.
// ---------------------------------------------------------------------------
#define STAGE_BYTES 32768
#define GSMEM_BYTES (3*STAGE_BYTES)

template<int EPI, bool OSPLIT, bool OF32>
__global__ __launch_bounds__(256, 2)
void gemm_bf3(const __nv_bfloat16* __restrict__ Ah, const __nv_bfloat16* __restrict__ Al,
              const __nv_bfloat16* __restrict__ Bh, const __nv_bfloat16* __restrict__ Bl,
              const float* __restrict__ bias, const float* __restrict__ Res,
              float* __restrict__ C, __nv_bfloat16* __restrict__ Chi,
              __nv_bfloat16* __restrict__ Clo, int M, int N, int K)
{
    extern __shared__ __nv_bfloat16 smbuf[];
    const uint32_t smem_u32 = (uint32_t)__cvta_generic_to_shared(smbuf);

    const int tid = threadIdx.x;
    const int m0 = blockIdx.y * 128;
    const int n0 = blockIdx.x * 128;

    // ---- global->smem loader: warps 0-3 load A(h,l), warps 4-7 load B(h,l) ----
    const int lrow = tid & 127;
    const bool isB = tid >= 128;
    const __nv_bfloat16* pH = (isB ? Bh + (size_t)(n0 + lrow) * K
                                   : Ah + (size_t)(m0 + lrow) * K);
    const __nv_bfloat16* pL = (isB ? Bl + (size_t)(n0 + lrow) * K
                                   : Al + (size_t)(m0 + lrow) * K);
    const uint32_t regH = isB ? 16384u : 0u;
    const uint32_t rowb = (uint32_t)lrow * 16;

    auto load_stage = [&](int kt, int s) {
        const uint32_t sb = smem_u32 + (uint32_t)s * STAGE_BYTES + regH;
        const size_t gk = (size_t)kt * 32;
        #pragma unroll
        for (int ko = 0; ko < 4; ko++) {
            const uint32_t o = (uint32_t)ko * 2048 + rowb;
            cp16(sb + o,        pH + gk + ko*8);
            cp16(sb + 8192 + o, pL + gk + ko*8);
        }
        cp_commit();
    };

    // ---- warp/frag mapping: 8 warps, 4 (m) x 2 (n), warp tile 32x64 ----
    const int wid  = tid >> 5;
    const int lane = tid & 31;
    const int wm = (wid >> 1) * 32;       // 0,32,64,96
    const int wn = (wid & 1) * 64;        // 0,64
    const int a_row = lane & 15;
    const int a_ko  = lane >> 4;
    const int b_row = (lane & 7) + ((lane & 16) >> 1);
    const int b_ko  = (lane >> 3) & 1;

    const uint32_t aoff = (uint32_t)((a_ko*1024 + (wm + a_row)*8) * 2);
    const uint32_t boff = (uint32_t)(16384 + (b_ko*1024 + (wn + b_row)*8) * 2);

    float acc[2][8][4];
    #pragma unroll
    for (int i = 0; i < 2; i++)
        #pragma unroll
        for (int j = 0; j < 8; j++)
            #pragma unroll
            for (int e = 0; e < 4; e++) acc[i][j][e] = 0.f;

    const int T = K >> 5;

    load_stage(0, 0);
    if (T > 1) load_stage(1, 1);

    for (int kt = 0; kt < T; kt++) {
        if (kt + 2 < T) { load_stage(kt + 2, (kt + 2) % 3); cp_wait2(); }
        else if (kt + 1 < T) cp_wait1();
        else cp_wait0();
        __syncthreads();

        const uint32_t sb = smem_u32 + (uint32_t)(kt % 3) * STAGE_BYTES;
        #pragma unroll
        for (int ko0 = 0; ko0 < 4; ko0 += 2) {
            uint32_t a_h[2][4], a_l[2][4];
            #pragma unroll
            for (int mf = 0; mf < 2; mf++) {
                const uint32_t ad = sb + aoff + (uint32_t)ko0*2048 + (uint32_t)mf*256;
                ldsm4(a_h[mf], ad);
                ldsm4(a_l[mf], ad + 8192);
            }
            #pragma unroll
            for (int nf2 = 0; nf2 < 4; nf2++) {
                uint32_t b_h[4], b_l[4];
                const uint32_t bd = sb + boff + (uint32_t)ko0*2048 + (uint32_t)nf2*256;
                ldsm4(b_h, bd);
                ldsm4(b_l, bd + 8192);
                #pragma unroll
                for (int mf = 0; mf < 2; mf++) {
                    const int nf = nf2 * 2;
                    mma16816(acc[mf][nf],   a_h[mf], b_h[0], b_h[1]);
                    mma16816(acc[mf][nf],   a_h[mf], b_l[0], b_l[1]);
                    mma16816(acc[mf][nf],   a_l[mf], b_h[0], b_h[1]);
                    mma16816(acc[mf][nf+1], a_h[mf], b_h[2], b_h[3]);
                    mma16816(acc[mf][nf+1], a_h[mf], b_l[2], b_l[3]);
                    mma16816(acc[mf][nf+1], a_l[mf], b_h[2], b_h[3]);
                }
            }
        }
        __syncthreads();
    }

    // ---- epilogue ----
    const int er = lane >> 2;
    const int ec = (lane & 3) * 2;
    #pragma unroll
    for (int mf = 0; mf < 2; mf++) {
        #pragma unroll
        for (int nf = 0; nf < 8; nf++) {
            const int m = m0 + wm + mf*16 + er;
            const int n = n0 + wn + nf*8 + ec;
            const float2 bv = *(const float2*)(bias + n);
            #pragma unroll
            for (int half = 0; half < 2; half++) {
                const int mm = m + half*8;
                float t0 = acc[mf][nf][half*2+0] + bv.x;
                float t1 = acc[mf][nf][half*2+1] + bv.y;
                if (EPI == 1) {
                    t0 = 0.5f * t0 * (1.f + erff(t0 * 0.70710678118654752f));
                    t1 = 0.5f * t1 * (1.f + erff(t1 * 0.70710678118654752f));
                }
                if (EPI == 2) {
                    const float2 rv = *(const float2*)(Res + (size_t)mm * N + n);
                    t0 += rv.x; t1 += rv.y;
                }
                if (OF32) {
                    *(float2*)(C + (size_t)mm * N + n) = make_float2(t0, t1);
                }
                if (OSPLIT) {
                    __nv_bfloat16 h0,h1,l0,l1;
                    split1(t0,h0,l0); split1(t1,h1,l1);
                    *(uint32_t*)(Chi + (size_t)mm * N + n) = pack2(h0,h1);
                    *(uint32_t*)(Clo + (size_t)mm * N + n) = pack2(l0,l1);
                }
            }
        }
    }
}

// ---------------------------------------------------------------------------
// Tensor-core full attention (bf16x3 flash) — round 7 version (known good).
// ---------------------------------------------------------------------------
#define ATTN_TC_SMEM 65536

__global__ __launch_bounds__(128, 3)
void attn_tc_kernel(const __nv_bfloat16* __restrict__ qkvh,
                    const __nv_bfloat16* __restrict__ qkvl,
                    __nv_bfloat16* __restrict__ oh,
                    __nv_bfloat16* __restrict__ ol)
{
    extern __shared__ char smc[];
    const uint32_t sb = (uint32_t)__cvta_generic_to_shared(smc);

    const int bh = blockIdx.x;
    const int b  = bh >> 4;
    const int h  = bh & 15;
    const int qt = blockIdx.y;
    const int tid  = threadIdx.x;
    const int wid  = tid >> 5;
    const int lane = tid & 31;

    const int r    = tid >> 1;
    const int koh  = (tid & 1) * 4;

    {
        const size_t qrow = (size_t)(b*SLEN + qt*64 + r) * D3 + h*HD;
        #pragma unroll
        for (int it = 0; it < 4; it++) {
            const int ko = koh + it;
            const uint32_t dst = sb + (uint32_t)(((ko*64 + r)*8) * 2);
            cp16(dst,        qkvh + qrow + ko*8);
            cp16(dst + 8192, qkvl + qrow + ko*8);
        }
        cp_commit();
    }

    const int a_row = lane & 15;
    const int a_ko  = lane >> 4;
    const int b_row = (lane & 7) + ((lane & 16) >> 1);
    const int b_ko  = (lane >> 3) & 1;
    const int v_key = lane & 15;
    const int v_ko  = lane >> 4;

    uint32_t qa_h[4][4], qa_l[4][4];

    cp_wait0();
    __syncthreads();
    #pragma unroll
    for (int ks = 0; ks < 4; ks++) {
        const uint32_t ad = sb +
            (uint32_t)((((ks*2 + a_ko)*64 + wid*16 + a_row)*8) * 2);
        ldsm4(qa_h[ks], ad);
        ldsm4(qa_l[ks], ad + 8192);
    }
    __syncthreads();

    auto load_kv = [&](int kt, int s) {
        const uint32_t stg = sb + (uint32_t)s * 32768;
        const size_t krow = (size_t)(b*SLEN + kt*64 + r) * D3 + DDIM + h*HD;
        const size_t vrow = krow + DDIM;
        #pragma unroll
        for (int it = 0; it < 4; it++) {
            const int ko = koh + it;
            const uint32_t off = (uint32_t)(((ko*64 + r)*8) * 2);
            cp16(stg + off,          qkvh + krow + ko*8);
            cp16(stg + 8192  + off,  qkvl + krow + ko*8);
            cp16(stg + 16384 + off,  qkvh + vrow + ko*8);
            cp16(stg + 24576 + off,  qkvl + vrow + ko*8);
        }
    };

    load_kv(0, 0);
    cp_commit();

    float m0 = -1e30f, m1 = -1e30f, l0 = 0.f, l1 = 0.f;
    float oacc[8][4];
    #pragma unroll
    for (int nf = 0; nf < 8; nf++)
        #pragma unroll
        for (int e = 0; e < 4; e++) oacc[nf][e] = 0.f;

    for (int kt = 0; kt < 16; kt++) {
        const int s = kt & 1;
        if (kt + 1 < 16) {
            load_kv(kt + 1, s ^ 1);
            cp_commit();
            cp_wait1();
        } else {
            cp_wait0();
        }
        __syncthreads();

        const uint32_t stg = sb + (uint32_t)s * 32768;

        float sc[8][4];
        #pragma unroll
        for (int nf = 0; nf < 8; nf++)
            #pragma unroll
            for (int e = 0; e < 4; e++) sc[nf][e] = 0.f;

        #pragma unroll
        for (int ks = 0; ks < 4; ks++) {
            #pragma unroll
            for (int np = 0; np < 4; np++) {
                uint32_t kb[4], kl[4];
                const uint32_t kd = stg +
                    (uint32_t)((((ks*2 + b_ko)*64 + np*16 + b_row)*8) * 2);
                ldsm4(kb, kd);
                ldsm4(kl, kd + 8192);
                mma16816(sc[2*np],   qa_h[ks], kb[0], kb[1]);
                mma16816(sc[2*np],   qa_h[ks], kl[0], kl[1]);
                mma16816(sc[2*np],   qa_l[ks], kb[0], kb[1]);
                mma16816(sc[2*np+1], qa_h[ks], kb[2], kb[3]);
                mma16816(sc[2*np+1], qa_h[ks], kl[2], kl[3]);
                mma16816(sc[2*np+1], qa_l[ks], kb[2], kb[3]);
            }
        }

        #pragma unroll
        for (int nf = 0; nf < 8; nf++)
            #pragma unroll
            for (int e = 0; e < 4; e++) sc[nf][e] *= 0.125f;

        float mx0 = m0, mx1 = m1;
        #pragma unroll
        for (int nf = 0; nf < 8; nf++) {
            mx0 = fmaxf(mx0, fmaxf(sc[nf][0], sc[nf][1]));
            mx1 = fmaxf(mx1, fmaxf(sc[nf][2], sc[nf][3]));
        }
        mx0 = fmaxf(mx0, __shfl_xor_sync(0xffffffffu, mx0, 1));
        mx0 = fmaxf(mx0, __shfl_xor_sync(0xffffffffu, mx0, 2));
        mx1 = fmaxf(mx1, __shfl_xor_sync(0xffffffffu, mx1, 1));
        mx1 = fmaxf(mx1, __shfl_xor_sync(0xffffffffu, mx1, 2));

        const float al0 = __expf(m0 - mx0);
        const float al1 = __expf(m1 - mx1);
        m0 = mx0; m1 = mx1;

        float s0 = 0.f, s1 = 0.f;
        uint32_t pah[4][4], pal[4][4];
        #pragma unroll
        for (int nf = 0; nf < 8; nf++) {
            const float p0 = __expf(sc[nf][0] - m0);
            const float p1 = __expf(sc[nf][1] - m0);
            const float p2 = __expf(sc[nf][2] - m1);
            const float p3 = __expf(sc[nf][3] - m1);
            s0 += p0 + p1;
            s1 += p2 + p3;
            __nv_bfloat16 h0,h1,h2,h3,lo0,lo1,lo2,lo3;
            split1(p0,h0,lo0); split1(p1,h1,lo1);
            split1(p2,h2,lo2); split1(p3,h3,lo3);
            const int ks = nf >> 1;
            const int hv = (nf & 1) * 2;
            pah[ks][hv+0] = pack2(h0, h1);
            pah[ks][hv+1] = pack2(h2, h3);
            pal[ks][hv+0] = pack2(lo0, lo1);
            pal[ks][hv+1] = pack2(lo2, lo3);
        }
        s0 += __shfl_xor_sync(0xffffffffu, s0, 1);
        s0 += __shfl_xor_sync(0xffffffffu, s0, 2);
        s1 += __shfl_xor_sync(0xffffffffu, s1, 1);
        s1 += __shfl_xor_sync(0xffffffffu, s1, 2);
        l0 = l0 * al0 + s0;
        l1 = l1 * al1 + s1;

        #pragma unroll
        for (int nf = 0; nf < 8; nf++) {
            oacc[nf][0] *= al0; oacc[nf][1] *= al0;
            oacc[nf][2] *= al1; oacc[nf][3] *= al1;
        }

        #pragma unroll
        for (int ks = 0; ks < 4; ks++) {
            #pragma unroll
            for (int np = 0; np < 4; np++) {
                uint32_t vb[4], vl[4];
                const uint32_t vd = stg + 16384 +
                    (uint32_t)((((np*2 + v_ko)*64 + ks*16 + v_key)*8) * 2);
                ldsm4t(vb, vd);
                ldsm4t(vl, vd + 8192);
                mma16816(oacc[2*np],   pah[ks], vb[0], vb[1]);
                mma16816(oacc[2*np],   pah[ks], vl[0], vl[1]);
                mma16816(oacc[2*np],   pal[ks], vb[0], vb[1]);
                mma16816(oacc[2*np+1], pah[ks], vb[2], vb[3]);
                mma16816(oacc[2*np+1], pah[ks], vl[2], vl[3]);
                mma16816(oacc[2*np+1], pal[ks], vb[2], vb[3]);
            }
        }
        __syncthreads();
    }

    const float inv0 = 1.f / l0;
    const float inv1 = 1.f / l1;
    const int er  = lane >> 2;
    const int ec  = (lane & 3) * 2;
    const int tok0 = b*SLEN + qt*64 + wid*16 + er;
    const int tok1 = tok0 + 8;
    #pragma unroll
    for (int nf = 0; nf < 8; nf++) {
        const int col = h*HD + nf*8 + ec;
        const float o0 = oacc[nf][0] * inv0;
        const float o1 = oacc[nf][1] * inv0;
        const float o2 = oacc[nf][2] * inv1;
        const float o3 = oacc[nf][3] * inv1;
        __nv_bfloat16 h0,h1,h2,h3,lo0,lo1,lo2,lo3;
        split1(o0,h0,lo0); split1(o1,h1,lo1);
        split1(o2,h2,lo2); split1(o3,h3,lo3);
        *(uint32_t*)(oh + (size_t)tok0 * DDIM + col) = pack2(h0, h1);
        *(uint32_t*)(ol + (size_t)tok0 * DDIM + col) = pack2(lo0, lo1);
        *(uint32_t*)(oh + (size_t)tok1 * DDIM + col) = pack2(h2, h3);
        *(uint32_t*)(ol + (size_t)tok1 * DDIM + col) = pack2(lo2, lo3);
    }
}

// ---------------------------------------------------------------------------
// Banded attention — unchanged.
// ---------------------------------------------------------------------------
__global__ __launch_bounds__(256)
void attn_band_kernel(const __nv_bfloat16* __restrict__ qkvh,
                      const __nv_bfloat16* __restrict__ qkvl,
                      __nv_bfloat16* __restrict__ oh,
                      __nv_bfloat16* __restrict__ ol)
{
    const int gw   = (blockIdx.x * blockDim.x + threadIdx.x) >> 5;
    const int lane = threadIdx.x & 31;
    const int i = gw & (SLEN-1);
    const int h = (gw >> 10) & (HNUM-1);
    const int b = gw >> 14;

    const size_t qbase = (size_t)(b*SLEN + i) * D3 + h*HD;
    const float q0 = bf2f(qkvh[qbase + lane])      + bf2f(qkvl[qbase + lane]);
    const float q1 = bf2f(qkvh[qbase + 32 + lane]) + bf2f(qkvl[qbase + 32 + lane]);

    float sc[5];
    int   jc[5];
    #pragma unroll
    for (int jj = 0; jj < 5; jj++) {
        int j = i - 2 + jj;
        bool valid = (j >= 0) && (j < SLEN);
        jc[jj] = valid ? j : i;
        const size_t kb = (size_t)(b*SLEN + jc[jj]) * D3 + DDIM + h*HD;
        const float k0 = bf2f(qkvh[kb + lane])      + bf2f(qkvl[kb + lane]);
        const float k1 = bf2f(qkvh[kb + 32 + lane]) + bf2f(qkvl[kb + 32 + lane]);
        float p = q0 * k0 + q1 * k1;
        #pragma unroll
        for (int off = 16; off; off >>= 1) p += __shfl_xor_sync(0xffffffffu, p, off);
        sc[jj] = valid ? p * 0.125f : -1e30f;
    }
    float mx = sc[0];
    #pragma unroll
    for (int jj = 1; jj < 5; jj++) mx = fmaxf(mx, sc[jj]);
    float w[5], sum = 0.f;
    #pragma unroll
    for (int jj = 0; jj < 5; jj++) { w[jj] = __expf(sc[jj] - mx); sum += w[jj]; }
    const float inv = 1.f / sum;

    float o0 = 0.f, o1 = 0.f;
    #pragma unroll
    for (int jj = 0; jj < 5; jj++) {
        const size_t vb = (size_t)(b*SLEN + jc[jj]) * D3 + 2*DDIM + h*HD;
        const float v0 = bf2f(qkvh[vb + lane])      + bf2f(qkvl[vb + lane]);
        const float v1 = bf2f(qkvh[vb + 32 + lane]) + bf2f(qkvl[vb + 32 + lane]);
        o0 = fmaf(w[jj], v0, o0);
        o1 = fmaf(w[jj], v1, o1);
    }
    o0 *= inv; o1 *= inv;

    const size_t ob = (size_t)(b*SLEN + i) * DDIM + h*HD;
    __nv_bfloat16 hh, ll;
    split1(o0, hh, ll);
    oh[ob + lane] = hh;  ol[ob + lane] = ll;
    split1(o1, hh, ll);
    oh[ob + 32 + lane] = hh;  ol[ob + 32 + lane] = ll;
}

// ---------------------------------------------------------------------------
// LayerNorm — unchanged.
// ---------------------------------------------------------------------------
__global__ __launch_bounds__(256)
void ln_kernel(const float* __restrict__ a, const float* __restrict__ r,
               const float* __restrict__ g, const float* __restrict__ bt,
               float* __restrict__ out,
               __nv_bfloat16* __restrict__ ohh, __nv_bfloat16* __restrict__ oll)
{
    __shared__ float red[2][8];
    __shared__ float s_mean, s_rstd;
    const int n = blockIdx.x;
    const int tid = threadIdx.x;
    const size_t base = (size_t)n * DDIM + tid * 4;

    float4 va = *(const float4*)(a + base);
    if (r) {
        float4 vr = *(const float4*)(r + base);
        va.x += vr.x; va.y += vr.y; va.z += vr.z; va.w += vr.w;
    }
    float s  = va.x + va.y + va.z + va.w;
    float sq = va.x*va.x + va.y*va.y + va.z*va.z + va.w*va.w;

    #pragma unroll
    for (int off = 16; off; off >>= 1) {
        s  += __shfl_xor_sync(0xffffffffu, s,  off);
        sq += __shfl_xor_sync(0xffffffffu, sq, off);
    }
    const int wid = tid >> 5;
    if ((tid & 31) == 0) { red[0][wid] = s; red[1][wid] = sq; }
    __syncthreads();
    if (tid < 32) {
        float ts  = (tid < 8) ? red[0][tid] : 0.f;
        float tsq = (tid < 8) ? red[1][tid] : 0.f;
        #pragma unroll
        for (int off = 4; off; off >>= 1) {
            ts  += __shfl_xor_sync(0xffffffffu, ts,  off);
            tsq += __shfl_xor_sync(0xffffffffu, tsq, off);
        }
        if (tid == 0) {
            float mean = ts * (1.f / DDIM);
            float var  = tsq * (1.f / DDIM) - mean * mean;
            s_mean = mean;
            s_rstd = rsqrtf(var + EPS);
        }
    }
    __syncthreads();
    const float mean = s_mean, rstd = s_rstd;
    float4 gg = *(const float4*)(g + tid*4);
    float4 bb = *(const float4*)(bt + tid*4);
    float4 o;
    o.x = (va.x - mean) * rstd * gg.x + bb.x;
    o.y = (va.y - mean) * rstd * gg.y + bb.y;
    o.z = (va.z - mean) * rstd * gg.z + bb.z;
    o.w = (va.w - mean) * rstd * gg.w + bb.w;
    *(float4*)(out + base) = o;
    if (ohh) {
        __nv_bfloat16 h0,h1,h2,h3,l0,l1,l2,l3;
        split1(o.x,h0,l0); split1(o.y,h1,l1); split1(o.z,h2,l2); split1(o.w,h3,l3);
        uint2 uh; uh.x = pack2(h0,h1); uh.y = pack2(h2,h3);
        uint2 ul; ul.x = pack2(l0,l1); ul.y = pack2(l2,l3);
        *(uint2*)(ohh + base) = uh;
        *(uint2*)(oll + base) = ul;
    }
}

// ---------------------------------------------------------------------------
// Orchestration
// ---------------------------------------------------------------------------
extern "C" void kernel_launch(void* const* d_in, const int* in_sizes, int n_in,
                              void* d_out, int out_size)
{
    const float* x_in   = (const float*)d_in[0];
    const float* w_in1  = (const float*)d_in[1];
    const float* b_in1  = (const float*)d_in[2];
    const float* w_out1 = (const float*)d_in[3];
    const float* b_out1 = (const float*)d_in[4];
    const float* ln1_g  = (const float*)d_in[5];
    const float* ln1_b  = (const float*)d_in[6];
    const float* w_in2  = (const float*)d_in[7];
    const float* b_in2  = (const float*)d_in[8];
    const float* w_out2 = (const float*)d_in[9];
    const float* b_out2 = (const float*)d_in[10];
    const float* ln2_g  = (const float*)d_in[11];
    const float* ln2_b  = (const float*)d_in[12];
    const float* ffn_w1 = (const float*)d_in[13];
    const float* ffn_b1 = (const float*)d_in[14];
    const float* ffn_w2 = (const float*)d_in[15];
    const float* ffn_b2 = (const float*)d_in[16];
    const float* lnf_g  = (const float*)d_in[17];
    const float* lnf_b  = (const float*)d_in[18];

    float *PROJ, *X, *X2, *ATT;
    __nv_bfloat16 *WH, *WL, *QKVH, *QKVL, *P1H, *P1L, *P2H, *P2L;
    cudaGetSymbolAddress((void**)&PROJ, g_proj);
    cudaGetSymbolAddress((void**)&X,    g_x);
    cudaGetSymbolAddress((void**)&X2,   g_x2);
    cudaGetSymbolAddress((void**)&ATT,  g_att);
    cudaGetSymbolAddress((void**)&WH,   g_wh);
    cudaGetSymbolAddress((void**)&WL,   g_wl);
    cudaGetSymbolAddress((void**)&QKVH, g_qkvh);
    cudaGetSymbolAddress((void**)&QKVL, g_qkvl);
    cudaGetSymbolAddress((void**)&P1H,  g_p1h);
    cudaGetSymbolAddress((void**)&P1L,  g_p1l);
    cudaGetSymbolAddress((void**)&P2H,  g_p2h);
    cudaGetSymbolAddress((void**)&P2L,  g_p2l);

    cudaFuncSetAttribute(attn_tc_kernel,
                         cudaFuncAttributeMaxDynamicSharedMemorySize, ATTN_TC_SMEM);
    cudaFuncSetAttribute(gemm_bf3<0,true,false>,
                         cudaFuncAttributeMaxDynamicSharedMemorySize, GSMEM_BYTES);
    cudaFuncSetAttribute(gemm_bf3<0,false,true>,
                         cudaFuncAttributeMaxDynamicSharedMemorySize, GSMEM_BYTES);
    cudaFuncSetAttribute(gemm_bf3<1,true,false>,
                         cudaFuncAttributeMaxDynamicSharedMemorySize, GSMEM_BYTES);
    cudaFuncSetAttribute(gemm_bf3<2,true,true>,
                         cudaFuncAttributeMaxDynamicSharedMemorySize, GSMEM_BYTES);

    const dim3 blk(256);
    const dim3 gblk(256);
    const dim3 g_qkvp(D3/128,  NTOK/128);    // (24,16)
    const dim3 g_outp(DDIM/128, NTOK/128);   // (8,16)
    const dim3 g_ffn1(MDIM/128, NTOK/128);   // (32,16)
    const dim3 g_attn(BNUM*HNUM, SLEN/64);   // (32,16)
    const int  g_band = (BNUM*HNUM*SLEN*32) / 256;
    const int  g_ln   = NTOK;

    // ---- single merged split launch: all 6 weights + layer-0 input ----
    split_all_kernel<<<SPLIT_TOTAL_BLOCKS, blk>>>(
        w_in1, w_out1, w_in2, w_out2, ffn_w1, ffn_w2, x_in,
        WH, WL, P1H, P1L);

    const float* xcur = x_in;
    for (int l = 0; l < LNUM; l++) {
        const size_t oW3 = (size_t)l * D3 * DDIM;
        const size_t oW1 = (size_t)l * DDIM * DDIM;
        const size_t oWm = (size_t)l * MDIM * DDIM;

        // ---- intra-frame full MHA ----
        gemm_bf3<0,true,false><<<g_qkvp, gblk, GSMEM_BYTES>>>(
            P1H, P1L, WH+W_IN1_OFF+oW3, WL+W_IN1_OFF+oW3,
            b_in1 + (size_t)l*D3, nullptr, nullptr, QKVH, QKVL, NTOK, D3, DDIM);
        attn_tc_kernel<<<g_attn, 128, ATTN_TC_SMEM>>>(QKVH, QKVL, P1H, P1L);
        gemm_bf3<0,false,true><<<g_outp, gblk, GSMEM_BYTES>>>(
            P1H, P1L, WH+W_OUT1_OFF+oW1, WL+W_OUT1_OFF+oW1,
            b_out1 + (size_t)l*DDIM, nullptr, PROJ, nullptr, nullptr, NTOK, DDIM, DDIM);
        ln_kernel<<<g_ln, blk>>>(PROJ, xcur, ln1_g + (size_t)l*DDIM,
                                 ln1_b + (size_t)l*DDIM, X2, P1H, P1L);

        // ---- inter-frame banded MHA ----
        gemm_bf3<0,true,false><<<g_qkvp, gblk, GSMEM_BYTES>>>(
            P1H, P1L, WH+W_IN2_OFF+oW3, WL+W_IN2_OFF+oW3,
            b_in2 + (size_t)l*D3, nullptr, nullptr, QKVH, QKVL, NTOK, D3, DDIM);
        attn_band_kernel<<<g_band, blk>>>(QKVH, QKVL, P1H, P1L);
        gemm_bf3<0,false,true><<<g_outp, gblk, GSMEM_BYTES>>>(
            P1H, P1L, WH+W_OUT2_OFF+oW1, WL+W_OUT2_OFF+oW1,
            b_out2 + (size_t)l*DDIM, nullptr, PROJ, nullptr, nullptr, NTOK, DDIM, DDIM);
        ln_kernel<<<g_ln, blk>>>(PROJ, X2, ln2_g + (size_t)l*DDIM,
                                 ln2_b + (size_t)l*DDIM, ATT, P1H, P1L);

        // ---- FFN ----
        gemm_bf3<1,true,false><<<g_ffn1, gblk, GSMEM_BYTES>>>(
            P1H, P1L, WH+FW1_OFF+oWm, WL+FW1_OFF+oWm,
            ffn_b1 + (size_t)l*MDIM, nullptr, nullptr, P2H, P2L, NTOK, MDIM, DDIM);
        gemm_bf3<2,true,true><<<g_outp, gblk, GSMEM_BYTES>>>(
            P2H, P2L, WH+FW2_OFF+oWm, WL+FW2_OFF+oWm,
            ffn_b2 + (size_t)l*DDIM, ATT, X, P1H, P1L, NTOK, DDIM, MDIM);
        xcur = X;
    }

    ln_kernel<<<g_ln, blk>>>(xcur, nullptr, lnf_g, lnf_b, (float*)d_out,
                             nullptr, nullptr);
}

// round 11
// speedup vs baseline: 1.8347x; 1.0382x over previous
#include <cuda_runtime.h>
#include <cuda_bf16.h>
#include <math.h>
#include <stdint.h>

// ---------------------------------------------------------------------------
// Problem constants
// ---------------------------------------------------------------------------
#define LNUM 4
#define DDIM 1024
#define HNUM 16
#define HD   64
#define MDIM 4096
#define SLEN 1024
#define BNUM 2
#define NTOK (BNUM*SLEN)        // 2048
#define D3   (3*DDIM)           // 3072
#define EPS  1e-5f

// Weight split array layout (element offsets)
#define W_IN1_OFF   0u
#define W_OUT1_OFF  12582912u
#define W_IN2_OFF   16777216u
#define W_OUT2_OFF  29360128u
#define FW1_OFF     33554432u
#define FW2_OFF     50331648u
#define WTOTAL      67108864u

// ---------------------------------------------------------------------------
// Device scratch (no allocations allowed)
// ---------------------------------------------------------------------------
static __device__ float g_proj[NTOK*DDIM];
static __device__ float g_x   [NTOK*DDIM];
static __device__ float g_x2  [NTOK*DDIM];
static __device__ float g_att [NTOK*DDIM];
static __device__ float g_part[4u*NTOK*DDIM];        // split-K partials (32MB)

static __device__ __nv_bfloat16 g_wh[WTOTAL];        // weight hi
static __device__ __nv_bfloat16 g_wl[WTOTAL];        // weight lo
static __device__ __nv_bfloat16 g_qkvh[NTOK*D3];     // qkv hi
static __device__ __nv_bfloat16 g_qkvl[NTOK*D3];     // qkv lo
static __device__ __nv_bfloat16 g_p1h[NTOK*DDIM];
static __device__ __nv_bfloat16 g_p1l[NTOK*DDIM];
static __device__ __nv_bfloat16 g_p2h[NTOK*MDIM];
static __device__ __nv_bfloat16 g_p2l[NTOK*MDIM];

// ---------------------------------------------------------------------------
// Helpers
// ---------------------------------------------------------------------------
__device__ __forceinline__ void cp16(uint32_t d, const void* s) {
    asm volatile("cp.async.cg.shared.global [%0], [%1], 16;\n" :: "r"(d), "l"(s));
}
__device__ __forceinline__ void cp_commit() {
    asm volatile("cp.async.commit_group;\n" ::: "memory");
}
__device__ __forceinline__ void cp_wait1() {
    asm volatile("cp.async.wait_group 1;\n" ::: "memory");
}
__device__ __forceinline__ void cp_wait0() {
    asm volatile("cp.async.wait_group 0;\n" ::: "memory");
}
__device__ __forceinline__ void ldsm4(uint32_t* r, uint32_t a) {
    asm volatile("ldmatrix.sync.aligned.m8n8.x4.shared.b16 {%0,%1,%2,%3}, [%4];"
        : "=r"(r[0]), "=r"(r[1]), "=r"(r[2]), "=r"(r[3]) : "r"(a));
}
__device__ __forceinline__ void ldsm4t(uint32_t* r, uint32_t a) {
    asm volatile("ldmatrix.sync.aligned.m8n8.x4.trans.shared.b16 {%0,%1,%2,%3}, [%4];"
        : "=r"(r[0]), "=r"(r[1]), "=r"(r[2]), "=r"(r[3]) : "r"(a));
}
__device__ __forceinline__ void mma16816(float* c, const uint32_t* a,
                                         uint32_t b0, uint32_t b1) {
    asm volatile(
        "mma.sync.aligned.m16n8k16.row.col.f32.bf16.bf16.f32 "
        "{%0,%1,%2,%3},{%4,%5,%6,%7},{%8,%9},{%0,%1,%2,%3};"
        : "+f"(c[0]), "+f"(c[1]), "+f"(c[2]), "+f"(c[3])
        : "r"(a[0]), "r"(a[1]), "r"(a[2]), "r"(a[3]), "r"(b0), "r"(b1));
}
__device__ __forceinline__ uint32_t pack2(__nv_bfloat16 a, __nv_bfloat16 b) {
    __nv_bfloat162 t = __halves2bfloat162(a, b);
    return *reinterpret_cast<uint32_t*>(&t);
}
__device__ __forceinline__ void split1(float v, __nv_bfloat16& h, __nv_bfloat16& l) {
    h = __float2bfloat16(v);
    l = __float2bfloat16(v - __bfloat162float(h));
}
__device__ __forceinline__ float bf2f(__nv_bfloat16 v) { return __bfloat162float(v); }

// ---------------------------------------------------------------------------
// Merged fp32 -> (hi,lo) bf16 split for all 6 weight tensors + x_in.
// ---------------------------------------------------------------------------
#define SPLIT_TOTAL_BLOCKS 16896

__global__ __launch_bounds__(256)
void split_all_kernel(const float* __restrict__ w_in1, const float* __restrict__ w_out1,
                      const float* __restrict__ w_in2, const float* __restrict__ w_out2,
                      const float* __restrict__ fw1,  const float* __restrict__ fw2,
                      const float* __restrict__ x,
                      __nv_bfloat16* __restrict__ WH, __nv_bfloat16* __restrict__ WL,
                      __nv_bfloat16* __restrict__ P1H, __nv_bfloat16* __restrict__ P1L)
{
    const int bid = blockIdx.x;
    const float* src;
    __nv_bfloat16 *dh, *dl;
    int rb;
    if (bid < 3072)       { src = w_in1;  dh = WH + W_IN1_OFF;  dl = WL + W_IN1_OFF;  rb = bid; }
    else if (bid < 4096)  { src = w_out1; dh = WH + W_OUT1_OFF; dl = WL + W_OUT1_OFF; rb = bid - 3072; }
    else if (bid < 7168)  { src = w_in2;  dh = WH + W_IN2_OFF;  dl = WL + W_IN2_OFF;  rb = bid - 4096; }
    else if (bid < 8192)  { src = w_out2; dh = WH + W_OUT2_OFF; dl = WL + W_OUT2_OFF; rb = bid - 7168; }
    else if (bid < 12288) { src = fw1;    dh = WH + FW1_OFF;    dl = WL + FW1_OFF;    rb = bid - 8192; }
    else if (bid < 16384) { src = fw2;    dh = WH + FW2_OFF;    dl = WL + FW2_OFF;    rb = bid - 12288; }
    else                  { src = x;      dh = P1H;             dl = P1L;             rb = bid - 16384; }

    const size_t base = (size_t)rb * 4096 + threadIdx.x * 4;
    #pragma unroll
    for (int j = 0; j < 4; j++) {
        const size_t i = base + j * 1024;
        float4 v = *(const float4*)(src + i);
        __nv_bfloat16 h0,h1,h2,h3,l0,l1,l2,l3;
        split1(v.x,h0,l0); split1(v.y,h1,l1); split1(v.z,h2,l2); split1(v.w,h3,l3);
        uint2 uh; uh.x = pack2(h0,h1); uh.y = pack2(h2,h3);
        uint2 ul; ul.x = pack2(l0,l1); ul.y = pack2(l2,l3);
        *(uint2*)(dh + i) = uh;
        *(uint2*)(dl + i) = ul;
    }
}

// ---------------------------------------------------------------------------
// bf16x3 tensor-core GEMM: C[M,N] = A[M,K] @ Bw[N,K]^T + bias (+ epilogue)
// CTA tile 128x128x32; 256 threads, 8 warps, warp tile 32x64 (4x2 grid).
// gridDim.z = S (split-K): CTA z accumulates K-range [z*K/S, (z+1)*K/S).
// PARTIAL: write raw fp32 partials to Part + z*M*N (no bias/epilogue).
// Single __syncthreads per mainloop iteration (prefetch after barrier:
// buffer (kt+2)%3 was last read at kt-1, which the top barrier orders).
// 3-stage cp.async pipeline (96KB smem, 2 CTA/SM -> 4 warps/SMSP).
// EPI: 0=bias, 1=bias+GELU, 2=bias+residual.
// ---------------------------------------------------------------------------
#define STAGE_BYTES 32768
#define GSMEM_BYTES (3*STAGE_BYTES)

template<int EPI, bool OSPLIT, bool OF32, bool PARTIAL>
__global__ __launch_bounds__(256, 2)
void gemm_bf3(const __nv_bfloat16* __restrict__ Ah, const __nv_bfloat16* __restrict__ Al,
              const __nv_bfloat16* __restrict__ Bh, const __nv_bfloat16* __restrict__ Bl,
              const float* __restrict__ bias, const float* __restrict__ Res,
              float* __restrict__ C, __nv_bfloat16* __restrict__ Chi,
              __nv_bfloat16* __restrict__ Clo, float* __restrict__ Part,
              int M, int N, int K)
{
    extern __shared__ __nv_bfloat16 smbuf[];
    const uint32_t smem_u32 = (uint32_t)__cvta_generic_to_shared(smbuf);

    const int tid = threadIdx.x;
    const int m0 = blockIdx.y * 128;
    const int n0 = blockIdx.x * 128;
    const int z  = blockIdx.z;
    const int Ksub = K / gridDim.z;

    // ---- global->smem loader: warps 0-3 load A(h,l), warps 4-7 load B(h,l) ----
    const int lrow = tid & 127;
    const bool isB = tid >= 128;
    const size_t kofs = (size_t)z * Ksub;
    const __nv_bfloat16* pH = (isB ? Bh + (size_t)(n0 + lrow) * K
                                   : Ah + (size_t)(m0 + lrow) * K) + kofs;
    const __nv_bfloat16* pL = (isB ? Bl + (size_t)(n0 + lrow) * K
                                   : Al + (size_t)(m0 + lrow) * K) + kofs;
    const uint32_t regH = isB ? 16384u : 0u;
    const uint32_t rowb = (uint32_t)lrow * 16;

    auto load_stage = [&](int kt, int s) {
        const uint32_t sb = smem_u32 + (uint32_t)s * STAGE_BYTES + regH;
        const size_t gk = (size_t)kt * 32;
        #pragma unroll
        for (int ko = 0; ko < 4; ko++) {
            const uint32_t o = (uint32_t)ko * 2048 + rowb;
            cp16(sb + o,        pH + gk + ko*8);
            cp16(sb + 8192 + o, pL + gk + ko*8);
        }
        cp_commit();
    };

    // ---- warp/frag mapping: 8 warps, 4 (m) x 2 (n), warp tile 32x64 ----
    const int wid  = tid >> 5;
    const int lane = tid & 31;
    const int wm = (wid >> 1) * 32;       // 0,32,64,96
    const int wn = (wid & 1) * 64;        // 0,64
    const int a_row = lane & 15;
    const int a_ko  = lane >> 4;
    const int b_row = (lane & 7) + ((lane & 16) >> 1);
    const int b_ko  = (lane >> 3) & 1;

    const uint32_t aoff = (uint32_t)((a_ko*1024 + (wm + a_row)*8) * 2);
    const uint32_t boff = (uint32_t)(16384 + (b_ko*1024 + (wn + b_row)*8) * 2);

    float acc[2][8][4];
    #pragma unroll
    for (int i = 0; i < 2; i++)
        #pragma unroll
        for (int j = 0; j < 8; j++)
            #pragma unroll
            for (int e = 0; e < 4; e++) acc[i][j][e] = 0.f;

    const int T = Ksub >> 5;

    load_stage(0, 0);
    if (T > 1) load_stage(1, 1);

    for (int kt = 0; kt < T; kt++) {
        if (kt + 1 < T) cp_wait1(); else cp_wait0();
        __syncthreads();
        if (kt + 2 < T) load_stage(kt + 2, (kt + 2) % 3);

        const uint32_t sb = smem_u32 + (uint32_t)(kt % 3) * STAGE_BYTES;
        #pragma unroll
        for (int ko0 = 0; ko0 < 4; ko0 += 2) {
            uint32_t a_h[2][4], a_l[2][4];
            #pragma unroll
            for (int mf = 0; mf < 2; mf++) {
                const uint32_t ad = sb + aoff + (uint32_t)ko0*2048 + (uint32_t)mf*256;
                ldsm4(a_h[mf], ad);
                ldsm4(a_l[mf], ad + 8192);
            }
            #pragma unroll
            for (int nf2 = 0; nf2 < 4; nf2++) {
                uint32_t b_h[4], b_l[4];
                const uint32_t bd = sb + boff + (uint32_t)ko0*2048 + (uint32_t)nf2*256;
                ldsm4(b_h, bd);
                ldsm4(b_l, bd + 8192);
                #pragma unroll
                for (int mf = 0; mf < 2; mf++) {
                    const int nf = nf2 * 2;
                    mma16816(acc[mf][nf],   a_h[mf], b_h[0], b_h[1]);
                    mma16816(acc[mf][nf],   a_h[mf], b_l[0], b_l[1]);
                    mma16816(acc[mf][nf],   a_l[mf], b_h[0], b_h[1]);
                    mma16816(acc[mf][nf+1], a_h[mf], b_h[2], b_h[3]);
                    mma16816(acc[mf][nf+1], a_h[mf], b_l[2], b_l[3]);
                    mma16816(acc[mf][nf+1], a_l[mf], b_h[2], b_h[3]);
                }
            }
        }
    }

    // ---- epilogue ----
    const int er = lane >> 2;
    const int ec = (lane & 3) * 2;
    if (PARTIAL) {
        float* dst = Part + (size_t)z * M * N;
        #pragma unroll
        for (int mf = 0; mf < 2; mf++)
            #pragma unroll
            for (int nf = 0; nf < 8; nf++) {
                const int m = m0 + wm + mf*16 + er;
                const int n = n0 + wn + nf*8 + ec;
                #pragma unroll
                for (int half = 0; half < 2; half++) {
                    const int mm = m + half*8;
                    *(float2*)(dst + (size_t)mm * N + n) =
                        make_float2(acc[mf][nf][half*2+0], acc[mf][nf][half*2+1]);
                }
            }
        return;
    }

    #pragma unroll
    for (int mf = 0; mf < 2; mf++) {
        #pragma unroll
        for (int nf = 0; nf < 8; nf++) {
            const int m = m0 + wm + mf*16 + er;
            const int n = n0 + wn + nf*8 + ec;
            const float2 bv = *(const float2*)(bias + n);
            #pragma unroll
            for (int half = 0; half < 2; half++) {
                const int mm = m + half*8;
                float t0 = acc[mf][nf][half*2+0] + bv.x;
                float t1 = acc[mf][nf][half*2+1] + bv.y;
                if (EPI == 1) {
                    t0 = 0.5f * t0 * (1.f + erff(t0 * 0.70710678118654752f));
                    t1 = 0.5f * t1 * (1.f + erff(t1 * 0.70710678118654752f));
                }
                if (EPI == 2) {
                    const float2 rv = *(const float2*)(Res + (size_t)mm * N + n);
                    t0 += rv.x; t1 += rv.y;
                }
                if (OF32) {
                    *(float2*)(C + (size_t)mm * N + n) = make_float2(t0, t1);
                }
                if (OSPLIT) {
                    __nv_bfloat16 h0,h1,l0,l1;
                    split1(t0,h0,l0); split1(t1,h1,l1);
                    *(uint32_t*)(Chi + (size_t)mm * N + n) = pack2(h0,h1);
                    *(uint32_t*)(Clo + (size_t)mm * N + n) = pack2(l0,l1);
                }
            }
        }
    }
}

// ---------------------------------------------------------------------------
// Split-K reduce + epilogue. N fixed at DDIM. Each thread: 4 contiguous cols.
// ---------------------------------------------------------------------------
template<int EPI, bool OSPLIT, bool OF32, int S>
__global__ __launch_bounds__(256)
void epi_reduce(const float* __restrict__ Part, const float* __restrict__ bias,
                const float* __restrict__ Res, float* __restrict__ C,
                __nv_bfloat16* __restrict__ Chi, __nv_bfloat16* __restrict__ Clo)
{
    const size_t i = (size_t)blockIdx.x * 1024 + threadIdx.x * 4;
    const int n = (int)(i & (DDIM - 1));
    float4 t = *(const float4*)(Part + i);
    #pragma unroll
    for (int s = 1; s < S; s++) {
        const float4 p = *(const float4*)(Part + (size_t)s * (NTOK*DDIM) + i);
        t.x += p.x; t.y += p.y; t.z += p.z; t.w += p.w;
    }
    const float4 bv = *(const float4*)(bias + n);
    t.x += bv.x; t.y += bv.y; t.z += bv.z; t.w += bv.w;
    if (EPI == 1) {
        t.x = 0.5f * t.x * (1.f + erff(t.x * 0.70710678118654752f));
        t.y = 0.5f * t.y * (1.f + erff(t.y * 0.70710678118654752f));
        t.z = 0.5f * t.z * (1.f + erff(t.z * 0.70710678118654752f));
        t.w = 0.5f * t.w * (1.f + erff(t.w * 0.70710678118654752f));
    }
    if (EPI == 2) {
        const float4 rv = *(const float4*)(Res + i);
        t.x += rv.x; t.y += rv.y; t.z += rv.z; t.w += rv.w;
    }
    if (OF32) *(float4*)(C + i) = t;
    if (OSPLIT) {
        __nv_bfloat16 h0,h1,h2,h3,l0,l1,l2,l3;
        split1(t.x,h0,l0); split1(t.y,h1,l1); split1(t.z,h2,l2); split1(t.w,h3,l3);
        uint2 uh; uh.x = pack2(h0,h1); uh.y = pack2(h2,h3);
        uint2 ul; ul.x = pack2(l0,l1); ul.y = pack2(l2,l3);
        *(uint2*)(Chi + i) = uh;
        *(uint2*)(Clo + i) = ul;
    }
}

// ---------------------------------------------------------------------------
// Tensor-core full attention (bf16x3 flash) — unchanged (known good).
// ---------------------------------------------------------------------------
#define ATTN_TC_SMEM 65536

__global__ __launch_bounds__(128, 3)
void attn_tc_kernel(const __nv_bfloat16* __restrict__ qkvh,
                    const __nv_bfloat16* __restrict__ qkvl,
                    __nv_bfloat16* __restrict__ oh,
                    __nv_bfloat16* __restrict__ ol)
{
    extern __shared__ char smc[];
    const uint32_t sb = (uint32_t)__cvta_generic_to_shared(smc);

    const int bh = blockIdx.x;
    const int b  = bh >> 4;
    const int h  = bh & 15;
    const int qt = blockIdx.y;
    const int tid  = threadIdx.x;
    const int wid  = tid >> 5;
    const int lane = tid & 31;

    const int r    = tid >> 1;
    const int koh  = (tid & 1) * 4;

    {
        const size_t qrow = (size_t)(b*SLEN + qt*64 + r) * D3 + h*HD;
        #pragma unroll
        for (int it = 0; it < 4; it++) {
            const int ko = koh + it;
            const uint32_t dst = sb + (uint32_t)(((ko*64 + r)*8) * 2);
            cp16(dst,        qkvh + qrow + ko*8);
            cp16(dst + 8192, qkvl + qrow + ko*8);
        }
        cp_commit();
    }

    const int a_row = lane & 15;
    const int a_ko  = lane >> 4;
    const int b_row = (lane & 7) + ((lane & 16) >> 1);
    const int b_ko  = (lane >> 3) & 1;
    const int v_key = lane & 15;
    const int v_ko  = lane >> 4;

    uint32_t qa_h[4][4], qa_l[4][4];

    cp_wait0();
    __syncthreads();
    #pragma unroll
    for (int ks = 0; ks < 4; ks++) {
        const uint32_t ad = sb +
            (uint32_t)((((ks*2 + a_ko)*64 + wid*16 + a_row)*8) * 2);
        ldsm4(qa_h[ks], ad);
        ldsm4(qa_l[ks], ad + 8192);
    }
    __syncthreads();

    auto load_kv = [&](int kt, int s) {
        const uint32_t stg = sb + (uint32_t)s * 32768;
        const size_t krow = (size_t)(b*SLEN + kt*64 + r) * D3 + DDIM + h*HD;
        const size_t vrow = krow + DDIM;
        #pragma unroll
        for (int it = 0; it < 4; it++) {
            const int ko = koh + it;
            const uint32_t off = (uint32_t)(((ko*64 + r)*8) * 2);
            cp16(stg + off,          qkvh + krow + ko*8);
            cp16(stg + 8192  + off,  qkvl + krow + ko*8);
            cp16(stg + 16384 + off,  qkvh + vrow + ko*8);
            cp16(stg + 24576 + off,  qkvl + vrow + ko*8);
        }
    };

    load_kv(0, 0);
    cp_commit();

    float m0 = -1e30f, m1 = -1e30f, l0 = 0.f, l1 = 0.f;
    float oacc[8][4];
    #pragma unroll
    for (int nf = 0; nf < 8; nf++)
        #pragma unroll
        for (int e = 0; e < 4; e++) oacc[nf][e] = 0.f;

    for (int kt = 0; kt < 16; kt++) {
        const int s = kt & 1;
        if (kt + 1 < 16) {
            load_kv(kt + 1, s ^ 1);
            cp_commit();
            cp_wait1();
        } else {
            cp_wait0();
        }
        __syncthreads();

        const uint32_t stg = sb + (uint32_t)s * 32768;

        float sc[8][4];
        #pragma unroll
        for (int nf = 0; nf < 8; nf++)
            #pragma unroll
            for (int e = 0; e < 4; e++) sc[nf][e] = 0.f;

        #pragma unroll
        for (int ks = 0; ks < 4; ks++) {
            #pragma unroll
            for (int np = 0; np < 4; np++) {
                uint32_t kb[4], kl[4];
                const uint32_t kd = stg +
                    (uint32_t)((((ks*2 + b_ko)*64 + np*16 + b_row)*8) * 2);
                ldsm4(kb, kd);
                ldsm4(kl, kd + 8192);
                mma16816(sc[2*np],   qa_h[ks], kb[0], kb[1]);
                mma16816(sc[2*np],   qa_h[ks], kl[0], kl[1]);
                mma16816(sc[2*np],   qa_l[ks], kb[0], kb[1]);
                mma16816(sc[2*np+1], qa_h[ks], kb[2], kb[3]);
                mma16816(sc[2*np+1], qa_h[ks], kl[2], kl[3]);
                mma16816(sc[2*np+1], qa_l[ks], kb[2], kb[3]);
            }
        }

        #pragma unroll
        for (int nf = 0; nf < 8; nf++)
            #pragma unroll
            for (int e = 0; e < 4; e++) sc[nf][e] *= 0.125f;

        float mx0 = m0, mx1 = m1;
        #pragma unroll
        for (int nf = 0; nf < 8; nf++) {
            mx0 = fmaxf(mx0, fmaxf(sc[nf][0], sc[nf][1]));
            mx1 = fmaxf(mx1, fmaxf(sc[nf][2], sc[nf][3]));
        }
        mx0 = fmaxf(mx0, __shfl_xor_sync(0xffffffffu, mx0, 1));
        mx0 = fmaxf(mx0, __shfl_xor_sync(0xffffffffu, mx0, 2));
        mx1 = fmaxf(mx1, __shfl_xor_sync(0xffffffffu, mx1, 1));
        mx1 = fmaxf(mx1, __shfl_xor_sync(0xffffffffu, mx1, 2));

        const float al0 = __expf(m0 - mx0);
        const float al1 = __expf(m1 - mx1);
        m0 = mx0; m1 = mx1;

        float s0 = 0.f, s1 = 0.f;
        uint32_t pah[4][4], pal[4][4];
        #pragma unroll
        for (int nf = 0; nf < 8; nf++) {
            const float p0 = __expf(sc[nf][0] - m0);
            const float p1 = __expf(sc[nf][1] - m0);
            const float p2 = __expf(sc[nf][2] - m1);
            const float p3 = __expf(sc[nf][3] - m1);
            s0 += p0 + p1;
            s1 += p2 + p3;
            __nv_bfloat16 h0,h1,h2,h3,lo0,lo1,lo2,lo3;
            split1(p0,h0,lo0); split1(p1,h1,lo1);
            split1(p2,h2,lo2); split1(p3,h3,lo3);
            const int ks = nf >> 1;
            const int hv = (nf & 1) * 2;
            pah[ks][hv+0] = pack2(h0, h1);
            pah[ks][hv+1] = pack2(h2, h3);
            pal[ks][hv+0] = pack2(lo0, lo1);
            pal[ks][hv+1] = pack2(lo2, lo3);
        }
        s0 += __shfl_xor_sync(0xffffffffu, s0, 1);
        s0 += __shfl_xor_sync(0xffffffffu, s0, 2);
        s1 += __shfl_xor_sync(0xffffffffu, s1, 1);
        s1 += __shfl_xor_sync(0xffffffffu, s1, 2);
        l0 = l0 * al0 + s0;
        l1 = l1 * al1 + s1;

        #pragma unroll
        for (int nf = 0; nf < 8; nf++) {
            oacc[nf][0] *= al0; oacc[nf][1] *= al0;
            oacc[nf][2] *= al1; oacc[nf][3] *= al1;
        }

        #pragma unroll
        for (int ks = 0; ks < 4; ks++) {
            #pragma unroll
            for (int np = 0; np < 4; np++) {
                uint32_t vb[4], vl[4];
                const uint32_t vd = stg + 16384 +
                    (uint32_t)((((np*2 + v_ko)*64 + ks*16 + v_key)*8) * 2);
                ldsm4t(vb, vd);
                ldsm4t(vl, vd + 8192);
                mma16816(oacc[2*np],   pah[ks], vb[0], vb[1]);
                mma16816(oacc[2*np],   pah[ks], vl[0], vl[1]);
                mma16816(oacc[2*np],   pal[ks], vb[0], vb[1]);
                mma16816(oacc[2*np+1], pah[ks], vb[2], vb[3]);
                mma16816(oacc[2*np+1], pah[ks], vl[2], vl[3]);
                mma16816(oacc[2*np+1], pal[ks], vb[2], vb[3]);
            }
        }
        __syncthreads();
    }

    const float inv0 = 1.f / l0;
    const float inv1 = 1.f / l1;
    const int er  = lane >> 2;
    const int ec  = (lane & 3) * 2;
    const int tok0 = b*SLEN + qt*64 + wid*16 + er;
    const int tok1 = tok0 + 8;
    #pragma unroll
    for (int nf = 0; nf < 8; nf++) {
        const int col = h*HD + nf*8 + ec;
        const float o0 = oacc[nf][0] * inv0;
        const float o1 = oacc[nf][1] * inv0;
        const float o2 = oacc[nf][2] * inv1;
        const float o3 = oacc[nf][3] * inv1;
        __nv_bfloat16 h0,h1,h2,h3,lo0,lo1,lo2,lo3;
        split1(o0,h0,lo0); split1(o1,h1,lo1);
        split1(o2,h2,lo2); split1(o3,h3,lo3);
        *(uint32_t*)(oh + (size_t)tok0 * DDIM + col) = pack2(h0, h1);
        *(uint32_t*)(ol + (size_t)tok0 * DDIM + col) = pack2(lo0, lo1);
        *(uint32_t*)(oh + (size_t)tok1 * DDIM + col) = pack2(h2, h3);
        *(uint32_t*)(ol + (size_t)tok1 * DDIM + col) = pack2(lo2, lo3);
    }
}

// ---------------------------------------------------------------------------
// Banded attention — unchanged.
// ---------------------------------------------------------------------------
__global__ __launch_bounds__(256)
void attn_band_kernel(const __nv_bfloat16* __restrict__ qkvh,
                      const __nv_bfloat16* __restrict__ qkvl,
                      __nv_bfloat16* __restrict__ oh,
                      __nv_bfloat16* __restrict__ ol)
{
    const int gw   = (blockIdx.x * blockDim.x + threadIdx.x) >> 5;
    const int lane = threadIdx.x & 31;
    const int i = gw & (SLEN-1);
    const int h = (gw >> 10) & (HNUM-1);
    const int b = gw >> 14;

    const size_t qbase = (size_t)(b*SLEN + i) * D3 + h*HD;
    const float q0 = bf2f(qkvh[qbase + lane])      + bf2f(qkvl[qbase + lane]);
    const float q1 = bf2f(qkvh[qbase + 32 + lane]) + bf2f(qkvl[qbase + 32 + lane]);

    float sc[5];
    int   jc[5];
    #pragma unroll
    for (int jj = 0; jj < 5; jj++) {
        int j = i - 2 + jj;
        bool valid = (j >= 0) && (j < SLEN);
        jc[jj] = valid ? j : i;
        const size_t kb = (size_t)(b*SLEN + jc[jj]) * D3 + DDIM + h*HD;
        const float k0 = bf2f(qkvh[kb + lane])      + bf2f(qkvl[kb + lane]);
        const float k1 = bf2f(qkvh[kb + 32 + lane]) + bf2f(qkvl[kb + 32 + lane]);
        float p = q0 * k0 + q1 * k1;
        #pragma unroll
        for (int off = 16; off; off >>= 1) p += __shfl_xor_sync(0xffffffffu, p, off);
        sc[jj] = valid ? p * 0.125f : -1e30f;
    }
    float mx = sc[0];
    #pragma unroll
    for (int jj = 1; jj < 5; jj++) mx = fmaxf(mx, sc[jj]);
    float w[5], sum = 0.f;
    #pragma unroll
    for (int jj = 0; jj < 5; jj++) { w[jj] = __expf(sc[jj] - mx); sum += w[jj]; }
    const float inv = 1.f / sum;

    float o0 = 0.f, o1 = 0.f;
    #pragma unroll
    for (int jj = 0; jj < 5; jj++) {
        const size_t vb = (size_t)(b*SLEN + jc[jj]) * D3 + 2*DDIM + h*HD;
        const float v0 = bf2f(qkvh[vb + lane])      + bf2f(qkvl[vb + lane]);
        const float v1 = bf2f(qkvh[vb + 32 + lane]) + bf2f(qkvl[vb + 32 + lane]);
        o0 = fmaf(w[jj], v0, o0);
        o1 = fmaf(w[jj], v1, o1);
    }
    o0 *= inv; o1 *= inv;

    const size_t ob = (size_t)(b*SLEN + i) * DDIM + h*HD;
    __nv_bfloat16 hh, ll;
    split1(o0, hh, ll);
    oh[ob + lane] = hh;  ol[ob + lane] = ll;
    split1(o1, hh, ll);
    oh[ob + 32 + lane] = hh;  ol[ob + 32 + lane] = ll;
}

// ---------------------------------------------------------------------------
// LayerNorm — unchanged.
// ---------------------------------------------------------------------------
__global__ __launch_bounds__(256)
void ln_kernel(const float* __restrict__ a, const float* __restrict__ r,
               const float* __restrict__ g, const float* __restrict__ bt,
               float* __restrict__ out,
               __nv_bfloat16* __restrict__ ohh, __nv_bfloat16* __restrict__ oll)
{
    __shared__ float red[2][8];
    __shared__ float s_mean, s_rstd;
    const int n = blockIdx.x;
    const int tid = threadIdx.x;
    const size_t base = (size_t)n * DDIM + tid * 4;

    float4 va = *(const float4*)(a + base);
    if (r) {
        float4 vr = *(const float4*)(r + base);
        va.x += vr.x; va.y += vr.y; va.z += vr.z; va.w += vr.w;
    }
    float s  = va.x + va.y + va.z + va.w;
    float sq = va.x*va.x + va.y*va.y + va.z*va.z + va.w*va.w;

    #pragma unroll
    for (int off = 16; off; off >>= 1) {
        s  += __shfl_xor_sync(0xffffffffu, s,  off);
        sq += __shfl_xor_sync(0xffffffffu, sq, off);
    }
    const int wid = tid >> 5;
    if ((tid & 31) == 0) { red[0][wid] = s; red[1][wid] = sq; }
    __syncthreads();
    if (tid < 32) {
        float ts  = (tid < 8) ? red[0][tid] : 0.f;
        float tsq = (tid < 8) ? red[1][tid] : 0.f;
        #pragma unroll
        for (int off = 4; off; off >>= 1) {
            ts  += __shfl_xor_sync(0xffffffffu, ts,  off);
            tsq += __shfl_xor_sync(0xffffffffu, tsq, off);
        }
        if (tid == 0) {
            float mean = ts * (1.f / DDIM);
            float var  = tsq * (1.f / DDIM) - mean * mean;
            s_mean = mean;
            s_rstd = rsqrtf(var + EPS);
        }
    }
    __syncthreads();
    const float mean = s_mean, rstd = s_rstd;
    float4 gg = *(const float4*)(g + tid*4);
    float4 bb = *(const float4*)(bt + tid*4);
    float4 o;
    o.x = (va.x - mean) * rstd * gg.x + bb.x;
    o.y = (va.y - mean) * rstd * gg.y + bb.y;
    o.z = (va.z - mean) * rstd * gg.z + bb.z;
    o.w = (va.w - mean) * rstd * gg.w + bb.w;
    *(float4*)(out + base) = o;
    if (ohh) {
        __nv_bfloat16 h0,h1,h2,h3,l0,l1,l2,l3;
        split1(o.x,h0,l0); split1(o.y,h1,l1); split1(o.z,h2,l2); split1(o.w,h3,l3);
        uint2 uh; uh.x = pack2(h0,h1); uh.y = pack2(h2,h3);
        uint2 ul; ul.x = pack2(l0,l1); ul.y = pack2(l2,l3);
        *(uint2*)(ohh + base) = uh;
        *(uint2*)(oll + base) = ul;
    }
}

// ---------------------------------------------------------------------------
// Orchestration
// ---------------------------------------------------------------------------
extern "C" void kernel_launch(void* const* d_in, const int* in_sizes, int n_in,
                              void* d_out, int out_size)
{
    const float* x_in   = (const float*)d_in[0];
    const float* w_in1  = (const float*)d_in[1];
    const float* b_in1  = (const float*)d_in[2];
    const float* w_out1 = (const float*)d_in[3];
    const float* b_out1 = (const float*)d_in[4];
    const float* ln1_g  = (const float*)d_in[5];
    const float* ln1_b  = (const float*)d_in[6];
    const float* w_in2  = (const float*)d_in[7];
    const float* b_in2  = (const float*)d_in[8];
    const float* w_out2 = (const float*)d_in[9];
    const float* b_out2 = (const float*)d_in[10];
    const float* ln2_g  = (const float*)d_in[11];
    const float* ln2_b  = (const float*)d_in[12];
    const float* ffn_w1 = (const float*)d_in[13];
    const float* ffn_b1 = (const float*)d_in[14];
    const float* ffn_w2 = (const float*)d_in[15];
    const float* ffn_b2 = (const float*)d_in[16];
    const float* lnf_g  = (const float*)d_in[17];
    const float* lnf_b  = (const float*)d_in[18];

    float *PROJ, *X, *X2, *ATT, *PART;
    __nv_bfloat16 *WH, *WL, *QKVH, *QKVL, *P1H, *P1L, *P2H, *P2L;
    cudaGetSymbolAddress((void**)&PROJ, g_proj);
    cudaGetSymbolAddress((void**)&X,    g_x);
    cudaGetSymbolAddress((void**)&X2,   g_x2);
    cudaGetSymbolAddress((void**)&ATT,  g_att);
    cudaGetSymbolAddress((void**)&PART, g_part);
    cudaGetSymbolAddress((void**)&WH,   g_wh);
    cudaGetSymbolAddress((void**)&WL,   g_wl);
    cudaGetSymbolAddress((void**)&QKVH, g_qkvh);
    cudaGetSymbolAddress((void**)&QKVL, g_qkvl);
    cudaGetSymbolAddress((void**)&P1H,  g_p1h);
    cudaGetSymbolAddress((void**)&P1L,  g_p1l);
    cudaGetSymbolAddress((void**)&P2H,  g_p2h);
    cudaGetSymbolAddress((void**)&P2L,  g_p2l);

    cudaFuncSetAttribute(attn_tc_kernel,
                         cudaFuncAttributeMaxDynamicSharedMemorySize, ATTN_TC_SMEM);
    cudaFuncSetAttribute(gemm_bf3<0,true,false,false>,
                         cudaFuncAttributeMaxDynamicSharedMemorySize, GSMEM_BYTES);
    cudaFuncSetAttribute(gemm_bf3<1,true,false,false>,
                         cudaFuncAttributeMaxDynamicSharedMemorySize, GSMEM_BYTES);
    cudaFuncSetAttribute(gemm_bf3<0,false,false,true>,
                         cudaFuncAttributeMaxDynamicSharedMemorySize, GSMEM_BYTES);

    const dim3 blk(256);
    const dim3 gblk(256);
    const dim3 g_qkvp(D3/128,  NTOK/128);        // (24,16)
    const dim3 g_outp(DDIM/128, NTOK/128, 2);    // (8,16,2)  split-K 2
    const dim3 g_ffn1(MDIM/128, NTOK/128);       // (32,16)
    const dim3 g_ffn2(DDIM/128, NTOK/128, 4);    // (8,16,4)  split-K 4
    const dim3 g_attn(BNUM*HNUM, SLEN/64);       // (32,16)
    const int  g_band = (BNUM*HNUM*SLEN*32) / 256;
    const int  g_ln   = NTOK;
    const int  g_red  = (NTOK*DDIM) / 1024;      // 2048

    // ---- single merged split launch: all 6 weights + layer-0 input ----
    split_all_kernel<<<SPLIT_TOTAL_BLOCKS, blk>>>(
        w_in1, w_out1, w_in2, w_out2, ffn_w1, ffn_w2, x_in,
        WH, WL, P1H, P1L);

    const float* xcur = x_in;
    for (int l = 0; l < LNUM; l++) {
        const size_t oW3 = (size_t)l * D3 * DDIM;
        const size_t oW1 = (size_t)l * DDIM * DDIM;
        const size_t oWm = (size_t)l * MDIM * DDIM;

        // ---- intra-frame full MHA ----
        gemm_bf3<0,true,false,false><<<g_qkvp, gblk, GSMEM_BYTES>>>(
            P1H, P1L, WH+W_IN1_OFF+oW3, WL+W_IN1_OFF+oW3,
            b_in1 + (size_t)l*D3, nullptr, nullptr, QKVH, QKVL, nullptr,
            NTOK, D3, DDIM);
        attn_tc_kernel<<<g_attn, 128, ATTN_TC_SMEM>>>(QKVH, QKVL, P1H, P1L);
        gemm_bf3<0,false,false,true><<<g_outp, gblk, GSMEM_BYTES>>>(
            P1H, P1L, WH+W_OUT1_OFF+oW1, WL+W_OUT1_OFF+oW1,
            nullptr, nullptr, nullptr, nullptr, nullptr, PART,
            NTOK, DDIM, DDIM);
        epi_reduce<0,false,true,2><<<g_red, blk>>>(
            PART, b_out1 + (size_t)l*DDIM, nullptr, PROJ, nullptr, nullptr);
        ln_kernel<<<g_ln, blk>>>(PROJ, xcur, ln1_g + (size_t)l*DDIM,
                                 ln1_b + (size_t)l*DDIM, X2, P1H, P1L);

        // ---- inter-frame banded MHA ----
        gemm_bf3<0,true,false,false><<<g_qkvp, gblk, GSMEM_BYTES>>>(
            P1H, P1L, WH+W_IN2_OFF+oW3, WL+W_IN2_OFF+oW3,
            b_in2 + (size_t)l*D3, nullptr, nullptr, QKVH, QKVL, nullptr,
            NTOK, D3, DDIM);
        attn_band_kernel<<<g_band, blk>>>(QKVH, QKVL, P1H, P1L);
        gemm_bf3<0,false,false,true><<<g_outp, gblk, GSMEM_BYTES>>>(
            P1H, P1L, WH+W_OUT2_OFF+oW1, WL+W_OUT2_OFF+oW1,
            nullptr, nullptr, nullptr, nullptr, nullptr, PART,
            NTOK, DDIM, DDIM);
        epi_reduce<0,false,true,2><<<g_red, blk>>>(
            PART, b_out2 + (size_t)l*DDIM, nullptr, PROJ, nullptr, nullptr);
        ln_kernel<<<g_ln, blk>>>(PROJ, X2, ln2_g + (size_t)l*DDIM,
                                 ln2_b + (size_t)l*DDIM, ATT, P1H, P1L);

        // ---- FFN ----
        gemm_bf3<1,true,false,false><<<g_ffn1, gblk, GSMEM_BYTES>>>(
            P1H, P1L, WH+FW1_OFF+oWm, WL+FW1_OFF+oWm,
            ffn_b1 + (size_t)l*MDIM, nullptr, nullptr, P2H, P2L, nullptr,
            NTOK, MDIM, DDIM);
        gemm_bf3<0,false,false,true><<<g_ffn2, gblk, GSMEM_BYTES>>>(
            P2H, P2L, WH+FW2_OFF+oWm, WL+FW2_OFF+oWm,
            nullptr, nullptr, nullptr, nullptr, nullptr, PART,
            NTOK, DDIM, MDIM);
        epi_reduce<2,true,true,4><<<g_red, blk>>>(
            PART, ffn_b2 + (size_t)l*DDIM, ATT, X, P1H, P1L);
        xcur = X;
    }

    ln_kernel<<<g_ln, blk>>>(xcur, nullptr, lnf_g, lnf_b, (float*)d_out,
                             nullptr, nullptr);
}

// round 12
// speedup vs baseline: 1.8377x; 1.0017x over previous
#include <cuda_runtime.h>
#include <cuda_bf16.h>
#include <math.h>
#include <stdint.h>

// ---------------------------------------------------------------------------
// Problem constants
// ---------------------------------------------------------------------------
#define LNUM 4
#define DDIM 1024
#define HNUM 16
#define HD   64
#define MDIM 4096
#define SLEN 1024
#define BNUM 2
#define NTOK (BNUM*SLEN)        // 2048
#define D3   (3*DDIM)           // 3072
#define EPS  1e-5f

// Weight split array layout (element offsets)
#define W_IN1_OFF   0u
#define W_OUT1_OFF  12582912u
#define W_IN2_OFF   16777216u
#define W_OUT2_OFF  29360128u
#define FW1_OFF     33554432u
#define FW2_OFF     50331648u
#define WTOTAL      67108864u

// ---------------------------------------------------------------------------
// Device scratch (no allocations allowed)
// ---------------------------------------------------------------------------
static __device__ float g_proj[NTOK*DDIM];
static __device__ float g_x   [NTOK*DDIM];
static __device__ float g_x2  [NTOK*DDIM];
static __device__ float g_att [NTOK*DDIM];
static __device__ float g_part[4u*NTOK*DDIM];        // split-K partials (32MB)

static __device__ __nv_bfloat16 g_wh[WTOTAL];        // weight hi
static __device__ __nv_bfloat16 g_wl[WTOTAL];        // weight lo
static __device__ __nv_bfloat16 g_qkvh[NTOK*D3];     // qkv hi
static __device__ __nv_bfloat16 g_qkvl[NTOK*D3];     // qkv lo
static __device__ __nv_bfloat16 g_p1h[NTOK*DDIM];
static __device__ __nv_bfloat16 g_p1l[NTOK*DDIM];
static __device__ __nv_bfloat16 g_p2h[NTOK*MDIM];
static __device__ __nv_bfloat16 g_p2l[NTOK*MDIM];

// ---------------------------------------------------------------------------
// Helpers
// ---------------------------------------------------------------------------
__device__ __forceinline__ void cp16(uint32_t d, const void* s) {
    asm volatile("cp.async.cg.shared.global [%0], [%1], 16;\n" :: "r"(d), "l"(s));
}
__device__ __forceinline__ void cp_commit() {
    asm volatile("cp.async.commit_group;\n" ::: "memory");
}
__device__ __forceinline__ void cp_wait1() {
    asm volatile("cp.async.wait_group 1;\n" ::: "memory");
}
__device__ __forceinline__ void cp_wait0() {
    asm volatile("cp.async.wait_group 0;\n" ::: "memory");
}
__device__ __forceinline__ void ldsm4(uint32_t* r, uint32_t a) {
    asm volatile("ldmatrix.sync.aligned.m8n8.x4.shared.b16 {%0,%1,%2,%3}, [%4];"
        : "=r"(r[0]), "=r"(r[1]), "=r"(r[2]), "=r"(r[3]) : "r"(a));
}
__device__ __forceinline__ void ldsm4t(uint32_t* r, uint32_t a) {
    asm volatile("ldmatrix.sync.aligned.m8n8.x4.trans.shared.b16 {%0,%1,%2,%3}, [%4];"
        : "=r"(r[0]), "=r"(r[1]), "=r"(r[2]), "=r"(r[3]) : "r"(a));
}
// NOTE: non-volatile — pure register computation; dependencies are carried by
// the register constraints, letting ptxas interleave independent MMA chains.
__device__ __forceinline__ void mma16816(float* c, const uint32_t* a,
                                         uint32_t b0, uint32_t b1) {
    asm("mma.sync.aligned.m16n8k16.row.col.f32.bf16.bf16.f32 "
        "{%0,%1,%2,%3},{%4,%5,%6,%7},{%8,%9},{%0,%1,%2,%3};"
        : "+f"(c[0]), "+f"(c[1]), "+f"(c[2]), "+f"(c[3])
        : "r"(a[0]), "r"(a[1]), "r"(a[2]), "r"(a[3]), "r"(b0), "r"(b1));
}
__device__ __forceinline__ uint32_t pack2(__nv_bfloat16 a, __nv_bfloat16 b) {
    __nv_bfloat162 t = __halves2bfloat162(a, b);
    return *reinterpret_cast<uint32_t*>(&t);
}
__device__ __forceinline__ void split1(float v, __nv_bfloat16& h, __nv_bfloat16& l) {
    h = __float2bfloat16(v);
    l = __float2bfloat16(v - __bfloat162float(h));
}
__device__ __forceinline__ float bf2f(__nv_bfloat16 v) { return __bfloat162float(v); }

// ---------------------------------------------------------------------------
// Merged fp32 -> (hi,lo) bf16 split for all 6 weight tensors + x_in.
// ---------------------------------------------------------------------------
#define SPLIT_TOTAL_BLOCKS 16896

__global__ __launch_bounds__(256)
void split_all_kernel(const float* __restrict__ w_in1, const float* __restrict__ w_out1,
                      const float* __restrict__ w_in2, const float* __restrict__ w_out2,
                      const float* __restrict__ fw1,  const float* __restrict__ fw2,
                      const float* __restrict__ x,
                      __nv_bfloat16* __restrict__ WH, __nv_bfloat16* __restrict__ WL,
                      __nv_bfloat16* __restrict__ P1H, __nv_bfloat16* __restrict__ P1L)
{
    const int bid = blockIdx.x;
    const float* src;
    __nv_bfloat16 *dh, *dl;
    int rb;
    if (bid < 3072)       { src = w_in1;  dh = WH + W_IN1_OFF;  dl = WL + W_IN1_OFF;  rb = bid; }
    else if (bid < 4096)  { src = w_out1; dh = WH + W_OUT1_OFF; dl = WL + W_OUT1_OFF; rb = bid - 3072; }
    else if (bid < 7168)  { src = w_in2;  dh = WH + W_IN2_OFF;  dl = WL + W_IN2_OFF;  rb = bid - 4096; }
    else if (bid < 8192)  { src = w_out2; dh = WH + W_OUT2_OFF; dl = WL + W_OUT2_OFF; rb = bid - 7168; }
    else if (bid < 12288) { src = fw1;    dh = WH + FW1_OFF;    dl = WL + FW1_OFF;    rb = bid - 8192; }
    else if (bid < 16384) { src = fw2;    dh = WH + FW2_OFF;    dl = WL + FW2_OFF;    rb = bid - 12288; }
    else                  { src = x;      dh = P1H;             dl = P1L;             rb = bid - 16384; }

    const size_t base = (size_t)rb * 4096 + threadIdx.x * 4;
    #pragma unroll
    for (int j = 0; j < 4; j++) {
        const size_t i = base + j * 1024;
        float4 v = *(const float4*)(src + i);
        __nv_bfloat16 h0,h1,h2,h3,l0,l1,l2,l3;
        split1(v.x,h0,l0); split1(v.y,h1,l1); split1(v.z,h2,l2); split1(v.w,h3,l3);
        uint2 uh; uh.x = pack2(h0,h1); uh.y = pack2(h2,h3);
        uint2 ul; ul.x = pack2(l0,l1); ul.y = pack2(l2,l3);
        *(uint2*)(dh + i) = uh;
        *(uint2*)(dl + i) = ul;
    }
}

// ---------------------------------------------------------------------------
// bf16x3 tensor-core GEMM. CTA 128x128x32; 256 threads, warp tile 32x64.
// MMA issue order interleaves the 4 independent accumulators between the
// three bf16x3 terms (dependent-op distance 4 instead of 1).
// gridDim.z = split-K factor; PARTIAL writes raw fp32 partials.
// ---------------------------------------------------------------------------
#define STAGE_BYTES 32768
#define GSMEM_BYTES (3*STAGE_BYTES)

template<int EPI, bool OSPLIT, bool OF32, bool PARTIAL>
__global__ __launch_bounds__(256, 2)
void gemm_bf3(const __nv_bfloat16* __restrict__ Ah, const __nv_bfloat16* __restrict__ Al,
              const __nv_bfloat16* __restrict__ Bh, const __nv_bfloat16* __restrict__ Bl,
              const float* __restrict__ bias, const float* __restrict__ Res,
              float* __restrict__ C, __nv_bfloat16* __restrict__ Chi,
              __nv_bfloat16* __restrict__ Clo, float* __restrict__ Part,
              int M, int N, int K)
{
    extern __shared__ __nv_bfloat16 smbuf[];
    const uint32_t smem_u32 = (uint32_t)__cvta_generic_to_shared(smbuf);

    const int tid = threadIdx.x;
    const int m0 = blockIdx.y * 128;
    const int n0 = blockIdx.x * 128;
    const int z  = blockIdx.z;
    const int Ksub = K / gridDim.z;

    const int lrow = tid & 127;
    const bool isB = tid >= 128;
    const size_t kofs = (size_t)z * Ksub;
    const __nv_bfloat16* pH = (isB ? Bh + (size_t)(n0 + lrow) * K
                                   : Ah + (size_t)(m0 + lrow) * K) + kofs;
    const __nv_bfloat16* pL = (isB ? Bl + (size_t)(n0 + lrow) * K
                                   : Al + (size_t)(m0 + lrow) * K) + kofs;
    const uint32_t regH = isB ? 16384u : 0u;
    const uint32_t rowb = (uint32_t)lrow * 16;

    auto load_stage = [&](int kt, int s) {
        const uint32_t sb = smem_u32 + (uint32_t)s * STAGE_BYTES + regH;
        const size_t gk = (size_t)kt * 32;
        #pragma unroll
        for (int ko = 0; ko < 4; ko++) {
            const uint32_t o = (uint32_t)ko * 2048 + rowb;
            cp16(sb + o,        pH + gk + ko*8);
            cp16(sb + 8192 + o, pL + gk + ko*8);
        }
        cp_commit();
    };

    const int wid  = tid >> 5;
    const int lane = tid & 31;
    const int wm = (wid >> 1) * 32;
    const int wn = (wid & 1) * 64;
    const int a_row = lane & 15;
    const int a_ko  = lane >> 4;
    const int b_row = (lane & 7) + ((lane & 16) >> 1);
    const int b_ko  = (lane >> 3) & 1;

    const uint32_t aoff = (uint32_t)((a_ko*1024 + (wm + a_row)*8) * 2);
    const uint32_t boff = (uint32_t)(16384 + (b_ko*1024 + (wn + b_row)*8) * 2);

    float acc[2][8][4];
    #pragma unroll
    for (int i = 0; i < 2; i++)
        #pragma unroll
        for (int j = 0; j < 8; j++)
            #pragma unroll
            for (int e = 0; e < 4; e++) acc[i][j][e] = 0.f;

    const int T = Ksub >> 5;

    load_stage(0, 0);
    if (T > 1) load_stage(1, 1);

    for (int kt = 0; kt < T; kt++) {
        if (kt + 1 < T) cp_wait1(); else cp_wait0();
        __syncthreads();
        if (kt + 2 < T) load_stage(kt + 2, (kt + 2) % 3);

        const uint32_t sb = smem_u32 + (uint32_t)(kt % 3) * STAGE_BYTES;
        #pragma unroll
        for (int ko0 = 0; ko0 < 4; ko0 += 2) {
            uint32_t a_h[2][4], a_l[2][4];
            #pragma unroll
            for (int mf = 0; mf < 2; mf++) {
                const uint32_t ad = sb + aoff + (uint32_t)ko0*2048 + (uint32_t)mf*256;
                ldsm4(a_h[mf], ad);
                ldsm4(a_l[mf], ad + 8192);
            }
            #pragma unroll
            for (int nf2 = 0; nf2 < 4; nf2++) {
                uint32_t b_h[4], b_l[4];
                const uint32_t bd = sb + boff + (uint32_t)ko0*2048 + (uint32_t)nf2*256;
                ldsm4(b_h, bd);
                ldsm4(b_l, bd + 8192);
                const int nf = nf2 * 2;
                // term hh across all 4 independent accumulators
                mma16816(acc[0][nf],   a_h[0], b_h[0], b_h[1]);
                mma16816(acc[0][nf+1], a_h[0], b_h[2], b_h[3]);
                mma16816(acc[1][nf],   a_h[1], b_h[0], b_h[1]);
                mma16816(acc[1][nf+1], a_h[1], b_h[2], b_h[3]);
                // term hl
                mma16816(acc[0][nf],   a_h[0], b_l[0], b_l[1]);
                mma16816(acc[0][nf+1], a_h[0], b_l[2], b_l[3]);
                mma16816(acc[1][nf],   a_h[1], b_l[0], b_l[1]);
                mma16816(acc[1][nf+1], a_h[1], b_l[2], b_l[3]);
                // term lh
                mma16816(acc[0][nf],   a_l[0], b_h[0], b_h[1]);
                mma16816(acc[0][nf+1], a_l[0], b_h[2], b_h[3]);
                mma16816(acc[1][nf],   a_l[1], b_h[0], b_h[1]);
                mma16816(acc[1][nf+1], a_l[1], b_h[2], b_h[3]);
            }
        }
    }

    // ---- epilogue ----
    const int er = lane >> 2;
    const int ec = (lane & 3) * 2;
    if (PARTIAL) {
        float* dst = Part + (size_t)z * M * N;
        #pragma unroll
        for (int mf = 0; mf < 2; mf++)
            #pragma unroll
            for (int nf = 0; nf < 8; nf++) {
                const int m = m0 + wm + mf*16 + er;
                const int n = n0 + wn + nf*8 + ec;
                #pragma unroll
                for (int half = 0; half < 2; half++) {
                    const int mm = m + half*8;
                    *(float2*)(dst + (size_t)mm * N + n) =
                        make_float2(acc[mf][nf][half*2+0], acc[mf][nf][half*2+1]);
                }
            }
        return;
    }

    #pragma unroll
    for (int mf = 0; mf < 2; mf++) {
        #pragma unroll
        for (int nf = 0; nf < 8; nf++) {
            const int m = m0 + wm + mf*16 + er;
            const int n = n0 + wn + nf*8 + ec;
            const float2 bv = *(const float2*)(bias + n);
            #pragma unroll
            for (int half = 0; half < 2; half++) {
                const int mm = m + half*8;
                float t0 = acc[mf][nf][half*2+0] + bv.x;
                float t1 = acc[mf][nf][half*2+1] + bv.y;
                if (EPI == 1) {
                    t0 = 0.5f * t0 * (1.f + erff(t0 * 0.70710678118654752f));
                    t1 = 0.5f * t1 * (1.f + erff(t1 * 0.70710678118654752f));
                }
                if (EPI == 2) {
                    const float2 rv = *(const float2*)(Res + (size_t)mm * N + n);
                    t0 += rv.x; t1 += rv.y;
                }
                if (OF32) {
                    *(float2*)(C + (size_t)mm * N + n) = make_float2(t0, t1);
                }
                if (OSPLIT) {
                    __nv_bfloat16 h0,h1,l0,l1;
                    split1(t0,h0,l0); split1(t1,h1,l1);
                    *(uint32_t*)(Chi + (size_t)mm * N + n) = pack2(h0,h1);
                    *(uint32_t*)(Clo + (size_t)mm * N + n) = pack2(l0,l1);
                }
            }
        }
    }
}

// ---------------------------------------------------------------------------
// Split-K reduce + epilogue. N fixed at DDIM.
// ---------------------------------------------------------------------------
template<int EPI, bool OSPLIT, bool OF32, int S>
__global__ __launch_bounds__(256)
void epi_reduce(const float* __restrict__ Part, const float* __restrict__ bias,
                const float* __restrict__ Res, float* __restrict__ C,
                __nv_bfloat16* __restrict__ Chi, __nv_bfloat16* __restrict__ Clo)
{
    const size_t i = (size_t)blockIdx.x * 1024 + threadIdx.x * 4;
    const int n = (int)(i & (DDIM - 1));
    float4 t = *(const float4*)(Part + i);
    #pragma unroll
    for (int s = 1; s < S; s++) {
        const float4 p = *(const float4*)(Part + (size_t)s * (NTOK*DDIM) + i);
        t.x += p.x; t.y += p.y; t.z += p.z; t.w += p.w;
    }
    const float4 bv = *(const float4*)(bias + n);
    t.x += bv.x; t.y += bv.y; t.z += bv.z; t.w += bv.w;
    if (EPI == 1) {
        t.x = 0.5f * t.x * (1.f + erff(t.x * 0.70710678118654752f));
        t.y = 0.5f * t.y * (1.f + erff(t.y * 0.70710678118654752f));
        t.z = 0.5f * t.z * (1.f + erff(t.z * 0.70710678118654752f));
        t.w = 0.5f * t.w * (1.f + erff(t.w * 0.70710678118654752f));
    }
    if (EPI == 2) {
        const float4 rv = *(const float4*)(Res + i);
        t.x += rv.x; t.y += rv.y; t.z += rv.z; t.w += rv.w;
    }
    if (OF32) *(float4*)(C + i) = t;
    if (OSPLIT) {
        __nv_bfloat16 h0,h1,h2,h3,l0,l1,l2,l3;
        split1(t.x,h0,l0); split1(t.y,h1,l1); split1(t.z,h2,l2); split1(t.w,h3,l3);
        uint2 uh; uh.x = pack2(h0,h1); uh.y = pack2(h2,h3);
        uint2 ul; ul.x = pack2(l0,l1); ul.y = pack2(l2,l3);
        *(uint2*)(Chi + i) = uh;
        *(uint2*)(Clo + i) = ul;
    }
}

// ---------------------------------------------------------------------------
// Tensor-core full attention (bf16x3 flash), MMA chains interleaved.
// ---------------------------------------------------------------------------
#define ATTN_TC_SMEM 65536

__global__ __launch_bounds__(128, 3)
void attn_tc_kernel(const __nv_bfloat16* __restrict__ qkvh,
                    const __nv_bfloat16* __restrict__ qkvl,
                    __nv_bfloat16* __restrict__ oh,
                    __nv_bfloat16* __restrict__ ol)
{
    extern __shared__ char smc[];
    const uint32_t sb = (uint32_t)__cvta_generic_to_shared(smc);

    const int bh = blockIdx.x;
    const int b  = bh >> 4;
    const int h  = bh & 15;
    const int qt = blockIdx.y;
    const int tid  = threadIdx.x;
    const int wid  = tid >> 5;
    const int lane = tid & 31;

    const int r    = tid >> 1;
    const int koh  = (tid & 1) * 4;

    {
        const size_t qrow = (size_t)(b*SLEN + qt*64 + r) * D3 + h*HD;
        #pragma unroll
        for (int it = 0; it < 4; it++) {
            const int ko = koh + it;
            const uint32_t dst = sb + (uint32_t)(((ko*64 + r)*8) * 2);
            cp16(dst,        qkvh + qrow + ko*8);
            cp16(dst + 8192, qkvl + qrow + ko*8);
        }
        cp_commit();
    }

    const int a_row = lane & 15;
    const int a_ko  = lane >> 4;
    const int b_row = (lane & 7) + ((lane & 16) >> 1);
    const int b_ko  = (lane >> 3) & 1;
    const int v_key = lane & 15;
    const int v_ko  = lane >> 4;

    uint32_t qa_h[4][4], qa_l[4][4];

    cp_wait0();
    __syncthreads();
    #pragma unroll
    for (int ks = 0; ks < 4; ks++) {
        const uint32_t ad = sb +
            (uint32_t)((((ks*2 + a_ko)*64 + wid*16 + a_row)*8) * 2);
        ldsm4(qa_h[ks], ad);
        ldsm4(qa_l[ks], ad + 8192);
    }
    __syncthreads();

    auto load_kv = [&](int kt, int s) {
        const uint32_t stg = sb + (uint32_t)s * 32768;
        const size_t krow = (size_t)(b*SLEN + kt*64 + r) * D3 + DDIM + h*HD;
        const size_t vrow = krow + DDIM;
        #pragma unroll
        for (int it = 0; it < 4; it++) {
            const int ko = koh + it;
            const uint32_t off = (uint32_t)(((ko*64 + r)*8) * 2);
            cp16(stg + off,          qkvh + krow + ko*8);
            cp16(stg + 8192  + off,  qkvl + krow + ko*8);
            cp16(stg + 16384 + off,  qkvh + vrow + ko*8);
            cp16(stg + 24576 + off,  qkvl + vrow + ko*8);
        }
    };

    load_kv(0, 0);
    cp_commit();

    float m0 = -1e30f, m1 = -1e30f, l0 = 0.f, l1 = 0.f;
    float oacc[8][4];
    #pragma unroll
    for (int nf = 0; nf < 8; nf++)
        #pragma unroll
        for (int e = 0; e < 4; e++) oacc[nf][e] = 0.f;

    for (int kt = 0; kt < 16; kt++) {
        const int s = kt & 1;
        if (kt + 1 < 16) {
            load_kv(kt + 1, s ^ 1);
            cp_commit();
            cp_wait1();
        } else {
            cp_wait0();
        }
        __syncthreads();

        const uint32_t stg = sb + (uint32_t)s * 32768;

        float sc[8][4];
        #pragma unroll
        for (int nf = 0; nf < 8; nf++)
            #pragma unroll
            for (int e = 0; e < 4; e++) sc[nf][e] = 0.f;

        #pragma unroll
        for (int ks = 0; ks < 4; ks++) {
            #pragma unroll
            for (int np = 0; np < 4; np++) {
                uint32_t kb[4], kl[4];
                const uint32_t kd = stg +
                    (uint32_t)((((ks*2 + b_ko)*64 + np*16 + b_row)*8) * 2);
                ldsm4(kb, kd);
                ldsm4(kl, kd + 8192);
                mma16816(sc[2*np],   qa_h[ks], kb[0], kb[1]);
                mma16816(sc[2*np+1], qa_h[ks], kb[2], kb[3]);
                mma16816(sc[2*np],   qa_h[ks], kl[0], kl[1]);
                mma16816(sc[2*np+1], qa_h[ks], kl[2], kl[3]);
                mma16816(sc[2*np],   qa_l[ks], kb[0], kb[1]);
                mma16816(sc[2*np+1], qa_l[ks], kb[2], kb[3]);
            }
        }

        #pragma unroll
        for (int nf = 0; nf < 8; nf++)
            #pragma unroll
            for (int e = 0; e < 4; e++) sc[nf][e] *= 0.125f;

        float mx0 = m0, mx1 = m1;
        #pragma unroll
        for (int nf = 0; nf < 8; nf++) {
            mx0 = fmaxf(mx0, fmaxf(sc[nf][0], sc[nf][1]));
            mx1 = fmaxf(mx1, fmaxf(sc[nf][2], sc[nf][3]));
        }
        mx0 = fmaxf(mx0, __shfl_xor_sync(0xffffffffu, mx0, 1));
        mx0 = fmaxf(mx0, __shfl_xor_sync(0xffffffffu, mx0, 2));
        mx1 = fmaxf(mx1, __shfl_xor_sync(0xffffffffu, mx1, 1));
        mx1 = fmaxf(mx1, __shfl_xor_sync(0xffffffffu, mx1, 2));

        const float al0 = __expf(m0 - mx0);
        const float al1 = __expf(m1 - mx1);
        m0 = mx0; m1 = mx1;

        float s0 = 0.f, s1 = 0.f;
        uint32_t pah[4][4], pal[4][4];
        #pragma unroll
        for (int nf = 0; nf < 8; nf++) {
            const float p0 = __expf(sc[nf][0] - m0);
            const float p1 = __expf(sc[nf][1] - m0);
            const float p2 = __expf(sc[nf][2] - m1);
            const float p3 = __expf(sc[nf][3] - m1);
            s0 += p0 + p1;
            s1 += p2 + p3;
            __nv_bfloat16 h0,h1,h2,h3,lo0,lo1,lo2,lo3;
            split1(p0,h0,lo0); split1(p1,h1,lo1);
            split1(p2,h2,lo2); split1(p3,h3,lo3);
            const int ks = nf >> 1;
            const int hv = (nf & 1) * 2;
            pah[ks][hv+0] = pack2(h0, h1);
            pah[ks][hv+1] = pack2(h2, h3);
            pal[ks][hv+0] = pack2(lo0, lo1);
            pal[ks][hv+1] = pack2(lo2, lo3);
        }
        s0 += __shfl_xor_sync(0xffffffffu, s0, 1);
        s0 += __shfl_xor_sync(0xffffffffu, s0, 2);
        s1 += __shfl_xor_sync(0xffffffffu, s1, 1);
        s1 += __shfl_xor_sync(0xffffffffu, s1, 2);
        l0 = l0 * al0 + s0;
        l1 = l1 * al1 + s1;

        #pragma unroll
        for (int nf = 0; nf < 8; nf++) {
            oacc[nf][0] *= al0; oacc[nf][1] *= al0;
            oacc[nf][2] *= al1; oacc[nf][3] *= al1;
        }

        #pragma unroll
        for (int ks = 0; ks < 4; ks++) {
            #pragma unroll
            for (int np = 0; np < 4; np++) {
                uint32_t vb[4], vl[4];
                const uint32_t vd = stg + 16384 +
                    (uint32_t)((((np*2 + v_ko)*64 + ks*16 + v_key)*8) * 2);
                ldsm4t(vb, vd);
                ldsm4t(vl, vd + 8192);
                mma16816(oacc[2*np],   pah[ks], vb[0], vb[1]);
                mma16816(oacc[2*np+1], pah[ks], vb[2], vb[3]);
                mma16816(oacc[2*np],   pah[ks], vl[0], vl[1]);
                mma16816(oacc[2*np+1], pah[ks], vl[2], vl[3]);
                mma16816(oacc[2*np],   pal[ks], vb[0], vb[1]);
                mma16816(oacc[2*np+1], pal[ks], vb[2], vb[3]);
            }
        }
        __syncthreads();
    }

    const float inv0 = 1.f / l0;
    const float inv1 = 1.f / l1;
    const int er  = lane >> 2;
    const int ec  = (lane & 3) * 2;
    const int tok0 = b*SLEN + qt*64 + wid*16 + er;
    const int tok1 = tok0 + 8;
    #pragma unroll
    for (int nf = 0; nf < 8; nf++) {
        const int col = h*HD + nf*8 + ec;
        const float o0 = oacc[nf][0] * inv0;
        const float o1 = oacc[nf][1] * inv0;
        const float o2 = oacc[nf][2] * inv1;
        const float o3 = oacc[nf][3] * inv1;
        __nv_bfloat16 h0,h1,h2,h3,lo0,lo1,lo2,lo3;
        split1(o0,h0,lo0); split1(o1,h1,lo1);
        split1(o2,h2,lo2); split1(o3,h3,lo3);
        *(uint32_t*)(oh + (size_t)tok0 * DDIM + col) = pack2(h0, h1);
        *(uint32_t*)(ol + (size_t)tok0 * DDIM + col) = pack2(lo0, lo1);
        *(uint32_t*)(oh + (size_t)tok1 * DDIM + col) = pack2(h2, h3);
        *(uint32_t*)(ol + (size_t)tok1 * DDIM + col) = pack2(lo2, lo3);
    }
}

// ---------------------------------------------------------------------------
// Banded attention — unchanged.
// ---------------------------------------------------------------------------
__global__ __launch_bounds__(256)
void attn_band_kernel(const __nv_bfloat16* __restrict__ qkvh,
                      const __nv_bfloat16* __restrict__ qkvl,
                      __nv_bfloat16* __restrict__ oh,
                      __nv_bfloat16* __restrict__ ol)
{
    const int gw   = (blockIdx.x * blockDim.x + threadIdx.x) >> 5;
    const int lane = threadIdx.x & 31;
    const int i = gw & (SLEN-1);
    const int h = (gw >> 10) & (HNUM-1);
    const int b = gw >> 14;

    const size_t qbase = (size_t)(b*SLEN + i) * D3 + h*HD;
    const float q0 = bf2f(qkvh[qbase + lane])      + bf2f(qkvl[qbase + lane]);
    const float q1 = bf2f(qkvh[qbase + 32 + lane]) + bf2f(qkvl[qbase + 32 + lane]);

    float sc[5];
    int   jc[5];
    #pragma unroll
    for (int jj = 0; jj < 5; jj++) {
        int j = i - 2 + jj;
        bool valid = (j >= 0) && (j < SLEN);
        jc[jj] = valid ? j : i;
        const size_t kb = (size_t)(b*SLEN + jc[jj]) * D3 + DDIM + h*HD;
        const float k0 = bf2f(qkvh[kb + lane])      + bf2f(qkvl[kb + lane]);
        const float k1 = bf2f(qkvh[kb + 32 + lane]) + bf2f(qkvl[kb + 32 + lane]);
        float p = q0 * k0 + q1 * k1;
        #pragma unroll
        for (int off = 16; off; off >>= 1) p += __shfl_xor_sync(0xffffffffu, p, off);
        sc[jj] = valid ? p * 0.125f : -1e30f;
    }
    float mx = sc[0];
    #pragma unroll
    for (int jj = 1; jj < 5; jj++) mx = fmaxf(mx, sc[jj]);
    float w[5], sum = 0.f;
    #pragma unroll
    for (int jj = 0; jj < 5; jj++) { w[jj] = __expf(sc[jj] - mx); sum += w[jj]; }
    const float inv = 1.f / sum;

    float o0 = 0.f, o1 = 0.f;
    #pragma unroll
    for (int jj = 0; jj < 5; jj++) {
        const size_t vb = (size_t)(b*SLEN + jc[jj]) * D3 + 2*DDIM + h*HD;
        const float v0 = bf2f(qkvh[vb + lane])      + bf2f(qkvl[vb + lane]);
        const float v1 = bf2f(qkvh[vb + 32 + lane]) + bf2f(qkvl[vb + 32 + lane]);
        o0 = fmaf(w[jj], v0, o0);
        o1 = fmaf(w[jj], v1, o1);
    }
    o0 *= inv; o1 *= inv;

    const size_t ob = (size_t)(b*SLEN + i) * DDIM + h*HD;
    __nv_bfloat16 hh, ll;
    split1(o0, hh, ll);
    oh[ob + lane] = hh;  ol[ob + lane] = ll;
    split1(o1, hh, ll);
    oh[ob + 32 + lane] = hh;  ol[ob + 32 + lane] = ll;
}

// ---------------------------------------------------------------------------
// LayerNorm — unchanged.
// ---------------------------------------------------------------------------
__global__ __launch_bounds__(256)
void ln_kernel(const float* __restrict__ a, const float* __restrict__ r,
               const float* __restrict__ g, const float* __restrict__ bt,
               float* __restrict__ out,
               __nv_bfloat16* __restrict__ ohh, __nv_bfloat16* __restrict__ oll)
{
    __shared__ float red[2][8];
    __shared__ float s_mean, s_rstd;
    const int n = blockIdx.x;
    const int tid = threadIdx.x;
    const size_t base = (size_t)n * DDIM + tid * 4;

    float4 va = *(const float4*)(a + base);
    if (r) {
        float4 vr = *(const float4*)(r + base);
        va.x += vr.x; va.y += vr.y; va.z += vr.z; va.w += vr.w;
    }
    float s  = va.x + va.y + va.z + va.w;
    float sq = va.x*va.x + va.y*va.y + va.z*va.z + va.w*va.w;

    #pragma unroll
    for (int off = 16; off; off >>= 1) {
        s  += __shfl_xor_sync(0xffffffffu, s,  off);
        sq += __shfl_xor_sync(0xffffffffu, sq, off);
    }
    const int wid = tid >> 5;
    if ((tid & 31) == 0) { red[0][wid] = s; red[1][wid] = sq; }
    __syncthreads();
    if (tid < 32) {
        float ts  = (tid < 8) ? red[0][tid] : 0.f;
        float tsq = (tid < 8) ? red[1][tid] : 0.f;
        #pragma unroll
        for (int off = 4; off; off >>= 1) {
            ts  += __shfl_xor_sync(0xffffffffu, ts,  off);
            tsq += __shfl_xor_sync(0xffffffffu, tsq, off);
        }
        if (tid == 0) {
            float mean = ts * (1.f / DDIM);
            float var  = tsq * (1.f / DDIM) - mean * mean;
            s_mean = mean;
            s_rstd = rsqrtf(var + EPS);
        }
    }
    __syncthreads();
    const float mean = s_mean, rstd = s_rstd;
    float4 gg = *(const float4*)(g + tid*4);
    float4 bb = *(const float4*)(bt + tid*4);
    float4 o;
    o.x = (va.x - mean) * rstd * gg.x + bb.x;
    o.y = (va.y - mean) * rstd * gg.y + bb.y;
    o.z = (va.z - mean) * rstd * gg.z + bb.z;
    o.w = (va.w - mean) * rstd * gg.w + bb.w;
    *(float4*)(out + base) = o;
    if (ohh) {
        __nv_bfloat16 h0,h1,h2,h3,l0,l1,l2,l3;
        split1(o.x,h0,l0); split1(o.y,h1,l1); split1(o.z,h2,l2); split1(o.w,h3,l3);
        uint2 uh; uh.x = pack2(h0,h1); uh.y = pack2(h2,h3);
        uint2 ul; ul.x = pack2(l0,l1); ul.y = pack2(l2,l3);
        *(uint2*)(ohh + base) = uh;
        *(uint2*)(oll + base) = ul;
    }
}

// ---------------------------------------------------------------------------
// Orchestration
// ---------------------------------------------------------------------------
extern "C" void kernel_launch(void* const* d_in, const int* in_sizes, int n_in,
                              void* d_out, int out_size)
{
    const float* x_in   = (const float*)d_in[0];
    const float* w_in1  = (const float*)d_in[1];
    const float* b_in1  = (const float*)d_in[2];
    const float* w_out1 = (const float*)d_in[3];
    const float* b_out1 = (const float*)d_in[4];
    const float* ln1_g  = (const float*)d_in[5];
    const float* ln1_b  = (const float*)d_in[6];
    const float* w_in2  = (const float*)d_in[7];
    const float* b_in2  = (const float*)d_in[8];
    const float* w_out2 = (const float*)d_in[9];
    const float* b_out2 = (const float*)d_in[10];
    const float* ln2_g  = (const float*)d_in[11];
    const float* ln2_b  = (const float*)d_in[12];
    const float* ffn_w1 = (const float*)d_in[13];
    const float* ffn_b1 = (const float*)d_in[14];
    const float* ffn_w2 = (const float*)d_in[15];
    const float* ffn_b2 = (const float*)d_in[16];
    const float* lnf_g  = (const float*)d_in[17];
    const float* lnf_b  = (const float*)d_in[18];

    float *PROJ, *X, *X2, *ATT, *PART;
    __nv_bfloat16 *WH, *WL, *QKVH, *QKVL, *P1H, *P1L, *P2H, *P2L;
    cudaGetSymbolAddress((void**)&PROJ, g_proj);
    cudaGetSymbolAddress((void**)&X,    g_x);
    cudaGetSymbolAddress((void**)&X2,   g_x2);
    cudaGetSymbolAddress((void**)&ATT,  g_att);
    cudaGetSymbolAddress((void**)&PART, g_part);
    cudaGetSymbolAddress((void**)&WH,   g_wh);
    cudaGetSymbolAddress((void**)&WL,   g_wl);
    cudaGetSymbolAddress((void**)&QKVH, g_qkvh);
    cudaGetSymbolAddress((void**)&QKVL, g_qkvl);
    cudaGetSymbolAddress((void**)&P1H,  g_p1h);
    cudaGetSymbolAddress((void**)&P1L,  g_p1l);
    cudaGetSymbolAddress((void**)&P2H,  g_p2h);
    cudaGetSymbolAddress((void**)&P2L,  g_p2l);

    cudaFuncSetAttribute(attn_tc_kernel,
                         cudaFuncAttributeMaxDynamicSharedMemorySize, ATTN_TC_SMEM);
    cudaFuncSetAttribute(gemm_bf3<0,true,false,false>,
                         cudaFuncAttributeMaxDynamicSharedMemorySize, GSMEM_BYTES);
    cudaFuncSetAttribute(gemm_bf3<1,true,false,false>,
                         cudaFuncAttributeMaxDynamicSharedMemorySize, GSMEM_BYTES);
    cudaFuncSetAttribute(gemm_bf3<0,false,false,true>,
                         cudaFuncAttributeMaxDynamicSharedMemorySize, GSMEM_BYTES);

    const dim3 blk(256);
    const dim3 gblk(256);
    const dim3 g_qkvp(D3/128,  NTOK/128);        // (24,16)
    const dim3 g_outp(DDIM/128, NTOK/128, 2);    // (8,16,2)  split-K 2
    const dim3 g_ffn1(MDIM/128, NTOK/128);       // (32,16)
    const dim3 g_ffn2(DDIM/128, NTOK/128, 4);    // (8,16,4)  split-K 4
    const dim3 g_attn(BNUM*HNUM, SLEN/64);       // (32,16)
    const int  g_band = (BNUM*HNUM*SLEN*32) / 256;
    const int  g_ln   = NTOK;
    const int  g_red  = (NTOK*DDIM) / 1024;      // 2048

    // ---- single merged split launch: all 6 weights + layer-0 input ----
    split_all_kernel<<<SPLIT_TOTAL_BLOCKS, blk>>>(
        w_in1, w_out1, w_in2, w_out2, ffn_w1, ffn_w2, x_in,
        WH, WL, P1H, P1L);

    const float* xcur = x_in;
    for (int l = 0; l < LNUM; l++) {
        const size_t oW3 = (size_t)l * D3 * DDIM;
        const size_t oW1 = (size_t)l * DDIM * DDIM;
        const size_t oWm = (size_t)l * MDIM * DDIM;

        // ---- intra-frame full MHA ----
        gemm_bf3<0,true,false,false><<<g_qkvp, gblk, GSMEM_BYTES>>>(
            P1H, P1L, WH+W_IN1_OFF+oW3, WL+W_IN1_OFF+oW3,
            b_in1 + (size_t)l*D3, nullptr, nullptr, QKVH, QKVL, nullptr,
            NTOK, D3, DDIM);
        attn_tc_kernel<<<g_attn, 128, ATTN_TC_SMEM>>>(QKVH, QKVL, P1H, P1L);
        gemm_bf3<0,false,false,true><<<g_outp, gblk, GSMEM_BYTES>>>(
            P1H, P1L, WH+W_OUT1_OFF+oW1, WL+W_OUT1_OFF+oW1,
            nullptr, nullptr, nullptr, nullptr, nullptr, PART,
            NTOK, DDIM, DDIM);
        epi_reduce<0,false,true,2><<<g_red, blk>>>(
            PART, b_out1 + (size_t)l*DDIM, nullptr, PROJ, nullptr, nullptr);
        ln_kernel<<<g_ln, blk>>>(PROJ, xcur, ln1_g + (size_t)l*DDIM,
                                 ln1_b + (size_t)l*DDIM, X2, P1H, P1L);

        // ---- inter-frame banded MHA ----
        gemm_bf3<0,true,false,false><<<g_qkvp, gblk, GSMEM_BYTES>>>(
            P1H, P1L, WH+W_IN2_OFF+oW3, WL+W_IN2_OFF+oW3,
            b_in2 + (size_t)l*D3, nullptr, nullptr, QKVH, QKVL, nullptr,
            NTOK, D3, DDIM);
        attn_band_kernel<<<g_band, blk>>>(QKVH, QKVL, P1H, P1L);
        gemm_bf3<0,false,false,true><<<g_outp, gblk, GSMEM_BYTES>>>(
            P1H, P1L, WH+W_OUT2_OFF+oW1, WL+W_OUT2_OFF+oW1,
            nullptr, nullptr, nullptr, nullptr, nullptr, PART,
            NTOK, DDIM, DDIM);
        epi_reduce<0,false,true,2><<<g_red, blk>>>(
            PART, b_out2 + (size_t)l*DDIM, nullptr, PROJ, nullptr, nullptr);
        ln_kernel<<<g_ln, blk>>>(PROJ, X2, ln2_g + (size_t)l*DDIM,
                                 ln2_b + (size_t)l*DDIM, ATT, P1H, P1L);

        // ---- FFN ----
        gemm_bf3<1,true,false,false><<<g_ffn1, gblk, GSMEM_BYTES>>>(
            P1H, P1L, WH+FW1_OFF+oWm, WL+FW1_OFF+oWm,
            ffn_b1 + (size_t)l*MDIM, nullptr, nullptr, P2H, P2L, nullptr,
            NTOK, MDIM, DDIM);
        gemm_bf3<0,false,false,true><<<g_ffn2, gblk, GSMEM_BYTES>>>(
            P2H, P2L, WH+FW2_OFF+oWm, WL+FW2_OFF+oWm,
            nullptr, nullptr, nullptr, nullptr, nullptr, PART,
            NTOK, DDIM, MDIM);
        epi_reduce<2,true,true,4><<<g_red, blk>>>(
            PART, ffn_b2 + (size_t)l*DDIM, ATT, X, P1H, P1L);
        xcur = X;
    }

    ln_kernel<<<g_ln, blk>>>(xcur, nullptr, lnf_g, lnf_b, (float*)d_out,
                             nullptr, nullptr);
}

// round 13
// speedup vs baseline: 1.8830x; 1.0246x over previous
#include <cuda_runtime.h>
#include <cuda_bf16.h>
#include <math.h>
#include <stdint.h>

// ---------------------------------------------------------------------------
// Problem constants
// ---------------------------------------------------------------------------
#define LNUM 4
#define DDIM 1024
#define HNUM 16
#define HD   64
#define MDIM 4096
#define SLEN 1024
#define BNUM 2
#define NTOK (BNUM*SLEN)        // 2048
#define D3   (3*DDIM)           // 3072
#define EPS  1e-5f

// Weight split array layout (element offsets)
#define W_IN1_OFF   0u
#define W_OUT1_OFF  12582912u
#define W_IN2_OFF   16777216u
#define W_OUT2_OFF  29360128u
#define FW1_OFF     33554432u
#define FW2_OFF     50331648u
#define WTOTAL      67108864u

// ---------------------------------------------------------------------------
// Device scratch (no allocations allowed)
// ---------------------------------------------------------------------------
static __device__ float g_proj[NTOK*DDIM];
static __device__ float g_x   [NTOK*DDIM];
static __device__ float g_x2  [NTOK*DDIM];
static __device__ float g_att [NTOK*DDIM];
static __device__ float g_part[4u*NTOK*DDIM];        // split-K partials (32MB)

static __device__ __nv_bfloat16 g_wh[WTOTAL];        // weight hi
static __device__ __nv_bfloat16 g_wl[WTOTAL];        // weight lo
static __device__ __nv_bfloat16 g_qkvh[NTOK*D3];     // qkv hi
static __device__ __nv_bfloat16 g_qkvl[NTOK*D3];     // qkv lo
static __device__ __nv_bfloat16 g_p1h[NTOK*DDIM];
static __device__ __nv_bfloat16 g_p1l[NTOK*DDIM];
static __device__ __nv_bfloat16 g_p2h[NTOK*MDIM];
static __device__ __nv_bfloat16 g_p2l[NTOK*MDIM];

// ---------------------------------------------------------------------------
// Helpers
// ---------------------------------------------------------------------------
__device__ __forceinline__ void cp16(uint32_t d, const void* s) {
    asm volatile("cp.async.cg.shared.global [%0], [%1], 16;\n" :: "r"(d), "l"(s));
}
__device__ __forceinline__ void cp_commit() {
    asm volatile("cp.async.commit_group;\n" ::: "memory");
}
__device__ __forceinline__ void cp_wait1() {
    asm volatile("cp.async.wait_group 1;\n" ::: "memory");
}
__device__ __forceinline__ void cp_wait0() {
    asm volatile("cp.async.wait_group 0;\n" ::: "memory");
}
__device__ __forceinline__ void ldsm4(uint32_t* r, uint32_t a) {
    asm volatile("ldmatrix.sync.aligned.m8n8.x4.shared.b16 {%0,%1,%2,%3}, [%4];"
        : "=r"(r[0]), "=r"(r[1]), "=r"(r[2]), "=r"(r[3]) : "r"(a));
}
__device__ __forceinline__ void ldsm4t(uint32_t* r, uint32_t a) {
    asm volatile("ldmatrix.sync.aligned.m8n8.x4.trans.shared.b16 {%0,%1,%2,%3}, [%4];"
        : "=r"(r[0]), "=r"(r[1]), "=r"(r[2]), "=r"(r[3]) : "r"(a));
}
// Non-volatile: pure register computation; deps carried by constraints.
__device__ __forceinline__ void mma16816(float* c, const uint32_t* a,
                                         uint32_t b0, uint32_t b1) {
    asm("mma.sync.aligned.m16n8k16.row.col.f32.bf16.bf16.f32 "
        "{%0,%1,%2,%3},{%4,%5,%6,%7},{%8,%9},{%0,%1,%2,%3};"
        : "+f"(c[0]), "+f"(c[1]), "+f"(c[2]), "+f"(c[3])
        : "r"(a[0]), "r"(a[1]), "r"(a[2]), "r"(a[3]), "r"(b0), "r"(b1));
}
__device__ __forceinline__ uint32_t pack2(__nv_bfloat16 a, __nv_bfloat16 b) {
    __nv_bfloat162 t = __halves2bfloat162(a, b);
    return *reinterpret_cast<uint32_t*>(&t);
}
__device__ __forceinline__ void split1(float v, __nv_bfloat16& h, __nv_bfloat16& l) {
    h = __float2bfloat16(v);
    l = __float2bfloat16(v - __bfloat162float(h));
}
__device__ __forceinline__ float bf2f(__nv_bfloat16 v) { return __bfloat162float(v); }

// ---------------------------------------------------------------------------
// Merged fp32 -> (hi,lo) bf16 split for all 6 weight tensors + x_in.
// ---------------------------------------------------------------------------
#define SPLIT_TOTAL_BLOCKS 16896

__global__ __launch_bounds__(256)
void split_all_kernel(const float* __restrict__ w_in1, const float* __restrict__ w_out1,
                      const float* __restrict__ w_in2, const float* __restrict__ w_out2,
                      const float* __restrict__ fw1,  const float* __restrict__ fw2,
                      const float* __restrict__ x,
                      __nv_bfloat16* __restrict__ WH, __nv_bfloat16* __restrict__ WL,
                      __nv_bfloat16* __restrict__ P1H, __nv_bfloat16* __restrict__ P1L)
{
    const int bid = blockIdx.x;
    const float* src;
    __nv_bfloat16 *dh, *dl;
    int rb;
    if (bid < 3072)       { src = w_in1;  dh = WH + W_IN1_OFF;  dl = WL + W_IN1_OFF;  rb = bid; }
    else if (bid < 4096)  { src = w_out1; dh = WH + W_OUT1_OFF; dl = WL + W_OUT1_OFF; rb = bid - 3072; }
    else if (bid < 7168)  { src = w_in2;  dh = WH + W_IN2_OFF;  dl = WL + W_IN2_OFF;  rb = bid - 4096; }
    else if (bid < 8192)  { src = w_out2; dh = WH + W_OUT2_OFF; dl = WL + W_OUT2_OFF; rb = bid - 7168; }
    else if (bid < 12288) { src = fw1;    dh = WH + FW1_OFF;    dl = WL + FW1_OFF;    rb = bid - 8192; }
    else if (bid < 16384) { src = fw2;    dh = WH + FW2_OFF;    dl = WL + FW2_OFF;    rb = bid - 12288; }
    else                  { src = x;      dh = P1H;             dl = P1L;             rb = bid - 16384; }

    const size_t base = (size_t)rb * 4096 + threadIdx.x * 4;
    #pragma unroll
    for (int j = 0; j < 4; j++) {
        const size_t i = base + j * 1024;
        float4 v = *(const float4*)(src + i);
        __nv_bfloat16 h0,h1,h2,h3,l0,l1,l2,l3;
        split1(v.x,h0,l0); split1(v.y,h1,l1); split1(v.z,h2,l2); split1(v.w,h3,l3);
        uint2 uh; uh.x = pack2(h0,h1); uh.y = pack2(h2,h3);
        uint2 ul; ul.x = pack2(l0,l1); ul.y = pack2(l2,l3);
        *(uint2*)(dh + i) = uh;
        *(uint2*)(dl + i) = ul;
    }
}

// ---------------------------------------------------------------------------
// bf16x3 tensor-core GEMM. CTA 128x128x32; 256 threads, warp tile 32x64.
// B fragments are register double-buffered: the ldsm pair for group nf2+1
// is issued BEFORE the 12 MMAs of group nf2, hiding the LDSM->HMMA latency
// behind the MMA issue stream (ldsm stays volatile; manual hoist).
// gridDim.z = split-K factor; PARTIAL writes raw fp32 partials.
// ---------------------------------------------------------------------------
#define STAGE_BYTES 32768
#define GSMEM_BYTES (3*STAGE_BYTES)

template<int EPI, bool OSPLIT, bool OF32, bool PARTIAL>
__global__ __launch_bounds__(256, 2)
void gemm_bf3(const __nv_bfloat16* __restrict__ Ah, const __nv_bfloat16* __restrict__ Al,
              const __nv_bfloat16* __restrict__ Bh, const __nv_bfloat16* __restrict__ Bl,
              const float* __restrict__ bias, const float* __restrict__ Res,
              float* __restrict__ C, __nv_bfloat16* __restrict__ Chi,
              __nv_bfloat16* __restrict__ Clo, float* __restrict__ Part,
              int M, int N, int K)
{
    extern __shared__ __nv_bfloat16 smbuf[];
    const uint32_t smem_u32 = (uint32_t)__cvta_generic_to_shared(smbuf);

    const int tid = threadIdx.x;
    const int m0 = blockIdx.y * 128;
    const int n0 = blockIdx.x * 128;
    const int z  = blockIdx.z;
    const int Ksub = K / gridDim.z;

    const int lrow = tid & 127;
    const bool isB = tid >= 128;
    const size_t kofs = (size_t)z * Ksub;
    const __nv_bfloat16* pH = (isB ? Bh + (size_t)(n0 + lrow) * K
                                   : Ah + (size_t)(m0 + lrow) * K) + kofs;
    const __nv_bfloat16* pL = (isB ? Bl + (size_t)(n0 + lrow) * K
                                   : Al + (size_t)(m0 + lrow) * K) + kofs;
    const uint32_t regH = isB ? 16384u : 0u;
    const uint32_t rowb = (uint32_t)lrow * 16;

    auto load_stage = [&](int kt, int s) {
        const uint32_t sb = smem_u32 + (uint32_t)s * STAGE_BYTES + regH;
        const size_t gk = (size_t)kt * 32;
        #pragma unroll
        for (int ko = 0; ko < 4; ko++) {
            const uint32_t o = (uint32_t)ko * 2048 + rowb;
            cp16(sb + o,        pH + gk + ko*8);
            cp16(sb + 8192 + o, pL + gk + ko*8);
        }
        cp_commit();
    };

    const int wid  = tid >> 5;
    const int lane = tid & 31;
    const int wm = (wid >> 1) * 32;
    const int wn = (wid & 1) * 64;
    const int a_row = lane & 15;
    const int a_ko  = lane >> 4;
    const int b_row = (lane & 7) + ((lane & 16) >> 1);
    const int b_ko  = (lane >> 3) & 1;

    const uint32_t aoff = (uint32_t)((a_ko*1024 + (wm + a_row)*8) * 2);
    const uint32_t boff = (uint32_t)(16384 + (b_ko*1024 + (wn + b_row)*8) * 2);

    float acc[2][8][4];
    #pragma unroll
    for (int i = 0; i < 2; i++)
        #pragma unroll
        for (int j = 0; j < 8; j++)
            #pragma unroll
            for (int e = 0; e < 4; e++) acc[i][j][e] = 0.f;

    const int T = Ksub >> 5;

    load_stage(0, 0);
    if (T > 1) load_stage(1, 1);

    for (int kt = 0; kt < T; kt++) {
        if (kt + 1 < T) cp_wait1(); else cp_wait0();
        __syncthreads();
        if (kt + 2 < T) load_stage(kt + 2, (kt + 2) % 3);

        const uint32_t sb = smem_u32 + (uint32_t)(kt % 3) * STAGE_BYTES;
        #pragma unroll
        for (int ko0 = 0; ko0 < 4; ko0 += 2) {
            uint32_t a_h[2][4], a_l[2][4];
            #pragma unroll
            for (int mf = 0; mf < 2; mf++) {
                const uint32_t ad = sb + aoff + (uint32_t)ko0*2048 + (uint32_t)mf*256;
                ldsm4(a_h[mf], ad);
                ldsm4(a_l[mf], ad + 8192);
            }
            // register double-buffer for B fragments
            uint32_t b_h[2][4], b_l[2][4];
            {
                const uint32_t bd0 = sb + boff + (uint32_t)ko0*2048;
                ldsm4(b_h[0], bd0);
                ldsm4(b_l[0], bd0 + 8192);
            }
            #pragma unroll
            for (int nf2 = 0; nf2 < 4; nf2++) {
                const int cur = nf2 & 1;
                const int nxt = cur ^ 1;
                if (nf2 < 3) {
                    const uint32_t bdn = sb + boff + (uint32_t)ko0*2048
                                       + (uint32_t)(nf2+1)*256;
                    ldsm4(b_h[nxt], bdn);
                    ldsm4(b_l[nxt], bdn + 8192);
                }
                const int nf = nf2 * 2;
                // term hh across the 4 independent accumulators
                mma16816(acc[0][nf],   a_h[0], b_h[cur][0], b_h[cur][1]);
                mma16816(acc[0][nf+1], a_h[0], b_h[cur][2], b_h[cur][3]);
                mma16816(acc[1][nf],   a_h[1], b_h[cur][0], b_h[cur][1]);
                mma16816(acc[1][nf+1], a_h[1], b_h[cur][2], b_h[cur][3]);
                // term hl
                mma16816(acc[0][nf],   a_h[0], b_l[cur][0], b_l[cur][1]);
                mma16816(acc[0][nf+1], a_h[0], b_l[cur][2], b_l[cur][3]);
                mma16816(acc[1][nf],   a_h[1], b_l[cur][0], b_l[cur][1]);
                mma16816(acc[1][nf+1], a_h[1], b_l[cur][2], b_l[cur][3]);
                // term lh
                mma16816(acc[0][nf],   a_l[0], b_h[cur][0], b_h[cur][1]);
                mma16816(acc[0][nf+1], a_l[0], b_h[cur][2], b_h[cur][3]);
                mma16816(acc[1][nf],   a_l[1], b_h[cur][0], b_h[cur][1]);
                mma16816(acc[1][nf+1], a_l[1], b_h[cur][2], b_h[cur][3]);
            }
        }
    }

    // ---- epilogue ----
    const int er = lane >> 2;
    const int ec = (lane & 3) * 2;
    if (PARTIAL) {
        float* dst = Part + (size_t)z * M * N;
        #pragma unroll
        for (int mf = 0; mf < 2; mf++)
            #pragma unroll
            for (int nf = 0; nf < 8; nf++) {
                const int m = m0 + wm + mf*16 + er;
                const int n = n0 + wn + nf*8 + ec;
                #pragma unroll
                for (int half = 0; half < 2; half++) {
                    const int mm = m + half*8;
                    *(float2*)(dst + (size_t)mm * N + n) =
                        make_float2(acc[mf][nf][half*2+0], acc[mf][nf][half*2+1]);
                }
            }
        return;
    }

    #pragma unroll
    for (int mf = 0; mf < 2; mf++) {
        #pragma unroll
        for (int nf = 0; nf < 8; nf++) {
            const int m = m0 + wm + mf*16 + er;
            const int n = n0 + wn + nf*8 + ec;
            const float2 bv = *(const float2*)(bias + n);
            #pragma unroll
            for (int half = 0; half < 2; half++) {
                const int mm = m + half*8;
                float t0 = acc[mf][nf][half*2+0] + bv.x;
                float t1 = acc[mf][nf][half*2+1] + bv.y;
                if (EPI == 1) {
                    t0 = 0.5f * t0 * (1.f + erff(t0 * 0.70710678118654752f));
                    t1 = 0.5f * t1 * (1.f + erff(t1 * 0.70710678118654752f));
                }
                if (EPI == 2) {
                    const float2 rv = *(const float2*)(Res + (size_t)mm * N + n);
                    t0 += rv.x; t1 += rv.y;
                }
                if (OF32) {
                    *(float2*)(C + (size_t)mm * N + n) = make_float2(t0, t1);
                }
                if (OSPLIT) {
                    __nv_bfloat16 h0,h1,l0,l1;
                    split1(t0,h0,l0); split1(t1,h1,l1);
                    *(uint32_t*)(Chi + (size_t)mm * N + n) = pack2(h0,h1);
                    *(uint32_t*)(Clo + (size_t)mm * N + n) = pack2(l0,l1);
                }
            }
        }
    }
}

// ---------------------------------------------------------------------------
// Split-K reduce + epilogue. N fixed at DDIM.
// ---------------------------------------------------------------------------
template<int EPI, bool OSPLIT, bool OF32, int S>
__global__ __launch_bounds__(256)
void epi_reduce(const float* __restrict__ Part, const float* __restrict__ bias,
                const float* __restrict__ Res, float* __restrict__ C,
                __nv_bfloat16* __restrict__ Chi, __nv_bfloat16* __restrict__ Clo)
{
    const size_t i = (size_t)blockIdx.x * 1024 + threadIdx.x * 4;
    const int n = (int)(i & (DDIM - 1));
    float4 t = *(const float4*)(Part + i);
    #pragma unroll
    for (int s = 1; s < S; s++) {
        const float4 p = *(const float4*)(Part + (size_t)s * (NTOK*DDIM) + i);
        t.x += p.x; t.y += p.y; t.z += p.z; t.w += p.w;
    }
    const float4 bv = *(const float4*)(bias + n);
    t.x += bv.x; t.y += bv.y; t.z += bv.z; t.w += bv.w;
    if (EPI == 1) {
        t.x = 0.5f * t.x * (1.f + erff(t.x * 0.70710678118654752f));
        t.y = 0.5f * t.y * (1.f + erff(t.y * 0.70710678118654752f));
        t.z = 0.5f * t.z * (1.f + erff(t.z * 0.70710678118654752f));
        t.w = 0.5f * t.w * (1.f + erff(t.w * 0.70710678118654752f));
    }
    if (EPI == 2) {
        const float4 rv = *(const float4*)(Res + i);
        t.x += rv.x; t.y += rv.y; t.z += rv.z; t.w += rv.w;
    }
    if (OF32) *(float4*)(C + i) = t;
    if (OSPLIT) {
        __nv_bfloat16 h0,h1,h2,h3,l0,l1,l2,l3;
        split1(t.x,h0,l0); split1(t.y,h1,l1); split1(t.z,h2,l2); split1(t.w,h3,l3);
        uint2 uh; uh.x = pack2(h0,h1); uh.y = pack2(h2,h3);
        uint2 ul; ul.x = pack2(l0,l1); ul.y = pack2(l2,l3);
        *(uint2*)(Chi + i) = uh;
        *(uint2*)(Clo + i) = ul;
    }
}

// ---------------------------------------------------------------------------
// Tensor-core full attention (bf16x3 flash) — unchanged from round 12.
// ---------------------------------------------------------------------------
#define ATTN_TC_SMEM 65536

__global__ __launch_bounds__(128, 3)
void attn_tc_kernel(const __nv_bfloat16* __restrict__ qkvh,
                    const __nv_bfloat16* __restrict__ qkvl,
                    __nv_bfloat16* __restrict__ oh,
                    __nv_bfloat16* __restrict__ ol)
{
    extern __shared__ char smc[];
    const uint32_t sb = (uint32_t)__cvta_generic_to_shared(smc);

    const int bh = blockIdx.x;
    const int b  = bh >> 4;
    const int h  = bh & 15;
    const int qt = blockIdx.y;
    const int tid  = threadIdx.x;
    const int wid  = tid >> 5;
    const int lane = tid & 31;

    const int r    = tid >> 1;
    const int koh  = (tid & 1) * 4;

    {
        const size_t qrow = (size_t)(b*SLEN + qt*64 + r) * D3 + h*HD;
        #pragma unroll
        for (int it = 0; it < 4; it++) {
            const int ko = koh + it;
            const uint32_t dst = sb + (uint32_t)(((ko*64 + r)*8) * 2);
            cp16(dst,        qkvh + qrow + ko*8);
            cp16(dst + 8192, qkvl + qrow + ko*8);
        }
        cp_commit();
    }

    const int a_row = lane & 15;
    const int a_ko  = lane >> 4;
    const int b_row = (lane & 7) + ((lane & 16) >> 1);
    const int b_ko  = (lane >> 3) & 1;
    const int v_key = lane & 15;
    const int v_ko  = lane >> 4;

    uint32_t qa_h[4][4], qa_l[4][4];

    cp_wait0();
    __syncthreads();
    #pragma unroll
    for (int ks = 0; ks < 4; ks++) {
        const uint32_t ad = sb +
            (uint32_t)((((ks*2 + a_ko)*64 + wid*16 + a_row)*8) * 2);
        ldsm4(qa_h[ks], ad);
        ldsm4(qa_l[ks], ad + 8192);
    }
    __syncthreads();

    auto load_kv = [&](int kt, int s) {
        const uint32_t stg = sb + (uint32_t)s * 32768;
        const size_t krow = (size_t)(b*SLEN + kt*64 + r) * D3 + DDIM + h*HD;
        const size_t vrow = krow + DDIM;
        #pragma unroll
        for (int it = 0; it < 4; it++) {
            const int ko = koh + it;
            const uint32_t off = (uint32_t)(((ko*64 + r)*8) * 2);
            cp16(stg + off,          qkvh + krow + ko*8);
            cp16(stg + 8192  + off,  qkvl + krow + ko*8);
            cp16(stg + 16384 + off,  qkvh + vrow + ko*8);
            cp16(stg + 24576 + off,  qkvl + vrow + ko*8);
        }
    };

    load_kv(0, 0);
    cp_commit();

    float m0 = -1e30f, m1 = -1e30f, l0 = 0.f, l1 = 0.f;
    float oacc[8][4];
    #pragma unroll
    for (int nf = 0; nf < 8; nf++)
        #pragma unroll
        for (int e = 0; e < 4; e++) oacc[nf][e] = 0.f;

    for (int kt = 0; kt < 16; kt++) {
        const int s = kt & 1;
        if (kt + 1 < 16) {
            load_kv(kt + 1, s ^ 1);
            cp_commit();
            cp_wait1();
        } else {
            cp_wait0();
        }
        __syncthreads();

        const uint32_t stg = sb + (uint32_t)s * 32768;

        float sc[8][4];
        #pragma unroll
        for (int nf = 0; nf < 8; nf++)
            #pragma unroll
            for (int e = 0; e < 4; e++) sc[nf][e] = 0.f;

        #pragma unroll
        for (int ks = 0; ks < 4; ks++) {
            #pragma unroll
            for (int np = 0; np < 4; np++) {
                uint32_t kb[4], kl[4];
                const uint32_t kd = stg +
                    (uint32_t)((((ks*2 + b_ko)*64 + np*16 + b_row)*8) * 2);
                ldsm4(kb, kd);
                ldsm4(kl, kd + 8192);
                mma16816(sc[2*np],   qa_h[ks], kb[0], kb[1]);
                mma16816(sc[2*np+1], qa_h[ks], kb[2], kb[3]);
                mma16816(sc[2*np],   qa_h[ks], kl[0], kl[1]);
                mma16816(sc[2*np+1], qa_h[ks], kl[2], kl[3]);
                mma16816(sc[2*np],   qa_l[ks], kb[0], kb[1]);
                mma16816(sc[2*np+1], qa_l[ks], kb[2], kb[3]);
            }
        }

        #pragma unroll
        for (int nf = 0; nf < 8; nf++)
            #pragma unroll
            for (int e = 0; e < 4; e++) sc[nf][e] *= 0.125f;

        float mx0 = m0, mx1 = m1;
        #pragma unroll
        for (int nf = 0; nf < 8; nf++) {
            mx0 = fmaxf(mx0, fmaxf(sc[nf][0], sc[nf][1]));
            mx1 = fmaxf(mx1, fmaxf(sc[nf][2], sc[nf][3]));
        }
        mx0 = fmaxf(mx0, __shfl_xor_sync(0xffffffffu, mx0, 1));
        mx0 = fmaxf(mx0, __shfl_xor_sync(0xffffffffu, mx0, 2));
        mx1 = fmaxf(mx1, __shfl_xor_sync(0xffffffffu, mx1, 1));
        mx1 = fmaxf(mx1, __shfl_xor_sync(0xffffffffu, mx1, 2));

        const float al0 = __expf(m0 - mx0);
        const float al1 = __expf(m1 - mx1);
        m0 = mx0; m1 = mx1;

        float s0 = 0.f, s1 = 0.f;
        uint32_t pah[4][4], pal[4][4];
        #pragma unroll
        for (int nf = 0; nf < 8; nf++) {
            const float p0 = __expf(sc[nf][0] - m0);
            const float p1 = __expf(sc[nf][1] - m0);
            const float p2 = __expf(sc[nf][2] - m1);
            const float p3 = __expf(sc[nf][3] - m1);
            s0 += p0 + p1;
            s1 += p2 + p3;
            __nv_bfloat16 h0,h1,h2,h3,lo0,lo1,lo2,lo3;
            split1(p0,h0,lo0); split1(p1,h1,lo1);
            split1(p2,h2,lo2); split1(p3,h3,lo3);
            const int ks = nf >> 1;
            const int hv = (nf & 1) * 2;
            pah[ks][hv+0] = pack2(h0, h1);
            pah[ks][hv+1] = pack2(h2, h3);
            pal[ks][hv+0] = pack2(lo0, lo1);
            pal[ks][hv+1] = pack2(lo2, lo3);
        }
        s0 += __shfl_xor_sync(0xffffffffu, s0, 1);
        s0 += __shfl_xor_sync(0xffffffffu, s0, 2);
        s1 += __shfl_xor_sync(0xffffffffu, s1, 1);
        s1 += __shfl_xor_sync(0xffffffffu, s1, 2);
        l0 = l0 * al0 + s0;
        l1 = l1 * al1 + s1;

        #pragma unroll
        for (int nf = 0; nf < 8; nf++) {
            oacc[nf][0] *= al0; oacc[nf][1] *= al0;
            oacc[nf][2] *= al1; oacc[nf][3] *= al1;
        }

        #pragma unroll
        for (int ks = 0; ks < 4; ks++) {
            #pragma unroll
            for (int np = 0; np < 4; np++) {
                uint32_t vb[4], vl[4];
                const uint32_t vd = stg + 16384 +
                    (uint32_t)((((np*2 + v_ko)*64 + ks*16 + v_key)*8) * 2);
                ldsm4t(vb, vd);
                ldsm4t(vl, vd + 8192);
                mma16816(oacc[2*np],   pah[ks], vb[0], vb[1]);
                mma16816(oacc[2*np+1], pah[ks], vb[2], vb[3]);
                mma16816(oacc[2*np],   pah[ks], vl[0], vl[1]);
                mma16816(oacc[2*np+1], pah[ks], vl[2], vl[3]);
                mma16816(oacc[2*np],   pal[ks], vb[0], vb[1]);
                mma16816(oacc[2*np+1], pal[ks], vb[2], vb[3]);
            }
        }
        __syncthreads();
    }

    const float inv0 = 1.f / l0;
    const float inv1 = 1.f / l1;
    const int er  = lane >> 2;
    const int ec  = (lane & 3) * 2;
    const int tok0 = b*SLEN + qt*64 + wid*16 + er;
    const int tok1 = tok0 + 8;
    #pragma unroll
    for (int nf = 0; nf < 8; nf++) {
        const int col = h*HD + nf*8 + ec;
        const float o0 = oacc[nf][0] * inv0;
        const float o1 = oacc[nf][1] * inv0;
        const float o2 = oacc[nf][2] * inv1;
        const float o3 = oacc[nf][3] * inv1;
        __nv_bfloat16 h0,h1,h2,h3,lo0,lo1,lo2,lo3;
        split1(o0,h0,lo0); split1(o1,h1,lo1);
        split1(o2,h2,lo2); split1(o3,h3,lo3);
        *(uint32_t*)(oh + (size_t)tok0 * DDIM + col) = pack2(h0, h1);
        *(uint32_t*)(ol + (size_t)tok0 * DDIM + col) = pack2(lo0, lo1);
        *(uint32_t*)(oh + (size_t)tok1 * DDIM + col) = pack2(h2, h3);
        *(uint32_t*)(ol + (size_t)tok1 * DDIM + col) = pack2(lo2, lo3);
    }
}

// ---------------------------------------------------------------------------
// Banded attention — unchanged.
// ---------------------------------------------------------------------------
__global__ __launch_bounds__(256)
void attn_band_kernel(const __nv_bfloat16* __restrict__ qkvh,
                      const __nv_bfloat16* __restrict__ qkvl,
                      __nv_bfloat16* __restrict__ oh,
                      __nv_bfloat16* __restrict__ ol)
{
    const int gw   = (blockIdx.x * blockDim.x + threadIdx.x) >> 5;
    const int lane = threadIdx.x & 31;
    const int i = gw & (SLEN-1);
    const int h = (gw >> 10) & (HNUM-1);
    const int b = gw >> 14;

    const size_t qbase = (size_t)(b*SLEN + i) * D3 + h*HD;
    const float q0 = bf2f(qkvh[qbase + lane])      + bf2f(qkvl[qbase + lane]);
    const float q1 = bf2f(qkvh[qbase + 32 + lane]) + bf2f(qkvl[qbase + 32 + lane]);

    float sc[5];
    int   jc[5];
    #pragma unroll
    for (int jj = 0; jj < 5; jj++) {
        int j = i - 2 + jj;
        bool valid = (j >= 0) && (j < SLEN);
        jc[jj] = valid ? j : i;
        const size_t kb = (size_t)(b*SLEN + jc[jj]) * D3 + DDIM + h*HD;
        const float k0 = bf2f(qkvh[kb + lane])      + bf2f(qkvl[kb + lane]);
        const float k1 = bf2f(qkvh[kb + 32 + lane]) + bf2f(qkvl[kb + 32 + lane]);
        float p = q0 * k0 + q1 * k1;
        #pragma unroll
        for (int off = 16; off; off >>= 1) p += __shfl_xor_sync(0xffffffffu, p, off);
        sc[jj] = valid ? p * 0.125f : -1e30f;
    }
    float mx = sc[0];
    #pragma unroll
    for (int jj = 1; jj < 5; jj++) mx = fmaxf(mx, sc[jj]);
    float w[5], sum = 0.f;
    #pragma unroll
    for (int jj = 0; jj < 5; jj++) { w[jj] = __expf(sc[jj] - mx); sum += w[jj]; }
    const float inv = 1.f / sum;

    float o0 = 0.f, o1 = 0.f;
    #pragma unroll
    for (int jj = 0; jj < 5; jj++) {
        const size_t vb = (size_t)(b*SLEN + jc[jj]) * D3 + 2*DDIM + h*HD;
        const float v0 = bf2f(qkvh[vb + lane])      + bf2f(qkvl[vb + lane]);
        const float v1 = bf2f(qkvh[vb + 32 + lane]) + bf2f(qkvl[vb + 32 + lane]);
        o0 = fmaf(w[jj], v0, o0);
        o1 = fmaf(w[jj], v1, o1);
    }
    o0 *= inv; o1 *= inv;

    const size_t ob = (size_t)(b*SLEN + i) * DDIM + h*HD;
    __nv_bfloat16 hh, ll;
    split1(o0, hh, ll);
    oh[ob + lane] = hh;  ol[ob + lane] = ll;
    split1(o1, hh, ll);
    oh[ob + 32 + lane] = hh;  ol[ob + 32 + lane] = ll;
}

// ---------------------------------------------------------------------------
// LayerNorm — unchanged.
// ---------------------------------------------------------------------------
__global__ __launch_bounds__(256)
void ln_kernel(const float* __restrict__ a, const float* __restrict__ r,
               const float* __restrict__ g, const float* __restrict__ bt,
               float* __restrict__ out,
               __nv_bfloat16* __restrict__ ohh, __nv_bfloat16* __restrict__ oll)
{
    __shared__ float red[2][8];
    __shared__ float s_mean, s_rstd;
    const int n = blockIdx.x;
    const int tid = threadIdx.x;
    const size_t base = (size_t)n * DDIM + tid * 4;

    float4 va = *(const float4*)(a + base);
    if (r) {
        float4 vr = *(const float4*)(r + base);
        va.x += vr.x; va.y += vr.y; va.z += vr.z; va.w += vr.w;
    }
    float s  = va.x + va.y + va.z + va.w;
    float sq = va.x*va.x + va.y*va.y + va.z*va.z + va.w*va.w;

    #pragma unroll
    for (int off = 16; off; off >>= 1) {
        s  += __shfl_xor_sync(0xffffffffu, s,  off);
        sq += __shfl_xor_sync(0xffffffffu, sq, off);
    }
    const int wid = tid >> 5;
    if ((tid & 31) == 0) { red[0][wid] = s; red[1][wid] = sq; }
    __syncthreads();
    if (tid < 32) {
        float ts  = (tid < 8) ? red[0][tid] : 0.f;
        float tsq = (tid < 8) ? red[1][tid] : 0.f;
        #pragma unroll
        for (int off = 4; off; off >>= 1) {
            ts  += __shfl_xor_sync(0xffffffffu, ts,  off);
            tsq += __shfl_xor_sync(0xffffffffu, tsq, off);
        }
        if (tid == 0) {
            float mean = ts * (1.f / DDIM);
            float var  = tsq * (1.f / DDIM) - mean * mean;
            s_mean = mean;
            s_rstd = rsqrtf(var + EPS);
        }
    }
    __syncthreads();
    const float mean = s_mean, rstd = s_rstd;
    float4 gg = *(const float4*)(g + tid*4);
    float4 bb = *(const float4*)(bt + tid*4);
    float4 o;
    o.x = (va.x - mean) * rstd * gg.x + bb.x;
    o.y = (va.y - mean) * rstd * gg.y + bb.y;
    o.z = (va.z - mean) * rstd * gg.z + bb.z;
    o.w = (va.w - mean) * rstd * gg.w + bb.w;
    *(float4*)(out + base) = o;
    if (ohh) {
        __nv_bfloat16 h0,h1,h2,h3,l0,l1,l2,l3;
        split1(o.x,h0,l0); split1(o.y,h1,l1); split1(o.z,h2,l2); split1(o.w,h3,l3);
        uint2 uh; uh.x = pack2(h0,h1); uh.y = pack2(h2,h3);
        uint2 ul; ul.x = pack2(l0,l1); ul.y = pack2(l2,l3);
        *(uint2*)(ohh + base) = uh;
        *(uint2*)(oll + base) = ul;
    }
}

// ---------------------------------------------------------------------------
// Orchestration
// ---------------------------------------------------------------------------
extern "C" void kernel_launch(void* const* d_in, const int* in_sizes, int n_in,
                              void* d_out, int out_size)
{
    const float* x_in   = (const float*)d_in[0];
    const float* w_in1  = (const float*)d_in[1];
    const float* b_in1  = (const float*)d_in[2];
    const float* w_out1 = (const float*)d_in[3];
    const float* b_out1 = (const float*)d_in[4];
    const float* ln1_g  = (const float*)d_in[5];
    const float* ln1_b  = (const float*)d_in[6];
    const float* w_in2  = (const float*)d_in[7];
    const float* b_in2  = (const float*)d_in[8];
    const float* w_out2 = (const float*)d_in[9];
    const float* b_out2 = (const float*)d_in[10];
    const float* ln2_g  = (const float*)d_in[11];
    const float* ln2_b  = (const float*)d_in[12];
    const float* ffn_w1 = (const float*)d_in[13];
    const float* ffn_b1 = (const float*)d_in[14];
    const float* ffn_w2 = (const float*)d_in[15];
    const float* ffn_b2 = (const float*)d_in[16];
    const float* lnf_g  = (const float*)d_in[17];
    const float* lnf_b  = (const float*)d_in[18];

    float *PROJ, *X, *X2, *ATT, *PART;
    __nv_bfloat16 *WH, *WL, *QKVH, *QKVL, *P1H, *P1L, *P2H, *P2L;
    cudaGetSymbolAddress((void**)&PROJ, g_proj);
    cudaGetSymbolAddress((void**)&X,    g_x);
    cudaGetSymbolAddress((void**)&X2,   g_x2);
    cudaGetSymbolAddress((void**)&ATT,  g_att);
    cudaGetSymbolAddress((void**)&PART, g_part);
    cudaGetSymbolAddress((void**)&WH,   g_wh);
    cudaGetSymbolAddress((void**)&WL,   g_wl);
    cudaGetSymbolAddress((void**)&QKVH, g_qkvh);
    cudaGetSymbolAddress((void**)&QKVL, g_qkvl);
    cudaGetSymbolAddress((void**)&P1H,  g_p1h);
    cudaGetSymbolAddress((void**)&P1L,  g_p1l);
    cudaGetSymbolAddress((void**)&P2H,  g_p2h);
    cudaGetSymbolAddress((void**)&P2L,  g_p2l);

    cudaFuncSetAttribute(attn_tc_kernel,
                         cudaFuncAttributeMaxDynamicSharedMemorySize, ATTN_TC_SMEM);
    cudaFuncSetAttribute(gemm_bf3<0,true,false,false>,
                         cudaFuncAttributeMaxDynamicSharedMemorySize, GSMEM_BYTES);
    cudaFuncSetAttribute(gemm_bf3<1,true,false,false>,
                         cudaFuncAttributeMaxDynamicSharedMemorySize, GSMEM_BYTES);
    cudaFuncSetAttribute(gemm_bf3<0,false,false,true>,
                         cudaFuncAttributeMaxDynamicSharedMemorySize, GSMEM_BYTES);

    const dim3 blk(256);
    const dim3 gblk(256);
    const dim3 g_qkvp(D3/128,  NTOK/128);        // (24,16)
    const dim3 g_outp(DDIM/128, NTOK/128, 2);    // (8,16,2)  split-K 2
    const dim3 g_ffn1(MDIM/128, NTOK/128);       // (32,16)
    const dim3 g_ffn2(DDIM/128, NTOK/128, 4);    // (8,16,4)  split-K 4
    const dim3 g_attn(BNUM*HNUM, SLEN/64);       // (32,16)
    const int  g_band = (BNUM*HNUM*SLEN*32) / 256;
    const int  g_ln   = NTOK;
    const int  g_red  = (NTOK*DDIM) / 1024;      // 2048

    // ---- single merged split launch: all 6 weights + layer-0 input ----
    split_all_kernel<<<SPLIT_TOTAL_BLOCKS, blk>>>(
        w_in1, w_out1, w_in2, w_out2, ffn_w1, ffn_w2, x_in,
        WH, WL, P1H, P1L);

    const float* xcur = x_in;
    for (int l = 0; l < LNUM; l++) {
        const size_t oW3 = (size_t)l * D3 * DDIM;
        const size_t oW1 = (size_t)l * DDIM * DDIM;
        const size_t oWm = (size_t)l * MDIM * DDIM;

        // ---- intra-frame full MHA ----
        gemm_bf3<0,true,false,false><<<g_qkvp, gblk, GSMEM_BYTES>>>(
            P1H, P1L, WH+W_IN1_OFF+oW3, WL+W_IN1_OFF+oW3,
            b_in1 + (size_t)l*D3, nullptr, nullptr, QKVH, QKVL, nullptr,
            NTOK, D3, DDIM);
        attn_tc_kernel<<<g_attn, 128, ATTN_TC_SMEM>>>(QKVH, QKVL, P1H, P1L);
        gemm_bf3<0,false,false,true><<<g_outp, gblk, GSMEM_BYTES>>>(
            P1H, P1L, WH+W_OUT1_OFF+oW1, WL+W_OUT1_OFF+oW1,
            nullptr, nullptr, nullptr, nullptr, nullptr, PART,
            NTOK, DDIM, DDIM);
        epi_reduce<0,false,true,2><<<g_red, blk>>>(
            PART, b_out1 + (size_t)l*DDIM, nullptr, PROJ, nullptr, nullptr);
        ln_kernel<<<g_ln, blk>>>(PROJ, xcur, ln1_g + (size_t)l*DDIM,
                                 ln1_b + (size_t)l*DDIM, X2, P1H, P1L);

        // ---- inter-frame banded MHA ----
        gemm_bf3<0,true,false,false><<<g_qkvp, gblk, GSMEM_BYTES>>>(
            P1H, P1L, WH+W_IN2_OFF+oW3, WL+W_IN2_OFF+oW3,
            b_in2 + (size_t)l*D3, nullptr, nullptr, QKVH, QKVL, nullptr,
            NTOK, D3, DDIM);
        attn_band_kernel<<<g_band, blk>>>(QKVH, QKVL, P1H, P1L);
        gemm_bf3<0,false,false,true><<<g_outp, gblk, GSMEM_BYTES>>>(
            P1H, P1L, WH+W_OUT2_OFF+oW1, WL+W_OUT2_OFF+oW1,
            nullptr, nullptr, nullptr, nullptr, nullptr, PART,
            NTOK, DDIM, DDIM);
        epi_reduce<0,false,true,2><<<g_red, blk>>>(
            PART, b_out2 + (size_t)l*DDIM, nullptr, PROJ, nullptr, nullptr);
        ln_kernel<<<g_ln, blk>>>(PROJ, X2, ln2_g + (size_t)l*DDIM,
                                 ln2_b + (size_t)l*DDIM, ATT, P1H, P1L);

        // ---- FFN ----
        gemm_bf3<1,true,false,false><<<g_ffn1, gblk, GSMEM_BYTES>>>(
            P1H, P1L, WH+FW1_OFF+oWm, WL+FW1_OFF+oWm,
            ffn_b1 + (size_t)l*MDIM, nullptr, nullptr, P2H, P2L, nullptr,
            NTOK, MDIM, DDIM);
        gemm_bf3<0,false,false,true><<<g_ffn2, gblk, GSMEM_BYTES>>>(
            P2H, P2L, WH+FW2_OFF+oWm, WL+FW2_OFF+oWm,
            nullptr, nullptr, nullptr, nullptr, nullptr, PART,
            NTOK, DDIM, MDIM);
        epi_reduce<2,true,true,4><<<g_red, blk>>>(
            PART, ffn_b2 + (size_t)l*DDIM, ATT, X, P1H, P1L);
        xcur = X;
    }

    ln_kernel<<<g_ln, blk>>>(xcur, nullptr, lnf_g, lnf_b, (float*)d_out,
                             nullptr, nullptr);
}

// round 14
// speedup vs baseline: 1.8966x; 1.0072x over previous
#include <cuda_runtime.h>
#include <cuda_bf16.h>
#include <math.h>
#include <stdint.h>

// ---------------------------------------------------------------------------
// Problem constants
// ---------------------------------------------------------------------------
#define LNUM 4
#define DDIM 1024
#define HNUM 16
#define HD   64
#define MDIM 4096
#define SLEN 1024
#define BNUM 2
#define NTOK (BNUM*SLEN)        // 2048
#define D3   (3*DDIM)           // 3072
#define EPS  1e-5f

// Weight split array layout (element offsets)
#define W_IN1_OFF   0u
#define W_OUT1_OFF  12582912u
#define W_IN2_OFF   16777216u
#define W_OUT2_OFF  29360128u
#define FW1_OFF     33554432u
#define FW2_OFF     50331648u
#define WTOTAL      67108864u

// ---------------------------------------------------------------------------
// Device scratch (no allocations allowed)
// ---------------------------------------------------------------------------
static __device__ float g_x   [NTOK*DDIM];
static __device__ float g_x2  [NTOK*DDIM];
static __device__ float g_att [NTOK*DDIM];
static __device__ float g_part[4u*NTOK*DDIM];        // split-K partials (32MB)

static __device__ __nv_bfloat16 g_wh[WTOTAL];        // weight hi
static __device__ __nv_bfloat16 g_wl[WTOTAL];        // weight lo
static __device__ __nv_bfloat16 g_qkvh[NTOK*D3];     // qkv hi
static __device__ __nv_bfloat16 g_qkvl[NTOK*D3];     // qkv lo
static __device__ __nv_bfloat16 g_p1h[NTOK*DDIM];
static __device__ __nv_bfloat16 g_p1l[NTOK*DDIM];
static __device__ __nv_bfloat16 g_p2h[NTOK*MDIM];
static __device__ __nv_bfloat16 g_p2l[NTOK*MDIM];

// ---------------------------------------------------------------------------
// Helpers
// ---------------------------------------------------------------------------
__device__ __forceinline__ void cp16(uint32_t d, const void* s) {
    asm volatile("cp.async.cg.shared.global [%0], [%1], 16;\n" :: "r"(d), "l"(s));
}
__device__ __forceinline__ void cp_commit() {
    asm volatile("cp.async.commit_group;\n" ::: "memory");
}
__device__ __forceinline__ void cp_wait1() {
    asm volatile("cp.async.wait_group 1;\n" ::: "memory");
}
__device__ __forceinline__ void cp_wait0() {
    asm volatile("cp.async.wait_group 0;\n" ::: "memory");
}
__device__ __forceinline__ void ldsm4(uint32_t* r, uint32_t a) {
    asm volatile("ldmatrix.sync.aligned.m8n8.x4.shared.b16 {%0,%1,%2,%3}, [%4];"
        : "=r"(r[0]), "=r"(r[1]), "=r"(r[2]), "=r"(r[3]) : "r"(a));
}
__device__ __forceinline__ void ldsm4t(uint32_t* r, uint32_t a) {
    asm volatile("ldmatrix.sync.aligned.m8n8.x4.trans.shared.b16 {%0,%1,%2,%3}, [%4];"
        : "=r"(r[0]), "=r"(r[1]), "=r"(r[2]), "=r"(r[3]) : "r"(a));
}
// Non-volatile: pure register computation; deps carried by constraints.
__device__ __forceinline__ void mma16816(float* c, const uint32_t* a,
                                         uint32_t b0, uint32_t b1) {
    asm("mma.sync.aligned.m16n8k16.row.col.f32.bf16.bf16.f32 "
        "{%0,%1,%2,%3},{%4,%5,%6,%7},{%8,%9},{%0,%1,%2,%3};"
        : "+f"(c[0]), "+f"(c[1]), "+f"(c[2]), "+f"(c[3])
        : "r"(a[0]), "r"(a[1]), "r"(a[2]), "r"(a[3]), "r"(b0), "r"(b1));
}
__device__ __forceinline__ uint32_t pack2(__nv_bfloat16 a, __nv_bfloat16 b) {
    __nv_bfloat162 t = __halves2bfloat162(a, b);
    return *reinterpret_cast<uint32_t*>(&t);
}
__device__ __forceinline__ void split1(float v, __nv_bfloat16& h, __nv_bfloat16& l) {
    h = __float2bfloat16(v);
    l = __float2bfloat16(v - __bfloat162float(h));
}
__device__ __forceinline__ float bf2f(__nv_bfloat16 v) { return __bfloat162float(v); }

// ---------------------------------------------------------------------------
// Merged fp32 -> (hi,lo) bf16 split for all 6 weight tensors + x_in.
// ---------------------------------------------------------------------------
#define SPLIT_TOTAL_BLOCKS 16896

__global__ __launch_bounds__(256)
void split_all_kernel(const float* __restrict__ w_in1, const float* __restrict__ w_out1,
                      const float* __restrict__ w_in2, const float* __restrict__ w_out2,
                      const float* __restrict__ fw1,  const float* __restrict__ fw2,
                      const float* __restrict__ x,
                      __nv_bfloat16* __restrict__ WH, __nv_bfloat16* __restrict__ WL,
                      __nv_bfloat16* __restrict__ P1H, __nv_bfloat16* __restrict__ P1L)
{
    const int bid = blockIdx.x;
    const float* src;
    __nv_bfloat16 *dh, *dl;
    int rb;
    if (bid < 3072)       { src = w_in1;  dh = WH + W_IN1_OFF;  dl = WL + W_IN1_OFF;  rb = bid; }
    else if (bid < 4096)  { src = w_out1; dh = WH + W_OUT1_OFF; dl = WL + W_OUT1_OFF; rb = bid - 3072; }
    else if (bid < 7168)  { src = w_in2;  dh = WH + W_IN2_OFF;  dl = WL + W_IN2_OFF;  rb = bid - 4096; }
    else if (bid < 8192)  { src = w_out2; dh = WH + W_OUT2_OFF; dl = WL + W_OUT2_OFF; rb = bid - 7168; }
    else if (bid < 12288) { src = fw1;    dh = WH + FW1_OFF;    dl = WL + FW1_OFF;    rb = bid - 8192; }
    else if (bid < 16384) { src = fw2;    dh = WH + FW2_OFF;    dl = WL + FW2_OFF;    rb = bid - 12288; }
    else                  { src = x;      dh = P1H;             dl = P1L;             rb = bid - 16384; }

    const size_t base = (size_t)rb * 4096 + threadIdx.x * 4;
    #pragma unroll
    for (int j = 0; j < 4; j++) {
        const size_t i = base + j * 1024;
        float4 v = *(const float4*)(src + i);
        __nv_bfloat16 h0,h1,h2,h3,l0,l1,l2,l3;
        split1(v.x,h0,l0); split1(v.y,h1,l1); split1(v.z,h2,l2); split1(v.w,h3,l3);
        uint2 uh; uh.x = pack2(h0,h1); uh.y = pack2(h2,h3);
        uint2 ul; ul.x = pack2(l0,l1); ul.y = pack2(l2,l3);
        *(uint2*)(dh + i) = uh;
        *(uint2*)(dl + i) = ul;
    }
}

// ---------------------------------------------------------------------------
// bf16x3 tensor-core GEMM — unchanged from round 13 (known good).
// ---------------------------------------------------------------------------
#define STAGE_BYTES 32768
#define GSMEM_BYTES (3*STAGE_BYTES)

template<int EPI, bool OSPLIT, bool OF32, bool PARTIAL>
__global__ __launch_bounds__(256, 2)
void gemm_bf3(const __nv_bfloat16* __restrict__ Ah, const __nv_bfloat16* __restrict__ Al,
              const __nv_bfloat16* __restrict__ Bh, const __nv_bfloat16* __restrict__ Bl,
              const float* __restrict__ bias, const float* __restrict__ Res,
              float* __restrict__ C, __nv_bfloat16* __restrict__ Chi,
              __nv_bfloat16* __restrict__ Clo, float* __restrict__ Part,
              int M, int N, int K)
{
    extern __shared__ __nv_bfloat16 smbuf[];
    const uint32_t smem_u32 = (uint32_t)__cvta_generic_to_shared(smbuf);

    const int tid = threadIdx.x;
    const int m0 = blockIdx.y * 128;
    const int n0 = blockIdx.x * 128;
    const int z  = blockIdx.z;
    const int Ksub = K / gridDim.z;

    const int lrow = tid & 127;
    const bool isB = tid >= 128;
    const size_t kofs = (size_t)z * Ksub;
    const __nv_bfloat16* pH = (isB ? Bh + (size_t)(n0 + lrow) * K
                                   : Ah + (size_t)(m0 + lrow) * K) + kofs;
    const __nv_bfloat16* pL = (isB ? Bl + (size_t)(n0 + lrow) * K
                                   : Al + (size_t)(m0 + lrow) * K) + kofs;
    const uint32_t regH = isB ? 16384u : 0u;
    const uint32_t rowb = (uint32_t)lrow * 16;

    auto load_stage = [&](int kt, int s) {
        const uint32_t sb = smem_u32 + (uint32_t)s * STAGE_BYTES + regH;
        const size_t gk = (size_t)kt * 32;
        #pragma unroll
        for (int ko = 0; ko < 4; ko++) {
            const uint32_t o = (uint32_t)ko * 2048 + rowb;
            cp16(sb + o,        pH + gk + ko*8);
            cp16(sb + 8192 + o, pL + gk + ko*8);
        }
        cp_commit();
    };

    const int wid  = tid >> 5;
    const int lane = tid & 31;
    const int wm = (wid >> 1) * 32;
    const int wn = (wid & 1) * 64;
    const int a_row = lane & 15;
    const int a_ko  = lane >> 4;
    const int b_row = (lane & 7) + ((lane & 16) >> 1);
    const int b_ko  = (lane >> 3) & 1;

    const uint32_t aoff = (uint32_t)((a_ko*1024 + (wm + a_row)*8) * 2);
    const uint32_t boff = (uint32_t)(16384 + (b_ko*1024 + (wn + b_row)*8) * 2);

    float acc[2][8][4];
    #pragma unroll
    for (int i = 0; i < 2; i++)
        #pragma unroll
        for (int j = 0; j < 8; j++)
            #pragma unroll
            for (int e = 0; e < 4; e++) acc[i][j][e] = 0.f;

    const int T = Ksub >> 5;

    load_stage(0, 0);
    if (T > 1) load_stage(1, 1);

    for (int kt = 0; kt < T; kt++) {
        if (kt + 1 < T) cp_wait1(); else cp_wait0();
        __syncthreads();
        if (kt + 2 < T) load_stage(kt + 2, (kt + 2) % 3);

        const uint32_t sb = smem_u32 + (uint32_t)(kt % 3) * STAGE_BYTES;
        #pragma unroll
        for (int ko0 = 0; ko0 < 4; ko0 += 2) {
            uint32_t a_h[2][4], a_l[2][4];
            #pragma unroll
            for (int mf = 0; mf < 2; mf++) {
                const uint32_t ad = sb + aoff + (uint32_t)ko0*2048 + (uint32_t)mf*256;
                ldsm4(a_h[mf], ad);
                ldsm4(a_l[mf], ad + 8192);
            }
            uint32_t b_h[2][4], b_l[2][4];
            {
                const uint32_t bd0 = sb + boff + (uint32_t)ko0*2048;
                ldsm4(b_h[0], bd0);
                ldsm4(b_l[0], bd0 + 8192);
            }
            #pragma unroll
            for (int nf2 = 0; nf2 < 4; nf2++) {
                const int cur = nf2 & 1;
                const int nxt = cur ^ 1;
                if (nf2 < 3) {
                    const uint32_t bdn = sb + boff + (uint32_t)ko0*2048
                                       + (uint32_t)(nf2+1)*256;
                    ldsm4(b_h[nxt], bdn);
                    ldsm4(b_l[nxt], bdn + 8192);
                }
                const int nf = nf2 * 2;
                mma16816(acc[0][nf],   a_h[0], b_h[cur][0], b_h[cur][1]);
                mma16816(acc[0][nf+1], a_h[0], b_h[cur][2], b_h[cur][3]);
                mma16816(acc[1][nf],   a_h[1], b_h[cur][0], b_h[cur][1]);
                mma16816(acc[1][nf+1], a_h[1], b_h[cur][2], b_h[cur][3]);
                mma16816(acc[0][nf],   a_h[0], b_l[cur][0], b_l[cur][1]);
                mma16816(acc[0][nf+1], a_h[0], b_l[cur][2], b_l[cur][3]);
                mma16816(acc[1][nf],   a_h[1], b_l[cur][0], b_l[cur][1]);
                mma16816(acc[1][nf+1], a_h[1], b_l[cur][2], b_l[cur][3]);
                mma16816(acc[0][nf],   a_l[0], b_h[cur][0], b_h[cur][1]);
                mma16816(acc[0][nf+1], a_l[0], b_h[cur][2], b_h[cur][3]);
                mma16816(acc[1][nf],   a_l[1], b_h[cur][0], b_h[cur][1]);
                mma16816(acc[1][nf+1], a_l[1], b_h[cur][2], b_h[cur][3]);
            }
        }
    }

    // ---- epilogue ----
    const int er = lane >> 2;
    const int ec = (lane & 3) * 2;
    if (PARTIAL) {
        float* dst = Part + (size_t)z * M * N;
        #pragma unroll
        for (int mf = 0; mf < 2; mf++)
            #pragma unroll
            for (int nf = 0; nf < 8; nf++) {
                const int m = m0 + wm + mf*16 + er;
                const int n = n0 + wn + nf*8 + ec;
                #pragma unroll
                for (int half = 0; half < 2; half++) {
                    const int mm = m + half*8;
                    *(float2*)(dst + (size_t)mm * N + n) =
                        make_float2(acc[mf][nf][half*2+0], acc[mf][nf][half*2+1]);
                }
            }
        return;
    }

    #pragma unroll
    for (int mf = 0; mf < 2; mf++) {
        #pragma unroll
        for (int nf = 0; nf < 8; nf++) {
            const int m = m0 + wm + mf*16 + er;
            const int n = n0 + wn + nf*8 + ec;
            const float2 bv = *(const float2*)(bias + n);
            #pragma unroll
            for (int half = 0; half < 2; half++) {
                const int mm = m + half*8;
                float t0 = acc[mf][nf][half*2+0] + bv.x;
                float t1 = acc[mf][nf][half*2+1] + bv.y;
                if (EPI == 1) {
                    t0 = 0.5f * t0 * (1.f + erff(t0 * 0.70710678118654752f));
                    t1 = 0.5f * t1 * (1.f + erff(t1 * 0.70710678118654752f));
                }
                if (EPI == 2) {
                    const float2 rv = *(const float2*)(Res + (size_t)mm * N + n);
                    t0 += rv.x; t1 += rv.y;
                }
                if (OF32) {
                    *(float2*)(C + (size_t)mm * N + n) = make_float2(t0, t1);
                }
                if (OSPLIT) {
                    __nv_bfloat16 h0,h1,l0,l1;
                    split1(t0,h0,l0); split1(t1,h1,l1);
                    *(uint32_t*)(Chi + (size_t)mm * N + n) = pack2(h0,h1);
                    *(uint32_t*)(Clo + (size_t)mm * N + n) = pack2(l0,l1);
                }
            }
        }
    }
}

// ---------------------------------------------------------------------------
// Split-K reduce + epilogue (no LN). N fixed at DDIM.
// ---------------------------------------------------------------------------
template<int EPI, bool OSPLIT, bool OF32, int S>
__global__ __launch_bounds__(256)
void epi_reduce(const float* __restrict__ Part, const float* __restrict__ bias,
                const float* __restrict__ Res, float* __restrict__ C,
                __nv_bfloat16* __restrict__ Chi, __nv_bfloat16* __restrict__ Clo)
{
    const size_t i = (size_t)blockIdx.x * 1024 + threadIdx.x * 4;
    const int n = (int)(i & (DDIM - 1));
    float4 t = *(const float4*)(Part + i);
    #pragma unroll
    for (int s = 1; s < S; s++) {
        const float4 p = *(const float4*)(Part + (size_t)s * (NTOK*DDIM) + i);
        t.x += p.x; t.y += p.y; t.z += p.z; t.w += p.w;
    }
    const float4 bv = *(const float4*)(bias + n);
    t.x += bv.x; t.y += bv.y; t.z += bv.z; t.w += bv.w;
    if (EPI == 1) {
        t.x = 0.5f * t.x * (1.f + erff(t.x * 0.70710678118654752f));
        t.y = 0.5f * t.y * (1.f + erff(t.y * 0.70710678118654752f));
        t.z = 0.5f * t.z * (1.f + erff(t.z * 0.70710678118654752f));
        t.w = 0.5f * t.w * (1.f + erff(t.w * 0.70710678118654752f));
    }
    if (EPI == 2) {
        const float4 rv = *(const float4*)(Res + i);
        t.x += rv.x; t.y += rv.y; t.z += rv.z; t.w += rv.w;
    }
    if (OF32) *(float4*)(C + i) = t;
    if (OSPLIT) {
        __nv_bfloat16 h0,h1,h2,h3,l0,l1,l2,l3;
        split1(t.x,h0,l0); split1(t.y,h1,l1); split1(t.z,h2,l2); split1(t.w,h3,l3);
        uint2 uh; uh.x = pack2(h0,h1); uh.y = pack2(h2,h3);
        uint2 ul; ul.x = pack2(l0,l1); ul.y = pack2(l2,l3);
        *(uint2*)(Chi + i) = uh;
        *(uint2*)(Clo + i) = ul;
    }
}

// ---------------------------------------------------------------------------
// FUSED split-K reduce + bias + residual + LayerNorm + split outputs.
// One block per token row (256 threads x 4 cols). Replaces
// epi_reduce<0,...> followed by ln_kernel for the out-proj paths.
// ---------------------------------------------------------------------------
template<int S>
__global__ __launch_bounds__(256)
void epi_ln_kernel(const float* __restrict__ Part, const float* __restrict__ bias,
                   const float* __restrict__ r,   const float* __restrict__ g,
                   const float* __restrict__ bt,  float* __restrict__ out,
                   __nv_bfloat16* __restrict__ ohh, __nv_bfloat16* __restrict__ oll)
{
    __shared__ float red[2][8];
    __shared__ float s_mean, s_rstd;
    const int tok = blockIdx.x;
    const int tid = threadIdx.x;
    const size_t base = (size_t)tok * DDIM + tid * 4;
    const int n = tid * 4;

    // reduce split-K partials + bias (same order as epi_reduce)
    float4 va = *(const float4*)(Part + base);
    #pragma unroll
    for (int s = 1; s < S; s++) {
        const float4 p = *(const float4*)(Part + (size_t)s * (NTOK*DDIM) + base);
        va.x += p.x; va.y += p.y; va.z += p.z; va.w += p.w;
    }
    const float4 bv = *(const float4*)(bias + n);
    va.x += bv.x; va.y += bv.y; va.z += bv.z; va.w += bv.w;

    // residual (same as ln_kernel's a + r)
    const float4 vr = *(const float4*)(r + base);
    va.x += vr.x; va.y += vr.y; va.z += vr.z; va.w += vr.w;

    float s  = va.x + va.y + va.z + va.w;
    float sq = va.x*va.x + va.y*va.y + va.z*va.z + va.w*va.w;

    #pragma unroll
    for (int off = 16; off; off >>= 1) {
        s  += __shfl_xor_sync(0xffffffffu, s,  off);
        sq += __shfl_xor_sync(0xffffffffu, sq, off);
    }
    const int wid = tid >> 5;
    if ((tid & 31) == 0) { red[0][wid] = s; red[1][wid] = sq; }
    __syncthreads();
    if (tid < 32) {
        float ts  = (tid < 8) ? red[0][tid] : 0.f;
        float tsq = (tid < 8) ? red[1][tid] : 0.f;
        #pragma unroll
        for (int off = 4; off; off >>= 1) {
            ts  += __shfl_xor_sync(0xffffffffu, ts,  off);
            tsq += __shfl_xor_sync(0xffffffffu, tsq, off);
        }
        if (tid == 0) {
            float mean = ts * (1.f / DDIM);
            float var  = tsq * (1.f / DDIM) - mean * mean;
            s_mean = mean;
            s_rstd = rsqrtf(var + EPS);
        }
    }
    __syncthreads();
    const float mean = s_mean, rstd = s_rstd;
    float4 gg = *(const float4*)(g + n);
    float4 bb = *(const float4*)(bt + n);
    float4 o;
    o.x = (va.x - mean) * rstd * gg.x + bb.x;
    o.y = (va.y - mean) * rstd * gg.y + bb.y;
    o.z = (va.z - mean) * rstd * gg.z + bb.z;
    o.w = (va.w - mean) * rstd * gg.w + bb.w;
    *(float4*)(out + base) = o;
    __nv_bfloat16 h0,h1,h2,h3,l0,l1,l2,l3;
    split1(o.x,h0,l0); split1(o.y,h1,l1); split1(o.z,h2,l2); split1(o.w,h3,l3);
    uint2 uh; uh.x = pack2(h0,h1); uh.y = pack2(h2,h3);
    uint2 ul; ul.x = pack2(l0,l1); ul.y = pack2(l2,l3);
    *(uint2*)(ohh + base) = uh;
    *(uint2*)(oll + base) = ul;
}

// ---------------------------------------------------------------------------
// Tensor-core full attention (bf16x3 flash); one barrier per key tile
// (load issued after the top barrier; cp_wait0 since only one group in flight).
// ---------------------------------------------------------------------------
#define ATTN_TC_SMEM 65536

__global__ __launch_bounds__(128, 3)
void attn_tc_kernel(const __nv_bfloat16* __restrict__ qkvh,
                    const __nv_bfloat16* __restrict__ qkvl,
                    __nv_bfloat16* __restrict__ oh,
                    __nv_bfloat16* __restrict__ ol)
{
    extern __shared__ char smc[];
    const uint32_t sb = (uint32_t)__cvta_generic_to_shared(smc);

    const int bh = blockIdx.x;
    const int b  = bh >> 4;
    const int h  = bh & 15;
    const int qt = blockIdx.y;
    const int tid  = threadIdx.x;
    const int wid  = tid >> 5;
    const int lane = tid & 31;

    const int r    = tid >> 1;
    const int koh  = (tid & 1) * 4;

    {
        const size_t qrow = (size_t)(b*SLEN + qt*64 + r) * D3 + h*HD;
        #pragma unroll
        for (int it = 0; it < 4; it++) {
            const int ko = koh + it;
            const uint32_t dst = sb + (uint32_t)(((ko*64 + r)*8) * 2);
            cp16(dst,        qkvh + qrow + ko*8);
            cp16(dst + 8192, qkvl + qrow + ko*8);
        }
        cp_commit();
    }

    const int a_row = lane & 15;
    const int a_ko  = lane >> 4;
    const int b_row = (lane & 7) + ((lane & 16) >> 1);
    const int b_ko  = (lane >> 3) & 1;
    const int v_key = lane & 15;
    const int v_ko  = lane >> 4;

    uint32_t qa_h[4][4], qa_l[4][4];

    cp_wait0();
    __syncthreads();
    #pragma unroll
    for (int ks = 0; ks < 4; ks++) {
        const uint32_t ad = sb +
            (uint32_t)((((ks*2 + a_ko)*64 + wid*16 + a_row)*8) * 2);
        ldsm4(qa_h[ks], ad);
        ldsm4(qa_l[ks], ad + 8192);
    }
    __syncthreads();

    auto load_kv = [&](int kt, int s) {
        const uint32_t stg = sb + (uint32_t)s * 32768;
        const size_t krow = (size_t)(b*SLEN + kt*64 + r) * D3 + DDIM + h*HD;
        const size_t vrow = krow + DDIM;
        #pragma unroll
        for (int it = 0; it < 4; it++) {
            const int ko = koh + it;
            const uint32_t off = (uint32_t)(((ko*64 + r)*8) * 2);
            cp16(stg + off,          qkvh + krow + ko*8);
            cp16(stg + 8192  + off,  qkvl + krow + ko*8);
            cp16(stg + 16384 + off,  qkvh + vrow + ko*8);
            cp16(stg + 24576 + off,  qkvl + vrow + ko*8);
        }
        cp_commit();
    };

    load_kv(0, 0);

    float m0 = -1e30f, m1 = -1e30f, l0 = 0.f, l1 = 0.f;
    float oacc[8][4];
    #pragma unroll
    for (int nf = 0; nf < 8; nf++)
        #pragma unroll
        for (int e = 0; e < 4; e++) oacc[nf][e] = 0.f;

    for (int kt = 0; kt < 16; kt++) {
        const int s = kt & 1;
        cp_wait0();
        __syncthreads();
        // all warps have finished reading buffer s^1 (previous iteration's
        // compute completed before arriving at the barrier) -> safe to refill.
        if (kt + 1 < 16) load_kv(kt + 1, s ^ 1);

        const uint32_t stg = sb + (uint32_t)s * 32768;

        float sc[8][4];
        #pragma unroll
        for (int nf = 0; nf < 8; nf++)
            #pragma unroll
            for (int e = 0; e < 4; e++) sc[nf][e] = 0.f;

        #pragma unroll
        for (int ks = 0; ks < 4; ks++) {
            #pragma unroll
            for (int np = 0; np < 4; np++) {
                uint32_t kb[4], kl[4];
                const uint32_t kd = stg +
                    (uint32_t)((((ks*2 + b_ko)*64 + np*16 + b_row)*8) * 2);
                ldsm4(kb, kd);
                ldsm4(kl, kd + 8192);
                mma16816(sc[2*np],   qa_h[ks], kb[0], kb[1]);
                mma16816(sc[2*np+1], qa_h[ks], kb[2], kb[3]);
                mma16816(sc[2*np],   qa_h[ks], kl[0], kl[1]);
                mma16816(sc[2*np+1], qa_h[ks], kl[2], kl[3]);
                mma16816(sc[2*np],   qa_l[ks], kb[0], kb[1]);
                mma16816(sc[2*np+1], qa_l[ks], kb[2], kb[3]);
            }
        }

        #pragma unroll
        for (int nf = 0; nf < 8; nf++)
            #pragma unroll
            for (int e = 0; e < 4; e++) sc[nf][e] *= 0.125f;

        float mx0 = m0, mx1 = m1;
        #pragma unroll
        for (int nf = 0; nf < 8; nf++) {
            mx0 = fmaxf(mx0, fmaxf(sc[nf][0], sc[nf][1]));
            mx1 = fmaxf(mx1, fmaxf(sc[nf][2], sc[nf][3]));
        }
        mx0 = fmaxf(mx0, __shfl_xor_sync(0xffffffffu, mx0, 1));
        mx0 = fmaxf(mx0, __shfl_xor_sync(0xffffffffu, mx0, 2));
        mx1 = fmaxf(mx1, __shfl_xor_sync(0xffffffffu, mx1, 1));
        mx1 = fmaxf(mx1, __shfl_xor_sync(0xffffffffu, mx1, 2));

        const float al0 = __expf(m0 - mx0);
        const float al1 = __expf(m1 - mx1);
        m0 = mx0; m1 = mx1;

        float s0 = 0.f, s1 = 0.f;
        uint32_t pah[4][4], pal[4][4];
        #pragma unroll
        for (int nf = 0; nf < 8; nf++) {
            const float p0 = __expf(sc[nf][0] - m0);
            const float p1 = __expf(sc[nf][1] - m0);
            const float p2 = __expf(sc[nf][2] - m1);
            const float p3 = __expf(sc[nf][3] - m1);
            s0 += p0 + p1;
            s1 += p2 + p3;
            __nv_bfloat16 h0,h1,h2,h3,lo0,lo1,lo2,lo3;
            split1(p0,h0,lo0); split1(p1,h1,lo1);
            split1(p2,h2,lo2); split1(p3,h3,lo3);
            const int ks = nf >> 1;
            const int hv = (nf & 1) * 2;
            pah[ks][hv+0] = pack2(h0, h1);
            pah[ks][hv+1] = pack2(h2, h3);
            pal[ks][hv+0] = pack2(lo0, lo1);
            pal[ks][hv+1] = pack2(lo2, lo3);
        }
        s0 += __shfl_xor_sync(0xffffffffu, s0, 1);
        s0 += __shfl_xor_sync(0xffffffffu, s0, 2);
        s1 += __shfl_xor_sync(0xffffffffu, s1, 1);
        s1 += __shfl_xor_sync(0xffffffffu, s1, 2);
        l0 = l0 * al0 + s0;
        l1 = l1 * al1 + s1;

        #pragma unroll
        for (int nf = 0; nf < 8; nf++) {
            oacc[nf][0] *= al0; oacc[nf][1] *= al0;
            oacc[nf][2] *= al1; oacc[nf][3] *= al1;
        }

        #pragma unroll
        for (int ks = 0; ks < 4; ks++) {
            #pragma unroll
            for (int np = 0; np < 4; np++) {
                uint32_t vb[4], vl[4];
                const uint32_t vd = stg + 16384 +
                    (uint32_t)((((np*2 + v_ko)*64 + ks*16 + v_key)*8) * 2);
                ldsm4t(vb, vd);
                ldsm4t(vl, vd + 8192);
                mma16816(oacc[2*np],   pah[ks], vb[0], vb[1]);
                mma16816(oacc[2*np+1], pah[ks], vb[2], vb[3]);
                mma16816(oacc[2*np],   pah[ks], vl[0], vl[1]);
                mma16816(oacc[2*np+1], pah[ks], vl[2], vl[3]);
                mma16816(oacc[2*np],   pal[ks], vb[0], vb[1]);
                mma16816(oacc[2*np+1], pal[ks], vb[2], vb[3]);
            }
        }
    }

    const float inv0 = 1.f / l0;
    const float inv1 = 1.f / l1;
    const int er  = lane >> 2;
    const int ec  = (lane & 3) * 2;
    const int tok0 = b*SLEN + qt*64 + wid*16 + er;
    const int tok1 = tok0 + 8;
    #pragma unroll
    for (int nf = 0; nf < 8; nf++) {
        const int col = h*HD + nf*8 + ec;
        const float o0 = oacc[nf][0] * inv0;
        const float o1 = oacc[nf][1] * inv0;
        const float o2 = oacc[nf][2] * inv1;
        const float o3 = oacc[nf][3] * inv1;
        __nv_bfloat16 h0,h1,h2,h3,lo0,lo1,lo2,lo3;
        split1(o0,h0,lo0); split1(o1,h1,lo1);
        split1(o2,h2,lo2); split1(o3,h3,lo3);
        *(uint32_t*)(oh + (size_t)tok0 * DDIM + col) = pack2(h0, h1);
        *(uint32_t*)(ol + (size_t)tok0 * DDIM + col) = pack2(lo0, lo1);
        *(uint32_t*)(oh + (size_t)tok1 * DDIM + col) = pack2(h2, h3);
        *(uint32_t*)(ol + (size_t)tok1 * DDIM + col) = pack2(lo2, lo3);
    }
}

// ---------------------------------------------------------------------------
// Banded attention — unchanged.
// ---------------------------------------------------------------------------
__global__ __launch_bounds__(256)
void attn_band_kernel(const __nv_bfloat16* __restrict__ qkvh,
                      const __nv_bfloat16* __restrict__ qkvl,
                      __nv_bfloat16* __restrict__ oh,
                      __nv_bfloat16* __restrict__ ol)
{
    const int gw   = (blockIdx.x * blockDim.x + threadIdx.x) >> 5;
    const int lane = threadIdx.x & 31;
    const int i = gw & (SLEN-1);
    const int h = (gw >> 10) & (HNUM-1);
    const int b = gw >> 14;

    const size_t qbase = (size_t)(b*SLEN + i) * D3 + h*HD;
    const float q0 = bf2f(qkvh[qbase + lane])      + bf2f(qkvl[qbase + lane]);
    const float q1 = bf2f(qkvh[qbase + 32 + lane]) + bf2f(qkvl[qbase + 32 + lane]);

    float sc[5];
    int   jc[5];
    #pragma unroll
    for (int jj = 0; jj < 5; jj++) {
        int j = i - 2 + jj;
        bool valid = (j >= 0) && (j < SLEN);
        jc[jj] = valid ? j : i;
        const size_t kb = (size_t)(b*SLEN + jc[jj]) * D3 + DDIM + h*HD;
        const float k0 = bf2f(qkvh[kb + lane])      + bf2f(qkvl[kb + lane]);
        const float k1 = bf2f(qkvh[kb + 32 + lane]) + bf2f(qkvl[kb + 32 + lane]);
        float p = q0 * k0 + q1 * k1;
        #pragma unroll
        for (int off = 16; off; off >>= 1) p += __shfl_xor_sync(0xffffffffu, p, off);
        sc[jj] = valid ? p * 0.125f : -1e30f;
    }
    float mx = sc[0];
    #pragma unroll
    for (int jj = 1; jj < 5; jj++) mx = fmaxf(mx, sc[jj]);
    float w[5], sum = 0.f;
    #pragma unroll
    for (int jj = 0; jj < 5; jj++) { w[jj] = __expf(sc[jj] - mx); sum += w[jj]; }
    const float inv = 1.f / sum;

    float o0 = 0.f, o1 = 0.f;
    #pragma unroll
    for (int jj = 0; jj < 5; jj++) {
        const size_t vb = (size_t)(b*SLEN + jc[jj]) * D3 + 2*DDIM + h*HD;
        const float v0 = bf2f(qkvh[vb + lane])      + bf2f(qkvl[vb + lane]);
        const float v1 = bf2f(qkvh[vb + 32 + lane]) + bf2f(qkvl[vb + 32 + lane]);
        o0 = fmaf(w[jj], v0, o0);
        o1 = fmaf(w[jj], v1, o1);
    }
    o0 *= inv; o1 *= inv;

    const size_t ob = (size_t)(b*SLEN + i) * DDIM + h*HD;
    __nv_bfloat16 hh, ll;
    split1(o0, hh, ll);
    oh[ob + lane] = hh;  ol[ob + lane] = ll;
    split1(o1, hh, ll);
    oh[ob + 32 + lane] = hh;  ol[ob + 32 + lane] = ll;
}

// ---------------------------------------------------------------------------
// LayerNorm (final output only).
// ---------------------------------------------------------------------------
__global__ __launch_bounds__(256)
void ln_kernel(const float* __restrict__ a, const float* __restrict__ g,
               const float* __restrict__ bt, float* __restrict__ out)
{
    __shared__ float red[2][8];
    __shared__ float s_mean, s_rstd;
    const int n = blockIdx.x;
    const int tid = threadIdx.x;
    const size_t base = (size_t)n * DDIM + tid * 4;

    float4 va = *(const float4*)(a + base);
    float s  = va.x + va.y + va.z + va.w;
    float sq = va.x*va.x + va.y*va.y + va.z*va.z + va.w*va.w;

    #pragma unroll
    for (int off = 16; off; off >>= 1) {
        s  += __shfl_xor_sync(0xffffffffu, s,  off);
        sq += __shfl_xor_sync(0xffffffffu, sq, off);
    }
    const int wid = tid >> 5;
    if ((tid & 31) == 0) { red[0][wid] = s; red[1][wid] = sq; }
    __syncthreads();
    if (tid < 32) {
        float ts  = (tid < 8) ? red[0][tid] : 0.f;
        float tsq = (tid < 8) ? red[1][tid] : 0.f;
        #pragma unroll
        for (int off = 4; off; off >>= 1) {
            ts  += __shfl_xor_sync(0xffffffffu, ts,  off);
            tsq += __shfl_xor_sync(0xffffffffu, tsq, off);
        }
        if (tid == 0) {
            float mean = ts * (1.f / DDIM);
            float var  = tsq * (1.f / DDIM) - mean * mean;
            s_mean = mean;
            s_rstd = rsqrtf(var + EPS);
        }
    }
    __syncthreads();
    const float mean = s_mean, rstd = s_rstd;
    float4 gg = *(const float4*)(g + tid*4);
    float4 bb = *(const float4*)(bt + tid*4);
    float4 o;
    o.x = (va.x - mean) * rstd * gg.x + bb.x;
    o.y = (va.y - mean) * rstd * gg.y + bb.y;
    o.z = (va.z - mean) * rstd * gg.z + bb.z;
    o.w = (va.w - mean) * rstd * gg.w + bb.w;
    *(float4*)(out + base) = o;
}

// ---------------------------------------------------------------------------
// Orchestration
// ---------------------------------------------------------------------------
extern "C" void kernel_launch(void* const* d_in, const int* in_sizes, int n_in,
                              void* d_out, int out_size)
{
    const float* x_in   = (const float*)d_in[0];
    const float* w_in1  = (const float*)d_in[1];
    const float* b_in1  = (const float*)d_in[2];
    const float* w_out1 = (const float*)d_in[3];
    const float* b_out1 = (const float*)d_in[4];
    const float* ln1_g  = (const float*)d_in[5];
    const float* ln1_b  = (const float*)d_in[6];
    const float* w_in2  = (const float*)d_in[7];
    const float* b_in2  = (const float*)d_in[8];
    const float* w_out2 = (const float*)d_in[9];
    const float* b_out2 = (const float*)d_in[10];
    const float* ln2_g  = (const float*)d_in[11];
    const float* ln2_b  = (const float*)d_in[12];
    const float* ffn_w1 = (const float*)d_in[13];
    const float* ffn_b1 = (const float*)d_in[14];
    const float* ffn_w2 = (const float*)d_in[15];
    const float* ffn_b2 = (const float*)d_in[16];
    const float* lnf_g  = (const float*)d_in[17];
    const float* lnf_b  = (const float*)d_in[18];

    float *X, *X2, *ATT, *PART;
    __nv_bfloat16 *WH, *WL, *QKVH, *QKVL, *P1H, *P1L, *P2H, *P2L;
    cudaGetSymbolAddress((void**)&X,    g_x);
    cudaGetSymbolAddress((void**)&X2,   g_x2);
    cudaGetSymbolAddress((void**)&ATT,  g_att);
    cudaGetSymbolAddress((void**)&PART, g_part);
    cudaGetSymbolAddress((void**)&WH,   g_wh);
    cudaGetSymbolAddress((void**)&WL,   g_wl);
    cudaGetSymbolAddress((void**)&QKVH, g_qkvh);
    cudaGetSymbolAddress((void**)&QKVL, g_qkvl);
    cudaGetSymbolAddress((void**)&P1H,  g_p1h);
    cudaGetSymbolAddress((void**)&P1L,  g_p1l);
    cudaGetSymbolAddress((void**)&P2H,  g_p2h);
    cudaGetSymbolAddress((void**)&P2L,  g_p2l);

    cudaFuncSetAttribute(attn_tc_kernel,
                         cudaFuncAttributeMaxDynamicSharedMemorySize, ATTN_TC_SMEM);
    cudaFuncSetAttribute(gemm_bf3<0,true,false,false>,
                         cudaFuncAttributeMaxDynamicSharedMemorySize, GSMEM_BYTES);
    cudaFuncSetAttribute(gemm_bf3<1,true,false,false>,
                         cudaFuncAttributeMaxDynamicSharedMemorySize, GSMEM_BYTES);
    cudaFuncSetAttribute(gemm_bf3<0,false,false,true>,
                         cudaFuncAttributeMaxDynamicSharedMemorySize, GSMEM_BYTES);

    const dim3 blk(256);
    const dim3 gblk(256);
    const dim3 g_qkvp(D3/128,  NTOK/128);        // (24,16)
    const dim3 g_outp(DDIM/128, NTOK/128, 2);    // (8,16,2)  split-K 2
    const dim3 g_ffn1(MDIM/128, NTOK/128);       // (32,16)
    const dim3 g_ffn2(DDIM/128, NTOK/128, 4);    // (8,16,4)  split-K 4
    const dim3 g_attn(BNUM*HNUM, SLEN/64);       // (32,16)
    const int  g_band = (BNUM*HNUM*SLEN*32) / 256;
    const int  g_ln   = NTOK;
    const int  g_red  = (NTOK*DDIM) / 1024;      // 2048

    // ---- single merged split launch: all 6 weights + layer-0 input ----
    split_all_kernel<<<SPLIT_TOTAL_BLOCKS, blk>>>(
        w_in1, w_out1, w_in2, w_out2, ffn_w1, ffn_w2, x_in,
        WH, WL, P1H, P1L);

    const float* xcur = x_in;
    for (int l = 0; l < LNUM; l++) {
        const size_t oW3 = (size_t)l * D3 * DDIM;
        const size_t oW1 = (size_t)l * DDIM * DDIM;
        const size_t oWm = (size_t)l * MDIM * DDIM;

        // ---- intra-frame full MHA ----
        gemm_bf3<0,true,false,false><<<g_qkvp, gblk, GSMEM_BYTES>>>(
            P1H, P1L, WH+W_IN1_OFF+oW3, WL+W_IN1_OFF+oW3,
            b_in1 + (size_t)l*D3, nullptr, nullptr, QKVH, QKVL, nullptr,
            NTOK, D3, DDIM);
        attn_tc_kernel<<<g_attn, 128, ATTN_TC_SMEM>>>(QKVH, QKVL, P1H, P1L);
        gemm_bf3<0,false,false,true><<<g_outp, gblk, GSMEM_BYTES>>>(
            P1H, P1L, WH+W_OUT1_OFF+oW1, WL+W_OUT1_OFF+oW1,
            nullptr, nullptr, nullptr, nullptr, nullptr, PART,
            NTOK, DDIM, DDIM);
        epi_ln_kernel<2><<<g_ln, blk>>>(
            PART, b_out1 + (size_t)l*DDIM, xcur,
            ln1_g + (size_t)l*DDIM, ln1_b + (size_t)l*DDIM, X2, P1H, P1L);

        // ---- inter-frame banded MHA ----
        gemm_bf3<0,true,false,false><<<g_qkvp, gblk, GSMEM_BYTES>>>(
            P1H, P1L, WH+W_IN2_OFF+oW3, WL+W_IN2_OFF+oW3,
            b_in2 + (size_t)l*D3, nullptr, nullptr, QKVH, QKVL, nullptr,
            NTOK, D3, DDIM);
        attn_band_kernel<<<g_band, blk>>>(QKVH, QKVL, P1H, P1L);
        gemm_bf3<0,false,false,true><<<g_outp, gblk, GSMEM_BYTES>>>(
            P1H, P1L, WH+W_OUT2_OFF+oW1, WL+W_OUT2_OFF+oW1,
            nullptr, nullptr, nullptr, nullptr, nullptr, PART,
            NTOK, DDIM, DDIM);
        epi_ln_kernel<2><<<g_ln, blk>>>(
            PART, b_out2 + (size_t)l*DDIM, X2,
            ln2_g + (size_t)l*DDIM, ln2_b + (size_t)l*DDIM, ATT, P1H, P1L);

        // ---- FFN ----
        gemm_bf3<1,true,false,false><<<g_ffn1, gblk, GSMEM_BYTES>>>(
            P1H, P1L, WH+FW1_OFF+oWm, WL+FW1_OFF+oWm,
            ffn_b1 + (size_t)l*MDIM, nullptr, nullptr, P2H, P2L, nullptr,
            NTOK, MDIM, DDIM);
        gemm_bf3<0,false,false,true><<<g_ffn2, gblk, GSMEM_BYTES>>>(
            P2H, P2L, WH+FW2_OFF+oWm, WL+FW2_OFF+oWm,
            nullptr, nullptr, nullptr, nullptr, nullptr, PART,
            NTOK, DDIM, MDIM);
        epi_reduce<2,true,true,4><<<g_red, blk>>>(
            PART, ffn_b2 + (size_t)l*DDIM, ATT, X, P1H, P1L);
        xcur = X;
    }

    ln_kernel<<<g_ln, blk>>>(xcur, lnf_g, lnf_b, (float*)d_out);
}

// round 15
// speedup vs baseline: 1.8985x; 1.0010x over previous
#include <cuda_runtime.h>
#include <cuda_bf16.h>
#include <math.h>
#include <stdint.h>

// ---------------------------------------------------------------------------
// Problem constants
// ---------------------------------------------------------------------------
#define LNUM 4
#define DDIM 1024
#define HNUM 16
#define HD   64
#define MDIM 4096
#define SLEN 1024
#define BNUM 2
#define NTOK (BNUM*SLEN)        // 2048
#define D3   (3*DDIM)           // 3072
#define EPS  1e-5f

// Weight split array layout (element offsets)
#define W_IN1_OFF   0u
#define W_OUT1_OFF  12582912u
#define W_IN2_OFF   16777216u
#define W_OUT2_OFF  29360128u
#define FW1_OFF     33554432u
#define FW2_OFF     50331648u
#define WTOTAL      67108864u

// ---------------------------------------------------------------------------
// Device scratch (no allocations allowed)
// ---------------------------------------------------------------------------
static __device__ float g_x   [NTOK*DDIM];
static __device__ float g_x2  [NTOK*DDIM];
static __device__ float g_att [NTOK*DDIM];
static __device__ float g_part[4u*NTOK*DDIM];        // split-K partials (32MB)

static __device__ __nv_bfloat16 g_wh[WTOTAL];        // weight hi
static __device__ __nv_bfloat16 g_wl[WTOTAL];        // weight lo
static __device__ __nv_bfloat16 g_qkvh[NTOK*D3];     // qkv hi
static __device__ __nv_bfloat16 g_qkvl[NTOK*D3];     // qkv lo
static __device__ __nv_bfloat16 g_p1h[NTOK*DDIM];
static __device__ __nv_bfloat16 g_p1l[NTOK*DDIM];
static __device__ __nv_bfloat16 g_p2h[NTOK*MDIM];
static __device__ __nv_bfloat16 g_p2l[NTOK*MDIM];

// ---------------------------------------------------------------------------
// Helpers
// ---------------------------------------------------------------------------
__device__ __forceinline__ void cp16(uint32_t d, const void* s) {
    asm volatile("cp.async.cg.shared.global [%0], [%1], 16;\n" :: "r"(d), "l"(s));
}
__device__ __forceinline__ void cp_commit() {
    asm volatile("cp.async.commit_group;\n" ::: "memory");
}
__device__ __forceinline__ void cp_wait1() {
    asm volatile("cp.async.wait_group 1;\n" ::: "memory");
}
__device__ __forceinline__ void cp_wait0() {
    asm volatile("cp.async.wait_group 0;\n" ::: "memory");
}
__device__ __forceinline__ void ldsm4(uint32_t* r, uint32_t a) {
    asm volatile("ldmatrix.sync.aligned.m8n8.x4.shared.b16 {%0,%1,%2,%3}, [%4];"
        : "=r"(r[0]), "=r"(r[1]), "=r"(r[2]), "=r"(r[3]) : "r"(a));
}
__device__ __forceinline__ void ldsm4t(uint32_t* r, uint32_t a) {
    asm volatile("ldmatrix.sync.aligned.m8n8.x4.trans.shared.b16 {%0,%1,%2,%3}, [%4];"
        : "=r"(r[0]), "=r"(r[1]), "=r"(r[2]), "=r"(r[3]) : "r"(a));
}
// Non-volatile: pure register computation; deps carried by constraints.
__device__ __forceinline__ void mma16816(float* c, const uint32_t* a,
                                         uint32_t b0, uint32_t b1) {
    asm("mma.sync.aligned.m16n8k16.row.col.f32.bf16.bf16.f32 "
        "{%0,%1,%2,%3},{%4,%5,%6,%7},{%8,%9},{%0,%1,%2,%3};"
        : "+f"(c[0]), "+f"(c[1]), "+f"(c[2]), "+f"(c[3])
        : "r"(a[0]), "r"(a[1]), "r"(a[2]), "r"(a[3]), "r"(b0), "r"(b1));
}
__device__ __forceinline__ uint32_t pack2(__nv_bfloat16 a, __nv_bfloat16 b) {
    __nv_bfloat162 t = __halves2bfloat162(a, b);
    return *reinterpret_cast<uint32_t*>(&t);
}
__device__ __forceinline__ void split1(float v, __nv_bfloat16& h, __nv_bfloat16& l) {
    h = __float2bfloat16(v);
    l = __float2bfloat16(v - __bfloat162float(h));
}
__device__ __forceinline__ float bf2f(__nv_bfloat16 v) { return __bfloat162float(v); }

// ---------------------------------------------------------------------------
// Merged fp32 -> (hi,lo) bf16 split for all 6 weight tensors + x_in.
// ---------------------------------------------------------------------------
#define SPLIT_TOTAL_BLOCKS 16896

__global__ __launch_bounds__(256)
void split_all_kernel(const float* __restrict__ w_in1, const float* __restrict__ w_out1,
                      const float* __restrict__ w_in2, const float* __restrict__ w_out2,
                      const float* __restrict__ fw1,  const float* __restrict__ fw2,
                      const float* __restrict__ x,
                      __nv_bfloat16* __restrict__ WH, __nv_bfloat16* __restrict__ WL,
                      __nv_bfloat16* __restrict__ P1H, __nv_bfloat16* __restrict__ P1L)
{
    const int bid = blockIdx.x;
    const float* src;
    __nv_bfloat16 *dh, *dl;
    int rb;
    if (bid < 3072)       { src = w_in1;  dh = WH + W_IN1_OFF;  dl = WL + W_IN1_OFF;  rb = bid; }
    else if (bid < 4096)  { src = w_out1; dh = WH + W_OUT1_OFF; dl = WL + W_OUT1_OFF; rb = bid - 3072; }
    else if (bid < 7168)  { src = w_in2;  dh = WH + W_IN2_OFF;  dl = WL + W_IN2_OFF;  rb = bid - 4096; }
    else if (bid < 8192)  { src = w_out2; dh = WH + W_OUT2_OFF; dl = WL + W_OUT2_OFF; rb = bid - 7168; }
    else if (bid < 12288) { src = fw1;    dh = WH + FW1_OFF;    dl = WL + FW1_OFF;    rb = bid - 8192; }
    else if (bid < 16384) { src = fw2;    dh = WH + FW2_OFF;    dl = WL + FW2_OFF;    rb = bid - 12288; }
    else                  { src = x;      dh = P1H;             dl = P1L;             rb = bid - 16384; }

    const size_t base = (size_t)rb * 4096 + threadIdx.x * 4;
    #pragma unroll
    for (int j = 0; j < 4; j++) {
        const size_t i = base + j * 1024;
        float4 v = *(const float4*)(src + i);
        __nv_bfloat16 h0,h1,h2,h3,l0,l1,l2,l3;
        split1(v.x,h0,l0); split1(v.y,h1,l1); split1(v.z,h2,l2); split1(v.w,h3,l3);
        uint2 uh; uh.x = pack2(h0,h1); uh.y = pack2(h2,h3);
        uint2 ul; ul.x = pack2(l0,l1); ul.y = pack2(l2,l3);
        *(uint2*)(dh + i) = uh;
        *(uint2*)(dl + i) = ul;
    }
}

// ---------------------------------------------------------------------------
// bf16x3 tensor-core GEMM — unchanged from round 13/14 (known good).
// ---------------------------------------------------------------------------
#define STAGE_BYTES 32768
#define GSMEM_BYTES (3*STAGE_BYTES)

template<int EPI, bool OSPLIT, bool OF32, bool PARTIAL>
__global__ __launch_bounds__(256, 2)
void gemm_bf3(const __nv_bfloat16* __restrict__ Ah, const __nv_bfloat16* __restrict__ Al,
              const __nv_bfloat16* __restrict__ Bh, const __nv_bfloat16* __restrict__ Bl,
              const float* __restrict__ bias, const float* __restrict__ Res,
              float* __restrict__ C, __nv_bfloat16* __restrict__ Chi,
              __nv_bfloat16* __restrict__ Clo, float* __restrict__ Part,
              int M, int N, int K)
{
    extern __shared__ __nv_bfloat16 smbuf[];
    const uint32_t smem_u32 = (uint32_t)__cvta_generic_to_shared(smbuf);

    const int tid = threadIdx.x;
    const int m0 = blockIdx.y * 128;
    const int n0 = blockIdx.x * 128;
    const int z  = blockIdx.z;
    const int Ksub = K / gridDim.z;

    const int lrow = tid & 127;
    const bool isB = tid >= 128;
    const size_t kofs = (size_t)z * Ksub;
    const __nv_bfloat16* pH = (isB ? Bh + (size_t)(n0 + lrow) * K
                                   : Ah + (size_t)(m0 + lrow) * K) + kofs;
    const __nv_bfloat16* pL = (isB ? Bl + (size_t)(n0 + lrow) * K
                                   : Al + (size_t)(m0 + lrow) * K) + kofs;
    const uint32_t regH = isB ? 16384u : 0u;
    const uint32_t rowb = (uint32_t)lrow * 16;

    auto load_stage = [&](int kt, int s) {
        const uint32_t sb = smem_u32 + (uint32_t)s * STAGE_BYTES + regH;
        const size_t gk = (size_t)kt * 32;
        #pragma unroll
        for (int ko = 0; ko < 4; ko++) {
            const uint32_t o = (uint32_t)ko * 2048 + rowb;
            cp16(sb + o,        pH + gk + ko*8);
            cp16(sb + 8192 + o, pL + gk + ko*8);
        }
        cp_commit();
    };

    const int wid  = tid >> 5;
    const int lane = tid & 31;
    const int wm = (wid >> 1) * 32;
    const int wn = (wid & 1) * 64;
    const int a_row = lane & 15;
    const int a_ko  = lane >> 4;
    const int b_row = (lane & 7) + ((lane & 16) >> 1);
    const int b_ko  = (lane >> 3) & 1;

    const uint32_t aoff = (uint32_t)((a_ko*1024 + (wm + a_row)*8) * 2);
    const uint32_t boff = (uint32_t)(16384 + (b_ko*1024 + (wn + b_row)*8) * 2);

    float acc[2][8][4];
    #pragma unroll
    for (int i = 0; i < 2; i++)
        #pragma unroll
        for (int j = 0; j < 8; j++)
            #pragma unroll
            for (int e = 0; e < 4; e++) acc[i][j][e] = 0.f;

    const int T = Ksub >> 5;

    load_stage(0, 0);
    if (T > 1) load_stage(1, 1);

    for (int kt = 0; kt < T; kt++) {
        if (kt + 1 < T) cp_wait1(); else cp_wait0();
        __syncthreads();
        if (kt + 2 < T) load_stage(kt + 2, (kt + 2) % 3);

        const uint32_t sb = smem_u32 + (uint32_t)(kt % 3) * STAGE_BYTES;
        #pragma unroll
        for (int ko0 = 0; ko0 < 4; ko0 += 2) {
            uint32_t a_h[2][4], a_l[2][4];
            #pragma unroll
            for (int mf = 0; mf < 2; mf++) {
                const uint32_t ad = sb + aoff + (uint32_t)ko0*2048 + (uint32_t)mf*256;
                ldsm4(a_h[mf], ad);
                ldsm4(a_l[mf], ad + 8192);
            }
            uint32_t b_h[2][4], b_l[2][4];
            {
                const uint32_t bd0 = sb + boff + (uint32_t)ko0*2048;
                ldsm4(b_h[0], bd0);
                ldsm4(b_l[0], bd0 + 8192);
            }
            #pragma unroll
            for (int nf2 = 0; nf2 < 4; nf2++) {
                const int cur = nf2 & 1;
                const int nxt = cur ^ 1;
                if (nf2 < 3) {
                    const uint32_t bdn = sb + boff + (uint32_t)ko0*2048
                                       + (uint32_t)(nf2+1)*256;
                    ldsm4(b_h[nxt], bdn);
                    ldsm4(b_l[nxt], bdn + 8192);
                }
                const int nf = nf2 * 2;
                mma16816(acc[0][nf],   a_h[0], b_h[cur][0], b_h[cur][1]);
                mma16816(acc[0][nf+1], a_h[0], b_h[cur][2], b_h[cur][3]);
                mma16816(acc[1][nf],   a_h[1], b_h[cur][0], b_h[cur][1]);
                mma16816(acc[1][nf+1], a_h[1], b_h[cur][2], b_h[cur][3]);
                mma16816(acc[0][nf],   a_h[0], b_l[cur][0], b_l[cur][1]);
                mma16816(acc[0][nf+1], a_h[0], b_l[cur][2], b_l[cur][3]);
                mma16816(acc[1][nf],   a_h[1], b_l[cur][0], b_l[cur][1]);
                mma16816(acc[1][nf+1], a_h[1], b_l[cur][2], b_l[cur][3]);
                mma16816(acc[0][nf],   a_l[0], b_h[cur][0], b_h[cur][1]);
                mma16816(acc[0][nf+1], a_l[0], b_h[cur][2], b_h[cur][3]);
                mma16816(acc[1][nf],   a_l[1], b_h[cur][0], b_h[cur][1]);
                mma16816(acc[1][nf+1], a_l[1], b_h[cur][2], b_h[cur][3]);
            }
        }
    }

    // ---- epilogue ----
    const int er = lane >> 2;
    const int ec = (lane & 3) * 2;
    if (PARTIAL) {
        float* dst = Part + (size_t)z * M * N;
        #pragma unroll
        for (int mf = 0; mf < 2; mf++)
            #pragma unroll
            for (int nf = 0; nf < 8; nf++) {
                const int m = m0 + wm + mf*16 + er;
                const int n = n0 + wn + nf*8 + ec;
                #pragma unroll
                for (int half = 0; half < 2; half++) {
                    const int mm = m + half*8;
                    *(float2*)(dst + (size_t)mm * N + n) =
                        make_float2(acc[mf][nf][half*2+0], acc[mf][nf][half*2+1]);
                }
            }
        return;
    }

    #pragma unroll
    for (int mf = 0; mf < 2; mf++) {
        #pragma unroll
        for (int nf = 0; nf < 8; nf++) {
            const int m = m0 + wm + mf*16 + er;
            const int n = n0 + wn + nf*8 + ec;
            const float2 bv = *(const float2*)(bias + n);
            #pragma unroll
            for (int half = 0; half < 2; half++) {
                const int mm = m + half*8;
                float t0 = acc[mf][nf][half*2+0] + bv.x;
                float t1 = acc[mf][nf][half*2+1] + bv.y;
                if (EPI == 1) {
                    t0 = 0.5f * t0 * (1.f + erff(t0 * 0.70710678118654752f));
                    t1 = 0.5f * t1 * (1.f + erff(t1 * 0.70710678118654752f));
                }
                if (EPI == 2) {
                    const float2 rv = *(const float2*)(Res + (size_t)mm * N + n);
                    t0 += rv.x; t1 += rv.y;
                }
                if (OF32) {
                    *(float2*)(C + (size_t)mm * N + n) = make_float2(t0, t1);
                }
                if (OSPLIT) {
                    __nv_bfloat16 h0,h1,l0,l1;
                    split1(t0,h0,l0); split1(t1,h1,l1);
                    *(uint32_t*)(Chi + (size_t)mm * N + n) = pack2(h0,h1);
                    *(uint32_t*)(Clo + (size_t)mm * N + n) = pack2(l0,l1);
                }
            }
        }
    }
}

// ---------------------------------------------------------------------------
// Split-K reduce + epilogue (no LN). N fixed at DDIM.
// ---------------------------------------------------------------------------
template<int EPI, bool OSPLIT, bool OF32, int S>
__global__ __launch_bounds__(256)
void epi_reduce(const float* __restrict__ Part, const float* __restrict__ bias,
                const float* __restrict__ Res, float* __restrict__ C,
                __nv_bfloat16* __restrict__ Chi, __nv_bfloat16* __restrict__ Clo)
{
    const size_t i = (size_t)blockIdx.x * 1024 + threadIdx.x * 4;
    const int n = (int)(i & (DDIM - 1));
    float4 t = *(const float4*)(Part + i);
    #pragma unroll
    for (int s = 1; s < S; s++) {
        const float4 p = *(const float4*)(Part + (size_t)s * (NTOK*DDIM) + i);
        t.x += p.x; t.y += p.y; t.z += p.z; t.w += p.w;
    }
    const float4 bv = *(const float4*)(bias + n);
    t.x += bv.x; t.y += bv.y; t.z += bv.z; t.w += bv.w;
    if (EPI == 1) {
        t.x = 0.5f * t.x * (1.f + erff(t.x * 0.70710678118654752f));
        t.y = 0.5f * t.y * (1.f + erff(t.y * 0.70710678118654752f));
        t.z = 0.5f * t.z * (1.f + erff(t.z * 0.70710678118654752f));
        t.w = 0.5f * t.w * (1.f + erff(t.w * 0.70710678118654752f));
    }
    if (EPI == 2) {
        const float4 rv = *(const float4*)(Res + i);
        t.x += rv.x; t.y += rv.y; t.z += rv.z; t.w += rv.w;
    }
    if (OF32) *(float4*)(C + i) = t;
    if (OSPLIT) {
        __nv_bfloat16 h0,h1,h2,h3,l0,l1,l2,l3;
        split1(t.x,h0,l0); split1(t.y,h1,l1); split1(t.z,h2,l2); split1(t.w,h3,l3);
        uint2 uh; uh.x = pack2(h0,h1); uh.y = pack2(h2,h3);
        uint2 ul; ul.x = pack2(l0,l1); ul.y = pack2(l2,l3);
        *(uint2*)(Chi + i) = uh;
        *(uint2*)(Clo + i) = ul;
    }
}

// ---------------------------------------------------------------------------
// FUSED split-K reduce + bias + residual + LayerNorm + split outputs.
// ---------------------------------------------------------------------------
template<int S>
__global__ __launch_bounds__(256)
void epi_ln_kernel(const float* __restrict__ Part, const float* __restrict__ bias,
                   const float* __restrict__ r,   const float* __restrict__ g,
                   const float* __restrict__ bt,  float* __restrict__ out,
                   __nv_bfloat16* __restrict__ ohh, __nv_bfloat16* __restrict__ oll)
{
    __shared__ float red[2][8];
    __shared__ float s_mean, s_rstd;
    const int tok = blockIdx.x;
    const int tid = threadIdx.x;
    const size_t base = (size_t)tok * DDIM + tid * 4;
    const int n = tid * 4;

    float4 va = *(const float4*)(Part + base);
    #pragma unroll
    for (int s = 1; s < S; s++) {
        const float4 p = *(const float4*)(Part + (size_t)s * (NTOK*DDIM) + base);
        va.x += p.x; va.y += p.y; va.z += p.z; va.w += p.w;
    }
    const float4 bv = *(const float4*)(bias + n);
    va.x += bv.x; va.y += bv.y; va.z += bv.z; va.w += bv.w;

    const float4 vr = *(const float4*)(r + base);
    va.x += vr.x; va.y += vr.y; va.z += vr.z; va.w += vr.w;

    float s  = va.x + va.y + va.z + va.w;
    float sq = va.x*va.x + va.y*va.y + va.z*va.z + va.w*va.w;

    #pragma unroll
    for (int off = 16; off; off >>= 1) {
        s  += __shfl_xor_sync(0xffffffffu, s,  off);
        sq += __shfl_xor_sync(0xffffffffu, sq, off);
    }
    const int wid = tid >> 5;
    if ((tid & 31) == 0) { red[0][wid] = s; red[1][wid] = sq; }
    __syncthreads();
    if (tid < 32) {
        float ts  = (tid < 8) ? red[0][tid] : 0.f;
        float tsq = (tid < 8) ? red[1][tid] : 0.f;
        #pragma unroll
        for (int off = 4; off; off >>= 1) {
            ts  += __shfl_xor_sync(0xffffffffu, ts,  off);
            tsq += __shfl_xor_sync(0xffffffffu, tsq, off);
        }
        if (tid == 0) {
            float mean = ts * (1.f / DDIM);
            float var  = tsq * (1.f / DDIM) - mean * mean;
            s_mean = mean;
            s_rstd = rsqrtf(var + EPS);
        }
    }
    __syncthreads();
    const float mean = s_mean, rstd = s_rstd;
    float4 gg = *(const float4*)(g + n);
    float4 bb = *(const float4*)(bt + n);
    float4 o;
    o.x = (va.x - mean) * rstd * gg.x + bb.x;
    o.y = (va.y - mean) * rstd * gg.y + bb.y;
    o.z = (va.z - mean) * rstd * gg.z + bb.z;
    o.w = (va.w - mean) * rstd * gg.w + bb.w;
    *(float4*)(out + base) = o;
    __nv_bfloat16 h0,h1,h2,h3,l0,l1,l2,l3;
    split1(o.x,h0,l0); split1(o.y,h1,l1); split1(o.z,h2,l2); split1(o.w,h3,l3);
    uint2 uh; uh.x = pack2(h0,h1); uh.y = pack2(h2,h3);
    uint2 ul; ul.x = pack2(l0,l1); ul.y = pack2(l2,l3);
    *(uint2*)(ohh + base) = uh;
    *(uint2*)(oll + base) = ul;
}

// ---------------------------------------------------------------------------
// Tensor-core full attention (bf16x3 flash). K and V fragments are register
// double-buffered across the 16 (ks,np) groups of each MMA phase, hiding the
// LDSM->HMMA latency behind the MMA issue stream (same technique as the GEMM).
// One barrier per key tile.
// ---------------------------------------------------------------------------
#define ATTN_TC_SMEM 65536

__global__ __launch_bounds__(128, 3)
void attn_tc_kernel(const __nv_bfloat16* __restrict__ qkvh,
                    const __nv_bfloat16* __restrict__ qkvl,
                    __nv_bfloat16* __restrict__ oh,
                    __nv_bfloat16* __restrict__ ol)
{
    extern __shared__ char smc[];
    const uint32_t sb = (uint32_t)__cvta_generic_to_shared(smc);

    const int bh = blockIdx.x;
    const int b  = bh >> 4;
    const int h  = bh & 15;
    const int qt = blockIdx.y;
    const int tid  = threadIdx.x;
    const int wid  = tid >> 5;
    const int lane = tid & 31;

    const int r    = tid >> 1;
    const int koh  = (tid & 1) * 4;

    {
        const size_t qrow = (size_t)(b*SLEN + qt*64 + r) * D3 + h*HD;
        #pragma unroll
        for (int it = 0; it < 4; it++) {
            const int ko = koh + it;
            const uint32_t dst = sb + (uint32_t)(((ko*64 + r)*8) * 2);
            cp16(dst,        qkvh + qrow + ko*8);
            cp16(dst + 8192, qkvl + qrow + ko*8);
        }
        cp_commit();
    }

    const int a_row = lane & 15;
    const int a_ko  = lane >> 4;
    const int b_row = (lane & 7) + ((lane & 16) >> 1);
    const int b_ko  = (lane >> 3) & 1;
    const int v_key = lane & 15;
    const int v_ko  = lane >> 4;

    uint32_t qa_h[4][4], qa_l[4][4];

    cp_wait0();
    __syncthreads();
    #pragma unroll
    for (int ks = 0; ks < 4; ks++) {
        const uint32_t ad = sb +
            (uint32_t)((((ks*2 + a_ko)*64 + wid*16 + a_row)*8) * 2);
        ldsm4(qa_h[ks], ad);
        ldsm4(qa_l[ks], ad + 8192);
    }
    __syncthreads();

    auto load_kv = [&](int kt, int s) {
        const uint32_t stg = sb + (uint32_t)s * 32768;
        const size_t krow = (size_t)(b*SLEN + kt*64 + r) * D3 + DDIM + h*HD;
        const size_t vrow = krow + DDIM;
        #pragma unroll
        for (int it = 0; it < 4; it++) {
            const int ko = koh + it;
            const uint32_t off = (uint32_t)(((ko*64 + r)*8) * 2);
            cp16(stg + off,          qkvh + krow + ko*8);
            cp16(stg + 8192  + off,  qkvl + krow + ko*8);
            cp16(stg + 16384 + off,  qkvh + vrow + ko*8);
            cp16(stg + 24576 + off,  qkvl + vrow + ko*8);
        }
        cp_commit();
    };

    load_kv(0, 0);

    float m0 = -1e30f, m1 = -1e30f, l0 = 0.f, l1 = 0.f;
    float oacc[8][4];
    #pragma unroll
    for (int nf = 0; nf < 8; nf++)
        #pragma unroll
        for (int e = 0; e < 4; e++) oacc[nf][e] = 0.f;

    for (int kt = 0; kt < 16; kt++) {
        const int s = kt & 1;
        cp_wait0();
        __syncthreads();
        if (kt + 1 < 16) load_kv(kt + 1, s ^ 1);

        const uint32_t stg = sb + (uint32_t)s * 32768;

        float sc[8][4];
        #pragma unroll
        for (int nf = 0; nf < 8; nf++)
            #pragma unroll
            for (int e = 0; e < 4; e++) sc[nf][e] = 0.f;

        // ---- QK: flattened 16 groups, K fragments double-buffered ----
        {
            auto kaddr = [&](int idx) {
                const int ks = idx >> 2, np = idx & 3;
                return stg + (uint32_t)((((ks*2 + b_ko)*64 + np*16 + b_row)*8) * 2);
            };
            uint32_t kb[2][4], kl[2][4];
            ldsm4(kb[0], kaddr(0));
            ldsm4(kl[0], kaddr(0) + 8192);
            #pragma unroll
            for (int idx = 0; idx < 16; idx++) {
                const int cur = idx & 1, nxt = cur ^ 1;
                if (idx < 15) {
                    const uint32_t na = kaddr(idx + 1);
                    ldsm4(kb[nxt], na);
                    ldsm4(kl[nxt], na + 8192);
                }
                const int ks = idx >> 2, np = idx & 3;
                mma16816(sc[2*np],   qa_h[ks], kb[cur][0], kb[cur][1]);
                mma16816(sc[2*np+1], qa_h[ks], kb[cur][2], kb[cur][3]);
                mma16816(sc[2*np],   qa_h[ks], kl[cur][0], kl[cur][1]);
                mma16816(sc[2*np+1], qa_h[ks], kl[cur][2], kl[cur][3]);
                mma16816(sc[2*np],   qa_l[ks], kb[cur][0], kb[cur][1]);
                mma16816(sc[2*np+1], qa_l[ks], kb[cur][2], kb[cur][3]);
            }
        }

        #pragma unroll
        for (int nf = 0; nf < 8; nf++)
            #pragma unroll
            for (int e = 0; e < 4; e++) sc[nf][e] *= 0.125f;

        float mx0 = m0, mx1 = m1;
        #pragma unroll
        for (int nf = 0; nf < 8; nf++) {
            mx0 = fmaxf(mx0, fmaxf(sc[nf][0], sc[nf][1]));
            mx1 = fmaxf(mx1, fmaxf(sc[nf][2], sc[nf][3]));
        }
        mx0 = fmaxf(mx0, __shfl_xor_sync(0xffffffffu, mx0, 1));
        mx0 = fmaxf(mx0, __shfl_xor_sync(0xffffffffu, mx0, 2));
        mx1 = fmaxf(mx1, __shfl_xor_sync(0xffffffffu, mx1, 1));
        mx1 = fmaxf(mx1, __shfl_xor_sync(0xffffffffu, mx1, 2));

        const float al0 = __expf(m0 - mx0);
        const float al1 = __expf(m1 - mx1);
        m0 = mx0; m1 = mx1;

        float s0 = 0.f, s1 = 0.f;
        uint32_t pah[4][4], pal[4][4];
        #pragma unroll
        for (int nf = 0; nf < 8; nf++) {
            const float p0 = __expf(sc[nf][0] - m0);
            const float p1 = __expf(sc[nf][1] - m0);
            const float p2 = __expf(sc[nf][2] - m1);
            const float p3 = __expf(sc[nf][3] - m1);
            s0 += p0 + p1;
            s1 += p2 + p3;
            __nv_bfloat16 h0,h1,h2,h3,lo0,lo1,lo2,lo3;
            split1(p0,h0,lo0); split1(p1,h1,lo1);
            split1(p2,h2,lo2); split1(p3,h3,lo3);
            const int ks = nf >> 1;
            const int hv = (nf & 1) * 2;
            pah[ks][hv+0] = pack2(h0, h1);
            pah[ks][hv+1] = pack2(h2, h3);
            pal[ks][hv+0] = pack2(lo0, lo1);
            pal[ks][hv+1] = pack2(lo2, lo3);
        }
        s0 += __shfl_xor_sync(0xffffffffu, s0, 1);
        s0 += __shfl_xor_sync(0xffffffffu, s0, 2);
        s1 += __shfl_xor_sync(0xffffffffu, s1, 1);
        s1 += __shfl_xor_sync(0xffffffffu, s1, 2);
        l0 = l0 * al0 + s0;
        l1 = l1 * al1 + s1;

        #pragma unroll
        for (int nf = 0; nf < 8; nf++) {
            oacc[nf][0] *= al0; oacc[nf][1] *= al0;
            oacc[nf][2] *= al1; oacc[nf][3] *= al1;
        }

        // ---- PV: flattened 16 groups, V fragments double-buffered ----
        {
            auto vaddr = [&](int idx) {
                const int ks = idx >> 2, np = idx & 3;
                return stg + 16384 +
                    (uint32_t)((((np*2 + v_ko)*64 + ks*16 + v_key)*8) * 2);
            };
            uint32_t vb[2][4], vl[2][4];
            ldsm4t(vb[0], vaddr(0));
            ldsm4t(vl[0], vaddr(0) + 8192);
            #pragma unroll
            for (int idx = 0; idx < 16; idx++) {
                const int cur = idx & 1, nxt = cur ^ 1;
                if (idx < 15) {
                    const uint32_t na = vaddr(idx + 1);
                    ldsm4t(vb[nxt], na);
                    ldsm4t(vl[nxt], na + 8192);
                }
                const int ks = idx >> 2, np = idx & 3;
                mma16816(oacc[2*np],   pah[ks], vb[cur][0], vb[cur][1]);
                mma16816(oacc[2*np+1], pah[ks], vb[cur][2], vb[cur][3]);
                mma16816(oacc[2*np],   pah[ks], vl[cur][0], vl[cur][1]);
                mma16816(oacc[2*np+1], pah[ks], vl[cur][2], vl[cur][3]);
                mma16816(oacc[2*np],   pal[ks], vb[cur][0], vb[cur][1]);
                mma16816(oacc[2*np+1], pal[ks], vb[cur][2], vb[cur][3]);
            }
        }
    }

    const float inv0 = 1.f / l0;
    const float inv1 = 1.f / l1;
    const int er  = lane >> 2;
    const int ec  = (lane & 3) * 2;
    const int tok0 = b*SLEN + qt*64 + wid*16 + er;
    const int tok1 = tok0 + 8;
    #pragma unroll
    for (int nf = 0; nf < 8; nf++) {
        const int col = h*HD + nf*8 + ec;
        const float o0 = oacc[nf][0] * inv0;
        const float o1 = oacc[nf][1] * inv0;
        const float o2 = oacc[nf][2] * inv1;
        const float o3 = oacc[nf][3] * inv1;
        __nv_bfloat16 h0,h1,h2,h3,lo0,lo1,lo2,lo3;
        split1(o0,h0,lo0); split1(o1,h1,lo1);
        split1(o2,h2,lo2); split1(o3,h3,lo3);
        *(uint32_t*)(oh + (size_t)tok0 * DDIM + col) = pack2(h0, h1);
        *(uint32_t*)(ol + (size_t)tok0 * DDIM + col) = pack2(lo0, lo1);
        *(uint32_t*)(oh + (size_t)tok1 * DDIM + col) = pack2(h2, h3);
        *(uint32_t*)(ol + (size_t)tok1 * DDIM + col) = pack2(lo2, lo3);
    }
}

// ---------------------------------------------------------------------------
// Banded attention — unchanged.
// ---------------------------------------------------------------------------
__global__ __launch_bounds__(256)
void attn_band_kernel(const __nv_bfloat16* __restrict__ qkvh,
                      const __nv_bfloat16* __restrict__ qkvl,
                      __nv_bfloat16* __restrict__ oh,
                      __nv_bfloat16* __restrict__ ol)
{
    const int gw   = (blockIdx.x * blockDim.x + threadIdx.x) >> 5;
    const int lane = threadIdx.x & 31;
    const int i = gw & (SLEN-1);
    const int h = (gw >> 10) & (HNUM-1);
    const int b = gw >> 14;

    const size_t qbase = (size_t)(b*SLEN + i) * D3 + h*HD;
    const float q0 = bf2f(qkvh[qbase + lane])      + bf2f(qkvl[qbase + lane]);
    const float q1 = bf2f(qkvh[qbase + 32 + lane]) + bf2f(qkvl[qbase + 32 + lane]);

    float sc[5];
    int   jc[5];
    #pragma unroll
    for (int jj = 0; jj < 5; jj++) {
        int j = i - 2 + jj;
        bool valid = (j >= 0) && (j < SLEN);
        jc[jj] = valid ? j : i;
        const size_t kb = (size_t)(b*SLEN + jc[jj]) * D3 + DDIM + h*HD;
        const float k0 = bf2f(qkvh[kb + lane])      + bf2f(qkvl[kb + lane]);
        const float k1 = bf2f(qkvh[kb + 32 + lane]) + bf2f(qkvl[kb + 32 + lane]);
        float p = q0 * k0 + q1 * k1;
        #pragma unroll
        for (int off = 16; off; off >>= 1) p += __shfl_xor_sync(0xffffffffu, p, off);
        sc[jj] = valid ? p * 0.125f : -1e30f;
    }
    float mx = sc[0];
    #pragma unroll
    for (int jj = 1; jj < 5; jj++) mx = fmaxf(mx, sc[jj]);
    float w[5], sum = 0.f;
    #pragma unroll
    for (int jj = 0; jj < 5; jj++) { w[jj] = __expf(sc[jj] - mx); sum += w[jj]; }
    const float inv = 1.f / sum;

    float o0 = 0.f, o1 = 0.f;
    #pragma unroll
    for (int jj = 0; jj < 5; jj++) {
        const size_t vb = (size_t)(b*SLEN + jc[jj]) * D3 + 2*DDIM + h*HD;
        const float v0 = bf2f(qkvh[vb + lane])      + bf2f(qkvl[vb + lane]);
        const float v1 = bf2f(qkvh[vb + 32 + lane]) + bf2f(qkvl[vb + 32 + lane]);
        o0 = fmaf(w[jj], v0, o0);
        o1 = fmaf(w[jj], v1, o1);
    }
    o0 *= inv; o1 *= inv;

    const size_t ob = (size_t)(b*SLEN + i) * DDIM + h*HD;
    __nv_bfloat16 hh, ll;
    split1(o0, hh, ll);
    oh[ob + lane] = hh;  ol[ob + lane] = ll;
    split1(o1, hh, ll);
    oh[ob + 32 + lane] = hh;  ol[ob + 32 + lane] = ll;
}

// ---------------------------------------------------------------------------
// LayerNorm (final output only).
// ---------------------------------------------------------------------------
__global__ __launch_bounds__(256)
void ln_kernel(const float* __restrict__ a, const float* __restrict__ g,
               const float* __restrict__ bt, float* __restrict__ out)
{
    __shared__ float red[2][8];
    __shared__ float s_mean, s_rstd;
    const int n = blockIdx.x;
    const int tid = threadIdx.x;
    const size_t base = (size_t)n * DDIM + tid * 4;

    float4 va = *(const float4*)(a + base);
    float s  = va.x + va.y + va.z + va.w;
    float sq = va.x*va.x + va.y*va.y + va.z*va.z + va.w*va.w;

    #pragma unroll
    for (int off = 16; off; off >>= 1) {
        s  += __shfl_xor_sync(0xffffffffu, s,  off);
        sq += __shfl_xor_sync(0xffffffffu, sq, off);
    }
    const int wid = tid >> 5;
    if ((tid & 31) == 0) { red[0][wid] = s; red[1][wid] = sq; }
    __syncthreads();
    if (tid < 32) {
        float ts  = (tid < 8) ? red[0][tid] : 0.f;
        float tsq = (tid < 8) ? red[1][tid] : 0.f;
        #pragma unroll
        for (int off = 4; off; off >>= 1) {
            ts  += __shfl_xor_sync(0xffffffffu, ts,  off);
            tsq += __shfl_xor_sync(0xffffffffu, tsq, off);
        }
        if (tid == 0) {
            float mean = ts * (1.f / DDIM);
            float var  = tsq * (1.f / DDIM) - mean * mean;
            s_mean = mean;
            s_rstd = rsqrtf(var + EPS);
        }
    }
    __syncthreads();
    const float mean = s_mean, rstd = s_rstd;
    float4 gg = *(const float4*)(g + tid*4);
    float4 bb = *(const float4*)(bt + tid*4);
    float4 o;
    o.x = (va.x - mean) * rstd * gg.x + bb.x;
    o.y = (va.y - mean) * rstd * gg.y + bb.y;
    o.z = (va.z - mean) * rstd * gg.z + bb.z;
    o.w = (va.w - mean) * rstd * gg.w + bb.w;
    *(float4*)(out + base) = o;
}

// ---------------------------------------------------------------------------
// Orchestration
// ---------------------------------------------------------------------------
extern "C" void kernel_launch(void* const* d_in, const int* in_sizes, int n_in,
                              void* d_out, int out_size)
{
    const float* x_in   = (const float*)d_in[0];
    const float* w_in1  = (const float*)d_in[1];
    const float* b_in1  = (const float*)d_in[2];
    const float* w_out1 = (const float*)d_in[3];
    const float* b_out1 = (const float*)d_in[4];
    const float* ln1_g  = (const float*)d_in[5];
    const float* ln1_b  = (const float*)d_in[6];
    const float* w_in2  = (const float*)d_in[7];
    const float* b_in2  = (const float*)d_in[8];
    const float* w_out2 = (const float*)d_in[9];
    const float* b_out2 = (const float*)d_in[10];
    const float* ln2_g  = (const float*)d_in[11];
    const float* ln2_b  = (const float*)d_in[12];
    const float* ffn_w1 = (const float*)d_in[13];
    const float* ffn_b1 = (const float*)d_in[14];
    const float* ffn_w2 = (const float*)d_in[15];
    const float* ffn_b2 = (const float*)d_in[16];
    const float* lnf_g  = (const float*)d_in[17];
    const float* lnf_b  = (const float*)d_in[18];

    float *X, *X2, *ATT, *PART;
    __nv_bfloat16 *WH, *WL, *QKVH, *QKVL, *P1H, *P1L, *P2H, *P2L;
    cudaGetSymbolAddress((void**)&X,    g_x);
    cudaGetSymbolAddress((void**)&X2,   g_x2);
    cudaGetSymbolAddress((void**)&ATT,  g_att);
    cudaGetSymbolAddress((void**)&PART, g_part);
    cudaGetSymbolAddress((void**)&WH,   g_wh);
    cudaGetSymbolAddress((void**)&WL,   g_wl);
    cudaGetSymbolAddress((void**)&QKVH, g_qkvh);
    cudaGetSymbolAddress((void**)&QKVL, g_qkvl);
    cudaGetSymbolAddress((void**)&P1H,  g_p1h);
    cudaGetSymbolAddress((void**)&P1L,  g_p1l);
    cudaGetSymbolAddress((void**)&P2H,  g_p2h);
    cudaGetSymbolAddress((void**)&P2L,  g_p2l);

    cudaFuncSetAttribute(attn_tc_kernel,
                         cudaFuncAttributeMaxDynamicSharedMemorySize, ATTN_TC_SMEM);
    cudaFuncSetAttribute(gemm_bf3<0,true,false,false>,
                         cudaFuncAttributeMaxDynamicSharedMemorySize, GSMEM_BYTES);
    cudaFuncSetAttribute(gemm_bf3<1,true,false,false>,
                         cudaFuncAttributeMaxDynamicSharedMemorySize, GSMEM_BYTES);
    cudaFuncSetAttribute(gemm_bf3<0,false,false,true>,
                         cudaFuncAttributeMaxDynamicSharedMemorySize, GSMEM_BYTES);

    const dim3 blk(256);
    const dim3 gblk(256);
    const dim3 g_qkvp(D3/128,  NTOK/128);        // (24,16)
    const dim3 g_outp(DDIM/128, NTOK/128, 2);    // (8,16,2)  split-K 2
    const dim3 g_ffn1(MDIM/128, NTOK/128);       // (32,16)
    const dim3 g_ffn2(DDIM/128, NTOK/128, 4);    // (8,16,4)  split-K 4
    const dim3 g_attn(BNUM*HNUM, SLEN/64);       // (32,16)
    const int  g_band = (BNUM*HNUM*SLEN*32) / 256;
    const int  g_ln   = NTOK;
    const int  g_red  = (NTOK*DDIM) / 1024;      // 2048

    // ---- single merged split launch: all 6 weights + layer-0 input ----
    split_all_kernel<<<SPLIT_TOTAL_BLOCKS, blk>>>(
        w_in1, w_out1, w_in2, w_out2, ffn_w1, ffn_w2, x_in,
        WH, WL, P1H, P1L);

    const float* xcur = x_in;
    for (int l = 0; l < LNUM; l++) {
        const size_t oW3 = (size_t)l * D3 * DDIM;
        const size_t oW1 = (size_t)l * DDIM * DDIM;
        const size_t oWm = (size_t)l * MDIM * DDIM;

        // ---- intra-frame full MHA ----
        gemm_bf3<0,true,false,false><<<g_qkvp, gblk, GSMEM_BYTES>>>(
            P1H, P1L, WH+W_IN1_OFF+oW3, WL+W_IN1_OFF+oW3,
            b_in1 + (size_t)l*D3, nullptr, nullptr, QKVH, QKVL, nullptr,
            NTOK, D3, DDIM);
        attn_tc_kernel<<<g_attn, 128, ATTN_TC_SMEM>>>(QKVH, QKVL, P1H, P1L);
        gemm_bf3<0,false,false,true><<<g_outp, gblk, GSMEM_BYTES>>>(
            P1H, P1L, WH+W_OUT1_OFF+oW1, WL+W_OUT1_OFF+oW1,
            nullptr, nullptr, nullptr, nullptr, nullptr, PART,
            NTOK, DDIM, DDIM);
        epi_ln_kernel<2><<<g_ln, blk>>>(
            PART, b_out1 + (size_t)l*DDIM, xcur,
            ln1_g + (size_t)l*DDIM, ln1_b + (size_t)l*DDIM, X2, P1H, P1L);

        // ---- inter-frame banded MHA ----
        gemm_bf3<0,true,false,false><<<g_qkvp, gblk, GSMEM_BYTES>>>(
            P1H, P1L, WH+W_IN2_OFF+oW3, WL+W_IN2_OFF+oW3,
            b_in2 + (size_t)l*D3, nullptr, nullptr, QKVH, QKVL, nullptr,
            NTOK, D3, DDIM);
        attn_band_kernel<<<g_band, blk>>>(QKVH, QKVL, P1H, P1L);
        gemm_bf3<0,false,false,true><<<g_outp, gblk, GSMEM_BYTES>>>(
            P1H, P1L, WH+W_OUT2_OFF+oW1, WL+W_OUT2_OFF+oW1,
            nullptr, nullptr, nullptr, nullptr, nullptr, PART,
            NTOK, DDIM, DDIM);
        epi_ln_kernel<2><<<g_ln, blk>>>(
            PART, b_out2 + (size_t)l*DDIM, X2,
            ln2_g + (size_t)l*DDIM, ln2_b + (size_t)l*DDIM, ATT, P1H, P1L);

        // ---- FFN ----
        gemm_bf3<1,true,false,false><<<g_ffn1, gblk, GSMEM_BYTES>>>(
            P1H, P1L, WH+FW1_OFF+oWm, WL+FW1_OFF+oWm,
            ffn_b1 + (size_t)l*MDIM, nullptr, nullptr, P2H, P2L, nullptr,
            NTOK, MDIM, DDIM);
        gemm_bf3<0,false,false,true><<<g_ffn2, gblk, GSMEM_BYTES>>>(
            P2H, P2L, WH+FW2_OFF+oWm, WL+FW2_OFF+oWm,
            nullptr, nullptr, nullptr, nullptr, nullptr, PART,
            NTOK, DDIM, MDIM);
        epi_reduce<2,true,true,4><<<g_red, blk>>>(
            PART, ffn_b2 + (size_t)l*DDIM, ATT, X, P1H, P1L);
        xcur = X;
    }

    ln_kernel<<<g_ln, blk>>>(xcur, lnf_g, lnf_b, (float*)d_out);
}